// round 1
// baseline (speedup 1.0000x reference)
#include <cuda_runtime.h>
#include <cuda_bf16.h>
#include <math.h>

// Problem constants
#define BATCH 32
#define CCH   128      // channels
#define NTOK  4096     // H*W
#define NH    4        // heads
#define DH    32       // dim head
#define QKV3  384      // 3*hidden

// ---------------- scratch (device globals; no allocation allowed) ----------
__device__ float g_qkv[(size_t)BATCH * QKV3 * NTOK];          // ~201 MB
__device__ float g_kmax[BATCH * NH * DH];
__device__ float g_ksum[BATCH * NH * DH];
__device__ float g_ctx_part[8 * BATCH * NH * DH * DH];        // 8 splits of ctx partials
__device__ float g_w2t[BATCH * CCH * CCH];                    // W2 transposed: [b][c][o]

// ---------------- f32x2 packed FMA helpers (sm_100+) ------------------------
__device__ __forceinline__ unsigned long long pack2(float x, float y) {
    unsigned long long r;
    asm("mov.b64 %0, {%1, %2};" : "=l"(r) : "f"(x), "f"(y));
    return r;
}
__device__ __forceinline__ void fma2(unsigned long long &d, unsigned long long a,
                                     unsigned long long b) {
    asm("fma.rn.f32x2 %0, %1, %2, %3;" : "=l"(d) : "l"(a), "l"(b), "l"(d));
}
__device__ __forceinline__ float2 unpack2(unsigned long long v) {
    float lo, hi;
    asm("mov.b64 {%0, %1}, %2;" : "=f"(lo), "=f"(hi) : "l"(v));
    return make_float2(lo, hi);
}

// ============================================================================
// K1: fused RMSNorm + qkv projection GEMM.
// Per block: output tile [128 rows x 64 tokens], K = 128 (full channel dim).
// grid (ntile=64, mtile=3, b=32), block 256.
// smem: xs[128][64] (normalized x tile), wst[128][132] (W transposed [k][r]).
// ============================================================================
__global__ __launch_bounds__(256, 2)
void k_rmsnorm_qkv(const float* __restrict__ x, const float* __restrict__ g,
                   const float* __restrict__ wqkv) {
    extern __shared__ float sm1[];
    float* xs   = sm1;                 // 8192
    float* wst  = sm1 + 8192;          // 128*132 = 16896
    float* red  = wst + 16896;         // 256
    float* invs = red + 256;           // 64
    float* gs   = invs + 64;           // 128

    const int nt = blockIdx.x, mt = blockIdx.y, b = blockIdx.z;
    const int tid = threadIdx.x;

    // load x tile [128 x 64] (coalesced rows of 64 tokens)
    const float* xb = x + (size_t)b * CCH * NTOK + (size_t)nt * 64;
    #pragma unroll
    for (int i = 0; i < 32; i++) {
        int idx = tid + i * 256;
        int c = idx >> 6, t = idx & 63;
        xs[c * 64 + t] = xb[(size_t)c * NTOK + t];
    }
    if (tid < 128) gs[tid] = g[tid];

    // load W tile transposed: wst[k][r] = W[mt*128 + r][k]
    const float* wb = wqkv + (size_t)mt * 128 * CCH;
    #pragma unroll
    for (int i = 0; i < 64; i++) {
        int idx = tid + i * 256;
        int k = idx & 127, r = idx >> 7;
        wst[k * 132 + r] = wb[r * CCH + k];
    }
    __syncthreads();

    // per-token RMS norm: 4 partial sums of 32 channels each
    {
        int t = tid & 63, qq = tid >> 6;
        float s = 0.f;
        #pragma unroll
        for (int cc = 0; cc < 32; cc++) {
            float v = xs[(qq * 32 + cc) * 64 + t];
            s += v * v;
        }
        red[qq * 64 + t] = s;
    }
    __syncthreads();
    if (tid < 64) {
        float s = red[tid] + red[64 + tid] + red[128 + tid] + red[192 + tid];
        float nrm = fmaxf(sqrtf(s), 1e-12f);
        invs[tid] = 11.313708498984761f / nrm;   // sqrt(128)/norm
    }
    __syncthreads();
    #pragma unroll
    for (int i = 0; i < 32; i++) {
        int idx = tid + i * 256;
        int c = idx >> 6, t = idx & 63;
        xs[c * 64 + t] *= invs[t] * gs[c];
    }
    __syncthreads();

    // GEMM: thread tile 8 rows x 4 cols, rows packed in f32x2 pairs
    const int ty = tid >> 4, tx = tid & 15;      // ty: 16 row-groups of 8, tx: 16 col-groups of 4
    unsigned long long acc[4][4];
    #pragma unroll
    for (int p = 0; p < 4; p++)
        #pragma unroll
        for (int c = 0; c < 4; c++) acc[p][c] = 0ull;

    #pragma unroll 4
    for (int k = 0; k < 128; k++) {
        // a: 8 consecutive rows at wst[k][ty*8 ..] as 4 packed pairs
        const ulonglong2 a01 = *reinterpret_cast<const ulonglong2*>(&wst[k * 132 + ty * 8]);
        const ulonglong2 a23 = *reinterpret_cast<const ulonglong2*>(&wst[k * 132 + ty * 8 + 4]);
        unsigned long long a2[4] = {a01.x, a01.y, a23.x, a23.y};
        // b: 4 tokens, each duplicated into both f32x2 lanes
        const float4 bv = *reinterpret_cast<const float4*>(&xs[k * 64 + tx * 4]);
        unsigned long long bd[4] = {pack2(bv.x, bv.x), pack2(bv.y, bv.y),
                                    pack2(bv.z, bv.z), pack2(bv.w, bv.w)};
        #pragma unroll
        for (int p = 0; p < 4; p++)
            #pragma unroll
            for (int c = 0; c < 4; c++)
                fma2(acc[p][c], a2[p], bd[c]);
    }

    // store: rows (ty*8 + 2p, +1), cols tx*4..+3
    float* outb = g_qkv + ((size_t)b * QKV3 + (size_t)mt * 128) * NTOK + (size_t)nt * 64;
    #pragma unroll
    for (int p = 0; p < 4; p++) {
        float2 c0 = unpack2(acc[p][0]), c1 = unpack2(acc[p][1]);
        float2 c2 = unpack2(acc[p][2]), c3 = unpack2(acc[p][3]);
        float4 lo = make_float4(c0.x, c1.x, c2.x, c3.x);
        float4 hi = make_float4(c0.y, c1.y, c2.y, c3.y);
        size_t base = (size_t)(ty * 8 + 2 * p) * NTOK + tx * 4;
        *reinterpret_cast<float4*>(outb + base)        = lo;
        *reinterpret_cast<float4*>(outb + base + NTOK) = hi;
    }
}

// ============================================================================
// K2: per (b,h,d) row of k: max and sum(exp) over 4096 tokens + 4 memory slots.
// grid 4096, block 256.
// ============================================================================
__global__ void k_kstats(const float* __restrict__ mem_kv) {
    __shared__ float red[256];
    const int row = blockIdx.x;                 // b*128 + h*32 + d
    const int b = row >> 7, hd = row & 127;
    const int tid = threadIdx.x;
    const float* kp = g_qkv + ((size_t)(b * QKV3 + CCH + hd)) * NTOK;

    float vals[16];
    float m = -1e30f;
    #pragma unroll
    for (int i = 0; i < 16; i++) {
        vals[i] = kp[tid + i * 256];
        m = fmaxf(m, vals[i]);
    }
    red[tid] = m;
    __syncthreads();
    for (int s = 128; s > 0; s >>= 1) {
        if (tid < s) red[tid] = fmaxf(red[tid], red[tid + s]);
        __syncthreads();
    }
    if (tid == 0) {
        float mm = red[0];
        #pragma unroll
        for (int j = 0; j < 4; j++)
            mm = fmaxf(mm, mem_kv[hd * 4 + j]);   // mem_kv[0][h][d][j]
        red[0] = mm;
    }
    __syncthreads();
    const float M = red[0];
    __syncthreads();

    float s = 0.f;
    #pragma unroll
    for (int i = 0; i < 16; i++) s += __expf(vals[i] - M);
    red[tid] = s;
    __syncthreads();
    for (int st = 128; st > 0; st >>= 1) {
        if (tid < st) red[tid] += red[tid + st];
        __syncthreads();
    }
    if (tid == 0) {
        float tot = red[0];
        #pragma unroll
        for (int j = 0; j < 4; j++) tot += __expf(mem_kv[hd * 4 + j] - M);
        g_kmax[row] = M;
        g_ksum[row] = tot;
    }
}

// ============================================================================
// K3: context partials: ctx[d][e] += sum_n exp(k[d,n]-max_d) * v[e,n]
// grid 32*4*8 (8 token splits of 512), block 256 (4 groups x 64 threads,
// each group a 32-token sub-range per 128-token chunk; thread tile 4x4).
// Deterministic: per-split partials, no float atomics.
// ============================================================================
__global__ void k_context() {
    __shared__ float es[32 * 132];
    __shared__ float vs[32 * 132];
    __shared__ float kms[32];
    const int blk = blockIdx.x;
    const int bh = blk >> 3, split = blk & 7;
    const int b = bh >> 2, h = bh & 3;
    const int tid = threadIdx.x;

    if (tid < 32) kms[tid] = g_kmax[bh * 32 + tid];
    const int grp = tid >> 6, lt = tid & 63;
    const int d0 = (lt >> 3) * 4, e0 = (lt & 7) * 4;

    float acc[4][4] = {};
    const float* kbase = g_qkv + ((size_t)(b * QKV3 + CCH + h * DH)) * NTOK;
    const float* vbase = g_qkv + ((size_t)(b * QKV3 + 2 * CCH + h * DH)) * NTOK;
    const int t0 = split * 512;
    __syncthreads();

    for (int c0 = 0; c0 < 512; c0 += 128) {
        #pragma unroll
        for (int i = 0; i < 16; i++) {
            int idx = tid + i * 256;
            int d = idx >> 7, t = idx & 127;
            float kv = kbase[(size_t)d * NTOK + t0 + c0 + t];
            es[d * 132 + t] = __expf(kv - kms[d]);
            vs[d * 132 + t] = vbase[(size_t)d * NTOK + t0 + c0 + t];
        }
        __syncthreads();
        const int tb = grp * 32;
        #pragma unroll
        for (int t4 = 0; t4 < 32; t4 += 4) {
            float4 av[4], bv[4];
            #pragma unroll
            for (int i = 0; i < 4; i++)
                av[i] = *reinterpret_cast<const float4*>(&es[(d0 + i) * 132 + tb + t4]);
            #pragma unroll
            for (int j = 0; j < 4; j++)
                bv[j] = *reinterpret_cast<const float4*>(&vs[(e0 + j) * 132 + tb + t4]);
            #pragma unroll
            for (int i = 0; i < 4; i++)
                #pragma unroll
                for (int j = 0; j < 4; j++)
                    acc[i][j] += av[i].x * bv[j].x + av[i].y * bv[j].y +
                                 av[i].z * bv[j].z + av[i].w * bv[j].w;
        }
        __syncthreads();
    }

    // combine the 4 groups deterministically through smem
    float* part = es;   // 4096 floats needed, es holds 4224
    #pragma unroll
    for (int i = 0; i < 4; i++)
        #pragma unroll
        for (int j = 0; j < 4; j++)
            part[grp * 1024 + (d0 + i) * 32 + (e0 + j)] = acc[i][j];
    __syncthreads();
    for (int idx = tid; idx < 1024; idx += 256) {
        float s = part[idx] + part[idx + 1024] + part[idx + 2048] + part[idx + 3072];
        g_ctx_part[((size_t)split * 128 + bh) * 1024 + idx] = s;
    }
}

// ============================================================================
// K4: fold: W2[b][o][h*32+d] = sum_e w_out[o][h*32+e] * ctx_n[b,h,d,e]
// where ctx_n = (ctx_partials_sum + memory-kv terms) / Z_d.  Stored transposed
// as g_w2t[b][c][o].  grid 32, block 128 (thread = c = h*32+d).
// ============================================================================
__global__ void k_w2(const float* __restrict__ wout, const float* __restrict__ mem_kv) {
    extern __shared__ float smw[];   // 128*128 = 16384 floats
    const int b = blockIdx.x;
    const int tid = threadIdx.x;     // c = h*32 + d
    const int h = tid >> 5, d = tid & 31;

    #pragma unroll
    for (int i = 0; i < 128; i++) smw[tid + i * 128] = wout[tid + i * 128];
    __syncthreads();

    const float km = g_kmax[b * 128 + tid];
    const float Z  = g_ksum[b * 128 + tid];
    float ew[4];
    #pragma unroll
    for (int j = 0; j < 4; j++)
        ew[j] = __expf(mem_kv[tid * 4 + j] - km);         // mem_kv[0][h][d][j]

    float ce[32];
    const float invZ = 1.0f / Z;
    #pragma unroll
    for (int e = 0; e < 32; e++) {
        float v = 0.f;
        const size_t base = (size_t)(b * 4 + h) * 1024 + d * 32 + e;
        #pragma unroll
        for (int s = 0; s < 8; s++)
            v += g_ctx_part[(size_t)s * 128 * 1024 + base];
        #pragma unroll
        for (int j = 0; j < 4; j++)
            v = fmaf(ew[j], mem_kv[512 + (h * 32 + e) * 4 + j], v);  // mem_kv[1][h][e][j]
        ce[e] = v * invZ;
    }

    for (int o = 0; o < 128; o++) {
        const float* wr = &smw[o * 128 + h * 32];
        float a = 0.f;
        #pragma unroll
        for (int e4 = 0; e4 < 32; e4 += 4) {
            float4 w4 = *reinterpret_cast<const float4*>(&wr[e4]);
            a = fmaf(w4.x, ce[e4], a);
            a = fmaf(w4.y, ce[e4 + 1], a);
            a = fmaf(w4.z, ce[e4 + 2], a);
            a = fmaf(w4.w, ce[e4 + 3], a);
        }
        g_w2t[((size_t)b * 128 + tid) * 128 + o] = a;
    }
}

// ============================================================================
// K5: fused q-softmax (over d per head, *scale) + output GEMM y = W2 @ qs + bias
// grid (64 token tiles, 32 b), block 256.  Tile [128 x 64], K = 128.
// ============================================================================
__global__ __launch_bounds__(256, 2)
void k_final(const float* __restrict__ bout, float* __restrict__ y) {
    extern __shared__ float sm5[];
    float* qsm = sm5;                 // 128*64 = 8192
    float* w2t = sm5 + 8192;          // 128*132 = 16896  ([c][o])
    float* bs  = w2t + 16896;         // 128

    const int nt = blockIdx.x, b = blockIdx.y;
    const int tid = threadIdx.x;

    // load q tile (channels 0..127 of qkv)
    const float* qg = g_qkv + (size_t)b * QKV3 * NTOK + (size_t)nt * 64;
    #pragma unroll
    for (int i = 0; i < 32; i++) {
        int idx = tid + i * 256;
        int c = idx >> 6, t = idx & 63;
        qsm[c * 64 + t] = qg[(size_t)c * NTOK + t];
    }
    // load W2 transposed [c][o] (already transposed in gmem -> conflict-free)
    const float* wg = g_w2t + (size_t)b * 16384;
    #pragma unroll
    for (int i = 0; i < 64; i++) {
        int idx = tid + i * 256;
        int c = idx >> 7, o = idx & 127;
        w2t[c * 132 + o] = wg[idx];
    }
    if (tid < 128) bs[tid] = bout[tid];
    __syncthreads();

    // per-(head, token) softmax over d, times scale = 1/sqrt(32)
    {
        const int h = tid >> 6, t = tid & 63;
        float qv[32];
        float m = -1e30f;
        #pragma unroll
        for (int d = 0; d < 32; d++) {
            qv[d] = qsm[(h * 32 + d) * 64 + t];
            m = fmaxf(m, qv[d]);
        }
        float ss = 0.f;
        #pragma unroll
        for (int d = 0; d < 32; d++) {
            qv[d] = __expf(qv[d] - m);
            ss += qv[d];
        }
        const float inv = 0.17677669529663687f / ss;
        #pragma unroll
        for (int d = 0; d < 32; d++)
            qsm[(h * 32 + d) * 64 + t] = qv[d] * inv;
    }
    __syncthreads();

    // GEMM 128x64x128, thread tile 8x4 packed rows
    const int ty = tid >> 4, tx = tid & 15;
    unsigned long long acc[4][4];
    #pragma unroll
    for (int p = 0; p < 4; p++)
        #pragma unroll
        for (int c = 0; c < 4; c++) acc[p][c] = 0ull;

    #pragma unroll 4
    for (int k = 0; k < 128; k++) {
        const ulonglong2 a01 = *reinterpret_cast<const ulonglong2*>(&w2t[k * 132 + ty * 8]);
        const ulonglong2 a23 = *reinterpret_cast<const ulonglong2*>(&w2t[k * 132 + ty * 8 + 4]);
        unsigned long long a2[4] = {a01.x, a01.y, a23.x, a23.y};
        const float4 bv = *reinterpret_cast<const float4*>(&qsm[k * 64 + tx * 4]);
        unsigned long long bd[4] = {pack2(bv.x, bv.x), pack2(bv.y, bv.y),
                                    pack2(bv.z, bv.z), pack2(bv.w, bv.w)};
        #pragma unroll
        for (int p = 0; p < 4; p++)
            #pragma unroll
            for (int c = 0; c < 4; c++)
                fma2(acc[p][c], a2[p], bd[c]);
    }

    // epilogue: +bias, store
    #pragma unroll
    for (int p = 0; p < 4; p++) {
        const int r0 = ty * 8 + 2 * p;
        const float b0 = bs[r0], b1 = bs[r0 + 1];
        float2 c0 = unpack2(acc[p][0]), c1 = unpack2(acc[p][1]);
        float2 c2 = unpack2(acc[p][2]), c3 = unpack2(acc[p][3]);
        float4 lo = make_float4(c0.x + b0, c1.x + b0, c2.x + b0, c3.x + b0);
        float4 hi = make_float4(c0.y + b1, c1.y + b1, c2.y + b1, c3.y + b1);
        size_t base = ((size_t)b * CCH + r0) * NTOK + (size_t)nt * 64 + tx * 4;
        *reinterpret_cast<float4*>(y + base)        = lo;
        *reinterpret_cast<float4*>(y + base + NTOK) = hi;
    }
}

// ============================================================================
extern "C" void kernel_launch(void* const* d_in, const int* in_sizes, int n_in,
                              void* d_out, int out_size) {
    const float* x      = (const float*)d_in[0];
    const float* g      = (const float*)d_in[1];
    const float* wqkv   = (const float*)d_in[2];
    const float* mem_kv = (const float*)d_in[3];
    const float* wout   = (const float*)d_in[4];
    const float* bout   = (const float*)d_in[5];
    float* y = (float*)d_out;

    const int SMEM_K1 = 25536 * 4;   // 102144 B
    const int SMEM_K5 = 25216 * 4;   // 100864 B
    const int SMEM_K4 = 16384 * 4;   // 65536 B
    cudaFuncSetAttribute(k_rmsnorm_qkv, cudaFuncAttributeMaxDynamicSharedMemorySize, SMEM_K1);
    cudaFuncSetAttribute(k_final,       cudaFuncAttributeMaxDynamicSharedMemorySize, SMEM_K5);
    cudaFuncSetAttribute(k_w2,          cudaFuncAttributeMaxDynamicSharedMemorySize, SMEM_K4);

    k_rmsnorm_qkv<<<dim3(64, 3, 32), 256, SMEM_K1>>>(x, g, wqkv);
    k_kstats<<<4096, 256>>>(mem_kv);
    k_context<<<1024, 256>>>();
    k_w2<<<32, 128, SMEM_K4>>>(wout, mem_kv);
    k_final<<<dim3(64, 32), 256, SMEM_K5>>>(bout, y);
}

// round 2
// speedup vs baseline: 1.0958x; 1.0958x over previous
#include <cuda_runtime.h>
#include <cuda_bf16.h>
#include <math.h>

// Problem constants
#define BATCH 32
#define CCH   128      // channels
#define NTOK  4096     // H*W
#define NH    4        // heads
#define DH    32       // dim head
#define QKV3  384      // 3*hidden

// ---------------- scratch (device globals; no allocation allowed) ----------
__device__ float g_qkv[(size_t)BATCH * QKV3 * NTOK];          // ~201 MB
__device__ float g_wg[QKV3 * CCH];                            // g-folded qkv weights
__device__ float g_kmax[BATCH * NH * DH];
__device__ float g_ksum[BATCH * NH * DH];
__device__ float g_ctx_part[8 * BATCH * NH * DH * DH];        // 8 splits of ctx partials
__device__ float g_w2t[BATCH * CCH * CCH];                    // W2 transposed: [b][c][o]

// ---------------- f32x2 packed FMA helpers (sm_100+) ------------------------
__device__ __forceinline__ unsigned long long pack2(float x, float y) {
    unsigned long long r;
    asm("mov.b64 %0, {%1, %2};" : "=l"(r) : "f"(x), "f"(y));
    return r;
}
__device__ __forceinline__ void fma2(unsigned long long &d, unsigned long long a,
                                     unsigned long long b) {
    asm("fma.rn.f32x2 %0, %1, %2, %3;" : "=l"(d) : "l"(a), "l"(b), "l"(d));
}
__device__ __forceinline__ float2 unpack2(unsigned long long v) {
    float lo, hi;
    asm("mov.b64 {%0, %1}, %2;" : "=f"(lo), "=f"(hi) : "l"(v));
    return make_float2(lo, hi);
}

// ============================================================================
// K0: fold g[k] * sqrt(C) into qkv weights.  49152 elements.
// ============================================================================
__global__ void k_prepw(const float* __restrict__ wqkv, const float* __restrict__ g) {
    int i = blockIdx.x * 256 + threadIdx.x;   // < 49152
    int k = i & 127;
    g_wg[i] = wqkv[i] * g[k] * 11.313708498984761f;
}

// ============================================================================
// K1: fused RMSNorm + qkv projection GEMM.
// Per block: output tile [128 rows x 64 tokens], K = 128 (full channel dim).
// grid (ntile=64, mtile=3, b=32), block 256.
// x tile held in registers through the norm reduction (no smem round trip).
// ============================================================================
__global__ __launch_bounds__(256, 2)
void k_qkv(const float* __restrict__ x) {
    extern __shared__ float sm1[];
    float* xs   = sm1;                 // 8192
    float* wst  = sm1 + 8192;          // 128*132 = 16896
    float* red  = wst + 16896;         // 256
    float* invs = red + 256;           // 64

    const int nt = blockIdx.x, mt = blockIdx.y, b = blockIdx.z;
    const int tid = threadIdx.x;
    const int t = tid & 63, cq = tid >> 6;     // this thread: fixed token t, c = cq+4i

    // load x tile into registers; accumulate per-token partial sum of squares
    const float* xb = x + (size_t)b * CCH * NTOK + (size_t)nt * 64 + t;
    float v[32];
    float s = 0.f;
    #pragma unroll
    for (int i = 0; i < 32; i++) {
        v[i] = xb[(size_t)(cq + 4 * i) * NTOK];
        s += v[i] * v[i];
    }
    red[cq * 64 + t] = s;

    // load W tile transposed: wst[k][r] = Wg[mt*128 + r][k]
    const float* wb = g_wg + (size_t)mt * 128 * CCH;
    #pragma unroll
    for (int i = 0; i < 64; i++) {
        int idx = tid + i * 256;
        int k = idx & 127, r = idx >> 7;
        wst[k * 132 + r] = wb[r * CCH + k];
    }
    __syncthreads();

    if (tid < 64) {
        float ss = red[tid] + red[64 + tid] + red[128 + tid] + red[192 + tid];
        invs[tid] = 1.0f / fmaxf(sqrtf(ss), 1e-12f);
    }
    __syncthreads();

    {
        const float it = invs[t];
        #pragma unroll
        for (int i = 0; i < 32; i++)
            xs[(cq + 4 * i) * 64 + t] = v[i] * it;
    }
    __syncthreads();

    // GEMM: thread tile 8 rows x 4 cols, rows packed in f32x2 pairs
    const int ty = tid >> 4, tx = tid & 15;
    unsigned long long acc[4][4];
    #pragma unroll
    for (int p = 0; p < 4; p++)
        #pragma unroll
        for (int c = 0; c < 4; c++) acc[p][c] = 0ull;

    #pragma unroll 4
    for (int k = 0; k < 128; k++) {
        const ulonglong2 a01 = *reinterpret_cast<const ulonglong2*>(&wst[k * 132 + ty * 8]);
        const ulonglong2 a23 = *reinterpret_cast<const ulonglong2*>(&wst[k * 132 + ty * 8 + 4]);
        unsigned long long a2[4] = {a01.x, a01.y, a23.x, a23.y};
        const float4 bv = *reinterpret_cast<const float4*>(&xs[k * 64 + tx * 4]);
        unsigned long long bd[4] = {pack2(bv.x, bv.x), pack2(bv.y, bv.y),
                                    pack2(bv.z, bv.z), pack2(bv.w, bv.w)};
        #pragma unroll
        for (int p = 0; p < 4; p++)
            #pragma unroll
            for (int c = 0; c < 4; c++)
                fma2(acc[p][c], a2[p], bd[c]);
    }

    float* outb = g_qkv + ((size_t)b * QKV3 + (size_t)mt * 128) * NTOK + (size_t)nt * 64;
    #pragma unroll
    for (int p = 0; p < 4; p++) {
        float2 c0 = unpack2(acc[p][0]), c1 = unpack2(acc[p][1]);
        float2 c2 = unpack2(acc[p][2]), c3 = unpack2(acc[p][3]);
        float4 lo = make_float4(c0.x, c1.x, c2.x, c3.x);
        float4 hi = make_float4(c0.y, c1.y, c2.y, c3.y);
        size_t base = (size_t)(ty * 8 + 2 * p) * NTOK + tx * 4;
        *reinterpret_cast<float4*>(outb + base)        = lo;
        *reinterpret_cast<float4*>(outb + base + NTOK) = hi;
    }
}

// ============================================================================
// K2: per (b,h,d) row of k: max and sum(exp) over 4096 tokens + 4 memory slots.
// grid 4096, block 256.  Warp-shuffle reductions.
// ============================================================================
__global__ void k_kstats(const float* __restrict__ mem_kv) {
    __shared__ float wred[8];
    const int row = blockIdx.x;                 // b*128 + h*32 + d
    const int b = row >> 7, hd = row & 127;
    const int tid = threadIdx.x;
    const int lane = tid & 31, wid = tid >> 5;
    const float* kp = g_qkv + ((size_t)(b * QKV3 + CCH + hd)) * NTOK;

    float vals[16];
    float m = -1e30f;
    #pragma unroll
    for (int i = 0; i < 16; i++) {
        vals[i] = kp[tid + i * 256];
        m = fmaxf(m, vals[i]);
    }
    #pragma unroll
    for (int o = 16; o > 0; o >>= 1)
        m = fmaxf(m, __shfl_xor_sync(0xFFFFFFFFu, m, o));
    if (lane == 0) wred[wid] = m;
    __syncthreads();
    if (tid == 0) {
        float mm = wred[0];
        #pragma unroll
        for (int w = 1; w < 8; w++) mm = fmaxf(mm, wred[w]);
        #pragma unroll
        for (int j = 0; j < 4; j++)
            mm = fmaxf(mm, mem_kv[hd * 4 + j]);   // mem_kv[0][h][d][j]
        wred[0] = mm;
    }
    __syncthreads();
    const float M = wred[0];
    __syncthreads();

    float s = 0.f;
    #pragma unroll
    for (int i = 0; i < 16; i++) s += __expf(vals[i] - M);
    #pragma unroll
    for (int o = 16; o > 0; o >>= 1)
        s += __shfl_xor_sync(0xFFFFFFFFu, s, o);
    if (lane == 0) wred[wid] = s;
    __syncthreads();
    if (tid == 0) {
        float tot = 0.f;
        #pragma unroll
        for (int w = 0; w < 8; w++) tot += wred[w];
        #pragma unroll
        for (int j = 0; j < 4; j++) tot += __expf(mem_kv[hd * 4 + j] - M);
        g_kmax[row] = M;
        g_ksum[row] = tot;
    }
}

// ============================================================================
// K3: context partials: ctx[d][e] += sum_n exp(k[d,n]-max_d) * v[e,n]
// grid 32*4*8 (8 token splits of 512), block 256.  Deterministic partials.
// ============================================================================
__global__ void k_context() {
    __shared__ float es[32 * 132];
    __shared__ float vs[32 * 132];
    __shared__ float kms[32];
    const int blk = blockIdx.x;
    const int bh = blk >> 3, split = blk & 7;
    const int b = bh >> 2, h = bh & 3;
    const int tid = threadIdx.x;

    if (tid < 32) kms[tid] = g_kmax[bh * 32 + tid];
    const int grp = tid >> 6, lt = tid & 63;
    const int d0 = (lt >> 3) * 4, e0 = (lt & 7) * 4;

    float acc[4][4] = {};
    const float* kbase = g_qkv + ((size_t)(b * QKV3 + CCH + h * DH)) * NTOK;
    const float* vbase = g_qkv + ((size_t)(b * QKV3 + 2 * CCH + h * DH)) * NTOK;
    const int t0 = split * 512;
    __syncthreads();

    for (int c0 = 0; c0 < 512; c0 += 128) {
        #pragma unroll
        for (int i = 0; i < 16; i++) {
            int idx = tid + i * 256;
            int d = idx >> 7, t = idx & 127;
            float kv = kbase[(size_t)d * NTOK + t0 + c0 + t];
            es[d * 132 + t] = __expf(kv - kms[d]);
            vs[d * 132 + t] = vbase[(size_t)d * NTOK + t0 + c0 + t];
        }
        __syncthreads();
        const int tb = grp * 32;
        #pragma unroll
        for (int t4 = 0; t4 < 32; t4 += 4) {
            float4 av[4], bv[4];
            #pragma unroll
            for (int i = 0; i < 4; i++)
                av[i] = *reinterpret_cast<const float4*>(&es[(d0 + i) * 132 + tb + t4]);
            #pragma unroll
            for (int j = 0; j < 4; j++)
                bv[j] = *reinterpret_cast<const float4*>(&vs[(e0 + j) * 132 + tb + t4]);
            #pragma unroll
            for (int i = 0; i < 4; i++)
                #pragma unroll
                for (int j = 0; j < 4; j++)
                    acc[i][j] += av[i].x * bv[j].x + av[i].y * bv[j].y +
                                 av[i].z * bv[j].z + av[i].w * bv[j].w;
        }
        __syncthreads();
    }

    // combine the 4 groups deterministically through smem
    float* part = es;   // 4096 floats needed, es holds 4224
    #pragma unroll
    for (int i = 0; i < 4; i++)
        #pragma unroll
        for (int j = 0; j < 4; j++)
            part[grp * 1024 + (d0 + i) * 32 + (e0 + j)] = acc[i][j];
    __syncthreads();
    for (int idx = tid; idx < 1024; idx += 256) {
        float s = part[idx] + part[idx + 1024] + part[idx + 2048] + part[idx + 3072];
        g_ctx_part[((size_t)split * 128 + bh) * 1024 + idx] = s;
    }
}

// ============================================================================
// K4: fold w_out through normalized context:
//   W2t[b][c][o] = sum_e w_out[o][h(c)*32+e] * ctx_n[b,h(c),d(c),e]
// grid (32 b, 4 o-tiles of 32), block 256.
// ============================================================================
__global__ void k_w2p(const float* __restrict__ wout, const float* __restrict__ mem_kv) {
    __shared__ float ce[128 * 36];    // ctx_n rows, padded (16B aligned, low conflict)
    __shared__ float ws[32 * 132];    // w_out rows for this o-tile
    __shared__ float ews[512];        // exp(mem_k - kmax) per (c, j)
    __shared__ float invz[128];
    const int b = blockIdx.x, og = blockIdx.y;
    const int tid = threadIdx.x;

    for (int idx = tid; idx < 512; idx += 256) {
        int c = idx >> 2;
        ews[idx] = __expf(mem_kv[idx] - g_kmax[b * 128 + c]);
    }
    if (tid < 128) invz[tid] = 1.0f / g_ksum[b * 128 + tid];
    #pragma unroll
    for (int i = 0; i < 16; i++) {
        int idx = tid + i * 256;
        ws[(idx >> 7) * 132 + (idx & 127)] = wout[og * 32 * 128 + idx];
    }
    __syncthreads();

    // ctx_n into smem: ce[c][e]
    for (int idx = tid; idx < 4096; idx += 256) {
        int c = idx >> 5, e = idx & 31, h = c >> 5, d = c & 31;
        size_t base = (size_t)(b * 4 + h) * 1024 + d * 32 + e;
        float vsum = 0.f;
        #pragma unroll
        for (int s = 0; s < 8; s++)
            vsum += g_ctx_part[(size_t)s * 131072 + base];
        #pragma unroll
        for (int j = 0; j < 4; j++)
            vsum = fmaf(ews[c * 4 + j], mem_kv[512 + ((h * 32 + e) * 4 + j)], vsum);
        ce[c * 36 + e] = vsum * invz[c];
    }
    __syncthreads();

    // per thread: one o, 16 c values
    const int o_l = tid >> 3;          // 0..31
    const int cb = tid & 7;
    const int o = og * 32 + o_l;
    const float* wr = &ws[o_l * 132];
    #pragma unroll
    for (int ci = 0; ci < 16; ci++) {
        int c = cb + ci * 8;
        const float* cr = &ce[c * 36];
        const float* wrr = wr + (c >> 5) * 32;
        float a = 0.f;
        #pragma unroll
        for (int e4 = 0; e4 < 32; e4 += 4) {
            float4 w4 = *reinterpret_cast<const float4*>(wrr + e4);
            float4 c4 = *reinterpret_cast<const float4*>(cr + e4);
            a = fmaf(w4.x, c4.x, a);
            a = fmaf(w4.y, c4.y, a);
            a = fmaf(w4.z, c4.z, a);
            a = fmaf(w4.w, c4.w, a);
        }
        g_w2t[((size_t)b * 128 + c) * 128 + o] = a;
    }
}

// ============================================================================
// K5: fused q-softmax (over d per head, *scale) + output GEMM y = W2 @ qs + bias
// grid (64 token tiles, 32 b), block 256.  Tile [128 x 64], K = 128.
// ============================================================================
__global__ __launch_bounds__(256, 2)
void k_final(const float* __restrict__ bout, float* __restrict__ y) {
    extern __shared__ float sm5[];
    float* qsm = sm5;                 // 128*64 = 8192
    float* w2t = sm5 + 8192;          // 128*132 = 16896  ([c][o])
    float* bs  = w2t + 16896;         // 128

    const int nt = blockIdx.x, b = blockIdx.y;
    const int tid = threadIdx.x;

    // load q tile (channels 0..127 of qkv)
    const float* qg = g_qkv + (size_t)b * QKV3 * NTOK + (size_t)nt * 64;
    #pragma unroll
    for (int i = 0; i < 32; i++) {
        int idx = tid + i * 256;
        int c = idx >> 6, t = idx & 63;
        qsm[c * 64 + t] = qg[(size_t)c * NTOK + t];
    }
    // load W2 transposed [c][o]
    const float* wg = g_w2t + (size_t)b * 16384;
    #pragma unroll
    for (int i = 0; i < 64; i++) {
        int idx = tid + i * 256;
        int c = idx >> 7, o = idx & 127;
        w2t[c * 132 + o] = wg[idx];
    }
    if (tid < 128) bs[tid] = bout[tid];
    __syncthreads();

    // per-(head, token) softmax over d, times scale = 1/sqrt(32)
    {
        const int h = tid >> 6, t = tid & 63;
        float qv[32];
        float m = -1e30f;
        #pragma unroll
        for (int d = 0; d < 32; d++) {
            qv[d] = qsm[(h * 32 + d) * 64 + t];
            m = fmaxf(m, qv[d]);
        }
        float ss = 0.f;
        #pragma unroll
        for (int d = 0; d < 32; d++) {
            qv[d] = __expf(qv[d] - m);
            ss += qv[d];
        }
        const float inv = 0.17677669529663687f / ss;
        #pragma unroll
        for (int d = 0; d < 32; d++)
            qsm[(h * 32 + d) * 64 + t] = qv[d] * inv;
    }
    __syncthreads();

    // GEMM 128x64x128, thread tile 8x4 packed rows
    const int ty = tid >> 4, tx = tid & 15;
    unsigned long long acc[4][4];
    #pragma unroll
    for (int p = 0; p < 4; p++)
        #pragma unroll
        for (int c = 0; c < 4; c++) acc[p][c] = 0ull;

    #pragma unroll 4
    for (int k = 0; k < 128; k++) {
        const ulonglong2 a01 = *reinterpret_cast<const ulonglong2*>(&w2t[k * 132 + ty * 8]);
        const ulonglong2 a23 = *reinterpret_cast<const ulonglong2*>(&w2t[k * 132 + ty * 8 + 4]);
        unsigned long long a2[4] = {a01.x, a01.y, a23.x, a23.y};
        const float4 bv = *reinterpret_cast<const float4*>(&qsm[k * 64 + tx * 4]);
        unsigned long long bd[4] = {pack2(bv.x, bv.x), pack2(bv.y, bv.y),
                                    pack2(bv.z, bv.z), pack2(bv.w, bv.w)};
        #pragma unroll
        for (int p = 0; p < 4; p++)
            #pragma unroll
            for (int c = 0; c < 4; c++)
                fma2(acc[p][c], a2[p], bd[c]);
    }

    // epilogue: +bias, store
    #pragma unroll
    for (int p = 0; p < 4; p++) {
        const int r0 = ty * 8 + 2 * p;
        const float b0 = bs[r0], b1 = bs[r0 + 1];
        float2 c0 = unpack2(acc[p][0]), c1 = unpack2(acc[p][1]);
        float2 c2 = unpack2(acc[p][2]), c3 = unpack2(acc[p][3]);
        float4 lo = make_float4(c0.x + b0, c1.x + b0, c2.x + b0, c3.x + b0);
        float4 hi = make_float4(c0.y + b1, c1.y + b1, c2.y + b1, c3.y + b1);
        size_t base = ((size_t)b * CCH + r0) * NTOK + (size_t)nt * 64 + tx * 4;
        *reinterpret_cast<float4*>(y + base)        = lo;
        *reinterpret_cast<float4*>(y + base + NTOK) = hi;
    }
}

// ============================================================================
extern "C" void kernel_launch(void* const* d_in, const int* in_sizes, int n_in,
                              void* d_out, int out_size) {
    const float* x      = (const float*)d_in[0];
    const float* g      = (const float*)d_in[1];
    const float* wqkv   = (const float*)d_in[2];
    const float* mem_kv = (const float*)d_in[3];
    const float* wout   = (const float*)d_in[4];
    const float* bout   = (const float*)d_in[5];
    float* y = (float*)d_out;

    const int SMEM_K1 = 25408 * 4;   // 101632 B
    const int SMEM_K5 = 25216 * 4;   // 100864 B
    cudaFuncSetAttribute(k_qkv,   cudaFuncAttributeMaxDynamicSharedMemorySize, SMEM_K1);
    cudaFuncSetAttribute(k_final, cudaFuncAttributeMaxDynamicSharedMemorySize, SMEM_K5);

    k_prepw<<<192, 256>>>(wqkv, g);
    k_qkv<<<dim3(64, 3, 32), 256, SMEM_K1>>>(x);
    k_kstats<<<4096, 256>>>(mem_kv);
    k_context<<<1024, 256>>>();
    k_w2p<<<dim3(32, 4), 256>>>(wout, mem_kv);
    k_final<<<dim3(64, 32), 256, SMEM_K5>>>(bout, y);
}

// round 3
// speedup vs baseline: 1.1635x; 1.0619x over previous
#include <cuda_runtime.h>
#include <cuda_bf16.h>
#include <math.h>

// Problem constants
#define BATCH 32
#define CCH   128      // channels
#define NTOK  4096     // H*W
#define NH    4        // heads
#define DH    32       // dim head
#define QKV3  384      // 3*hidden
#define NSPLIT 16      // token splits for context partials

// ---------------- scratch (device globals; no allocation allowed) ----------
__device__ float g_qkv[(size_t)BATCH * QKV3 * NTOK];          // ~201 MB
__device__ float g_wg[QKV3 * CCH];                            // g-folded qkv weights
__device__ float g_kmax[BATCH * NH * DH];
__device__ float g_ksum[BATCH * NH * DH];
__device__ float g_ctx_part[NSPLIT * BATCH * NH * DH * DH];   // split ctx partials
__device__ float g_w2t[BATCH * CCH * CCH];                    // W2 transposed: [b][c][o]

// ---------------- f32x2 packed FMA helpers (sm_100+) ------------------------
__device__ __forceinline__ unsigned long long pack2(float x, float y) {
    unsigned long long r;
    asm("mov.b64 %0, {%1, %2};" : "=l"(r) : "f"(x), "f"(y));
    return r;
}
__device__ __forceinline__ void fma2(unsigned long long &d, unsigned long long a,
                                     unsigned long long b) {
    asm("fma.rn.f32x2 %0, %1, %2, %3;" : "=l"(d) : "l"(a), "l"(b), "l"(d));
}
__device__ __forceinline__ float2 unpack2(unsigned long long v) {
    float lo, hi;
    asm("mov.b64 {%0, %1}, %2;" : "=f"(lo), "=f"(hi) : "l"(v));
    return make_float2(lo, hi);
}

// ============================================================================
// K0: fold g[k] * sqrt(C) into qkv weights.  49152 elements.
// ============================================================================
__global__ void k_prepw(const float* __restrict__ wqkv, const float* __restrict__ g) {
    int i = blockIdx.x * 256 + threadIdx.x;   // < 49152
    int k = i & 127;
    g_wg[i] = wqkv[i] * g[k] * 11.313708498984761f;
}

// ============================================================================
// K1: fused RMSNorm + qkv projection GEMM.
// Per block: output tile [128 rows x 64 tokens], K = 128 (full channel dim).
// grid (ntile=64, mtile=3, b=32), block 256.
// ============================================================================
__global__ __launch_bounds__(256, 2)
void k_qkv(const float* __restrict__ x) {
    extern __shared__ float sm1[];
    float* xs   = sm1;                 // 8192
    float* wst  = sm1 + 8192;          // 128*132 = 16896
    float* red  = wst + 16896;         // 256
    float* invs = red + 256;           // 64

    const int nt = blockIdx.x, mt = blockIdx.y, b = blockIdx.z;
    const int tid = threadIdx.x;
    const int t = tid & 63, cq = tid >> 6;

    // load x tile into registers; per-token partial sum of squares
    const float* xb = x + (size_t)b * CCH * NTOK + (size_t)nt * 64 + t;
    float v[32];
    float s = 0.f;
    #pragma unroll
    for (int i = 0; i < 32; i++) {
        v[i] = xb[(size_t)(cq + 4 * i) * NTOK];
        s += v[i] * v[i];
    }
    red[cq * 64 + t] = s;

    // load W tile transposed: wst[k][r] = Wg[mt*128 + r][k]
    const float* wb = g_wg + (size_t)mt * 128 * CCH;
    #pragma unroll
    for (int i = 0; i < 64; i++) {
        int idx = tid + i * 256;
        int k = idx & 127, r = idx >> 7;
        wst[k * 132 + r] = wb[r * CCH + k];
    }
    __syncthreads();

    if (tid < 64) {
        float ss = red[tid] + red[64 + tid] + red[128 + tid] + red[192 + tid];
        invs[tid] = 1.0f / fmaxf(sqrtf(ss), 1e-12f);
    }
    __syncthreads();

    {
        const float it = invs[t];
        #pragma unroll
        for (int i = 0; i < 32; i++)
            xs[(cq + 4 * i) * 64 + t] = v[i] * it;
    }
    __syncthreads();

    // GEMM: thread tile 8 rows x 4 cols, rows packed in f32x2 pairs
    const int ty = tid >> 4, tx = tid & 15;
    unsigned long long acc[4][4];
    #pragma unroll
    for (int p = 0; p < 4; p++)
        #pragma unroll
        for (int c = 0; c < 4; c++) acc[p][c] = 0ull;

    #pragma unroll 4
    for (int k = 0; k < 128; k++) {
        const ulonglong2 a01 = *reinterpret_cast<const ulonglong2*>(&wst[k * 132 + ty * 8]);
        const ulonglong2 a23 = *reinterpret_cast<const ulonglong2*>(&wst[k * 132 + ty * 8 + 4]);
        unsigned long long a2[4] = {a01.x, a01.y, a23.x, a23.y};
        const float4 bv = *reinterpret_cast<const float4*>(&xs[k * 64 + tx * 4]);
        unsigned long long bd[4] = {pack2(bv.x, bv.x), pack2(bv.y, bv.y),
                                    pack2(bv.z, bv.z), pack2(bv.w, bv.w)};
        #pragma unroll
        for (int p = 0; p < 4; p++)
            #pragma unroll
            for (int c = 0; c < 4; c++)
                fma2(acc[p][c], a2[p], bd[c]);
    }

    float* outb = g_qkv + ((size_t)b * QKV3 + (size_t)mt * 128) * NTOK + (size_t)nt * 64;
    #pragma unroll
    for (int p = 0; p < 4; p++) {
        float2 c0 = unpack2(acc[p][0]), c1 = unpack2(acc[p][1]);
        float2 c2 = unpack2(acc[p][2]), c3 = unpack2(acc[p][3]);
        float4 lo = make_float4(c0.x, c1.x, c2.x, c3.x);
        float4 hi = make_float4(c0.y, c1.y, c2.y, c3.y);
        size_t base = (size_t)(ty * 8 + 2 * p) * NTOK + tx * 4;
        *reinterpret_cast<float4*>(outb + base)        = lo;
        *reinterpret_cast<float4*>(outb + base + NTOK) = hi;
    }
}

// ============================================================================
// K2: per (b,h,d) row of k: max and sum(exp) over 4096 tokens + 4 memory slots.
// grid 4096, block 256.  Warp-shuffle reductions.
// ============================================================================
__global__ void k_kstats(const float* __restrict__ mem_kv) {
    __shared__ float wred[8];
    const int row = blockIdx.x;
    const int b = row >> 7, hd = row & 127;
    const int tid = threadIdx.x;
    const int lane = tid & 31, wid = tid >> 5;
    const float* kp = g_qkv + ((size_t)(b * QKV3 + CCH + hd)) * NTOK;

    float vals[16];
    float m = -1e30f;
    #pragma unroll
    for (int i = 0; i < 16; i++) {
        vals[i] = kp[tid + i * 256];
        m = fmaxf(m, vals[i]);
    }
    #pragma unroll
    for (int o = 16; o > 0; o >>= 1)
        m = fmaxf(m, __shfl_xor_sync(0xFFFFFFFFu, m, o));
    if (lane == 0) wred[wid] = m;
    __syncthreads();
    if (tid == 0) {
        float mm = wred[0];
        #pragma unroll
        for (int w = 1; w < 8; w++) mm = fmaxf(mm, wred[w]);
        #pragma unroll
        for (int j = 0; j < 4; j++)
            mm = fmaxf(mm, mem_kv[hd * 4 + j]);
        wred[0] = mm;
    }
    __syncthreads();
    const float M = wred[0];
    __syncthreads();

    float s = 0.f;
    #pragma unroll
    for (int i = 0; i < 16; i++) s += __expf(vals[i] - M);
    #pragma unroll
    for (int o = 16; o > 0; o >>= 1)
        s += __shfl_xor_sync(0xFFFFFFFFu, s, o);
    if (lane == 0) wred[wid] = s;
    __syncthreads();
    if (tid == 0) {
        float tot = 0.f;
        #pragma unroll
        for (int w = 0; w < 8; w++) tot += wred[w];
        #pragma unroll
        for (int j = 0; j < 4; j++) tot += __expf(mem_kv[hd * 4 + j] - M);
        g_kmax[row] = M;
        g_ksum[row] = tot;
    }
}

// ============================================================================
// K3: context partials: ctx[d][e] += sum_n exp(k[d,n]-max_d) * v[e,n]
// grid 128*NSPLIT blocks (NSPLIT token splits of 256), block 256.
// 4 groups x 64 threads; group handles a 32-token slab; 4x4 thread tile,
// f32x2 packed MACs over token pairs.  Deterministic per-split partials.
// ============================================================================
__global__ __launch_bounds__(256, 3)
void k_context() {
    __shared__ float es[32 * 132];
    __shared__ float vs[32 * 132];
    __shared__ float kms[32];
    const int blk = blockIdx.x;
    const int bh = blk >> 4, split = blk & (NSPLIT - 1);
    const int b = bh >> 2, h = bh & 3;
    const int tid = threadIdx.x;

    if (tid < 32) kms[tid] = g_kmax[bh * 32 + tid];
    const int grp = tid >> 6, lt = tid & 63;
    const int d0 = (lt >> 3) * 4, e0 = (lt & 7) * 4;
    const int tb = grp * 32;

    unsigned long long acc[4][4];
    #pragma unroll
    for (int i = 0; i < 4; i++)
        #pragma unroll
        for (int j = 0; j < 4; j++) acc[i][j] = 0ull;

    const float* kbase = g_qkv + ((size_t)(b * QKV3 + CCH + h * DH)) * NTOK;
    const float* vbase = g_qkv + ((size_t)(b * QKV3 + 2 * CCH + h * DH)) * NTOK;
    const int t0 = split * 256;
    __syncthreads();

    for (int c0 = 0; c0 < 256; c0 += 128) {
        // vectorized staging: 32 rows x 32 float4-cols per array
        #pragma unroll
        for (int i = 0; i < 4; i++) {
            int f4 = tid + i * 256;
            int d = f4 >> 5, tq = (f4 & 31) * 4;
            const float4 kv4 = *reinterpret_cast<const float4*>(
                &kbase[(size_t)d * NTOK + t0 + c0 + tq]);
            const float4 vv4 = *reinterpret_cast<const float4*>(
                &vbase[(size_t)d * NTOK + t0 + c0 + tq]);
            const float km = kms[d];
            float4 e4 = make_float4(__expf(kv4.x - km), __expf(kv4.y - km),
                                    __expf(kv4.z - km), __expf(kv4.w - km));
            *reinterpret_cast<float4*>(&es[d * 132 + tq]) = e4;
            *reinterpret_cast<float4*>(&vs[d * 132 + tq]) = vv4;
        }
        __syncthreads();

        #pragma unroll
        for (int t4 = 0; t4 < 32; t4 += 4) {
            ulonglong2 a2[4], b2[4];
            #pragma unroll
            for (int i = 0; i < 4; i++)
                a2[i] = *reinterpret_cast<const ulonglong2*>(&es[(d0 + i) * 132 + tb + t4]);
            #pragma unroll
            for (int j = 0; j < 4; j++)
                b2[j] = *reinterpret_cast<const ulonglong2*>(&vs[(e0 + j) * 132 + tb + t4]);
            #pragma unroll
            for (int i = 0; i < 4; i++)
                #pragma unroll
                for (int j = 0; j < 4; j++) {
                    fma2(acc[i][j], a2[i].x, b2[j].x);
                    fma2(acc[i][j], a2[i].y, b2[j].y);
                }
        }
        __syncthreads();
    }

    // combine the 4 groups deterministically through smem
    float* part = es;   // 4096 floats needed, es holds 4224
    #pragma unroll
    for (int i = 0; i < 4; i++)
        #pragma unroll
        for (int j = 0; j < 4; j++) {
            float2 p = unpack2(acc[i][j]);
            part[grp * 1024 + (d0 + i) * 32 + (e0 + j)] = p.x + p.y;
        }
    __syncthreads();
    for (int idx = tid; idx < 1024; idx += 256) {
        float s = part[idx] + part[idx + 1024] + part[idx + 2048] + part[idx + 3072];
        g_ctx_part[((size_t)split * 128 + bh) * 1024 + idx] = s;
    }
}

// ============================================================================
// K4: fold w_out through normalized context -> W2t[b][c][o].
// grid (32 b, 4 o-tiles of 32), block 256.
// ============================================================================
__global__ void k_w2p(const float* __restrict__ wout, const float* __restrict__ mem_kv) {
    __shared__ float ce[128 * 36];
    __shared__ float ws[32 * 132];
    __shared__ float ews[512];
    __shared__ float invz[128];
    const int b = blockIdx.x, og = blockIdx.y;
    const int tid = threadIdx.x;

    for (int idx = tid; idx < 512; idx += 256) {
        int c = idx >> 2;
        ews[idx] = __expf(mem_kv[idx] - g_kmax[b * 128 + c]);
    }
    if (tid < 128) invz[tid] = 1.0f / g_ksum[b * 128 + tid];
    #pragma unroll
    for (int i = 0; i < 16; i++) {
        int idx = tid + i * 256;
        ws[(idx >> 7) * 132 + (idx & 127)] = wout[og * 32 * 128 + idx];
    }
    __syncthreads();

    for (int idx = tid; idx < 4096; idx += 256) {
        int c = idx >> 5, e = idx & 31, h = c >> 5, d = c & 31;
        size_t base = (size_t)(b * 4 + h) * 1024 + d * 32 + e;
        float vsum = 0.f;
        #pragma unroll
        for (int s = 0; s < NSPLIT; s++)
            vsum += g_ctx_part[(size_t)s * 131072 + base];
        #pragma unroll
        for (int j = 0; j < 4; j++)
            vsum = fmaf(ews[c * 4 + j], mem_kv[512 + ((h * 32 + e) * 4 + j)], vsum);
        ce[c * 36 + e] = vsum * invz[c];
    }
    __syncthreads();

    const int o_l = tid >> 3;
    const int cb = tid & 7;
    const int o = og * 32 + o_l;
    const float* wr = &ws[o_l * 132];
    #pragma unroll
    for (int ci = 0; ci < 16; ci++) {
        int c = cb + ci * 8;
        const float* cr = &ce[c * 36];
        const float* wrr = wr + (c >> 5) * 32;
        float a = 0.f;
        #pragma unroll
        for (int e4 = 0; e4 < 32; e4 += 4) {
            float4 w4 = *reinterpret_cast<const float4*>(wrr + e4);
            float4 c4 = *reinterpret_cast<const float4*>(cr + e4);
            a = fmaf(w4.x, c4.x, a);
            a = fmaf(w4.y, c4.y, a);
            a = fmaf(w4.z, c4.z, a);
            a = fmaf(w4.w, c4.w, a);
        }
        g_w2t[((size_t)b * 128 + c) * 128 + o] = a;
    }
}

// ============================================================================
// K5: fused q-softmax + output GEMM y = W2 @ qs + bias.
// grid (64 token tiles, 32 b), block 256.  Tile [128 x 64], K = 128.
// ============================================================================
__global__ __launch_bounds__(256, 2)
void k_final(const float* __restrict__ bout, float* __restrict__ y) {
    extern __shared__ float sm5[];
    float* qsm = sm5;                 // 8192
    float* w2t = sm5 + 8192;          // 16896
    float* bs  = w2t + 16896;         // 128

    const int nt = blockIdx.x, b = blockIdx.y;
    const int tid = threadIdx.x;

    const float* qg = g_qkv + (size_t)b * QKV3 * NTOK + (size_t)nt * 64;
    #pragma unroll
    for (int i = 0; i < 32; i++) {
        int idx = tid + i * 256;
        int c = idx >> 6, t = idx & 63;
        qsm[c * 64 + t] = qg[(size_t)c * NTOK + t];
    }
    const float* wg = g_w2t + (size_t)b * 16384;
    #pragma unroll
    for (int i = 0; i < 64; i++) {
        int idx = tid + i * 256;
        int c = idx >> 7, o = idx & 127;
        w2t[c * 132 + o] = wg[idx];
    }
    if (tid < 128) bs[tid] = bout[tid];
    __syncthreads();

    {
        const int h = tid >> 6, t = tid & 63;
        float qv[32];
        float m = -1e30f;
        #pragma unroll
        for (int d = 0; d < 32; d++) {
            qv[d] = qsm[(h * 32 + d) * 64 + t];
            m = fmaxf(m, qv[d]);
        }
        float ss = 0.f;
        #pragma unroll
        for (int d = 0; d < 32; d++) {
            qv[d] = __expf(qv[d] - m);
            ss += qv[d];
        }
        const float inv = 0.17677669529663687f / ss;
        #pragma unroll
        for (int d = 0; d < 32; d++)
            qsm[(h * 32 + d) * 64 + t] = qv[d] * inv;
    }
    __syncthreads();

    const int ty = tid >> 4, tx = tid & 15;
    unsigned long long acc[4][4];
    #pragma unroll
    for (int p = 0; p < 4; p++)
        #pragma unroll
        for (int c = 0; c < 4; c++) acc[p][c] = 0ull;

    #pragma unroll 4
    for (int k = 0; k < 128; k++) {
        const ulonglong2 a01 = *reinterpret_cast<const ulonglong2*>(&w2t[k * 132 + ty * 8]);
        const ulonglong2 a23 = *reinterpret_cast<const ulonglong2*>(&w2t[k * 132 + ty * 8 + 4]);
        unsigned long long a2[4] = {a01.x, a01.y, a23.x, a23.y};
        const float4 bv = *reinterpret_cast<const float4*>(&qsm[k * 64 + tx * 4]);
        unsigned long long bd[4] = {pack2(bv.x, bv.x), pack2(bv.y, bv.y),
                                    pack2(bv.z, bv.z), pack2(bv.w, bv.w)};
        #pragma unroll
        for (int p = 0; p < 4; p++)
            #pragma unroll
            for (int c = 0; c < 4; c++)
                fma2(acc[p][c], a2[p], bd[c]);
    }

    #pragma unroll
    for (int p = 0; p < 4; p++) {
        const int r0 = ty * 8 + 2 * p;
        const float b0 = bs[r0], b1 = bs[r0 + 1];
        float2 c0 = unpack2(acc[p][0]), c1 = unpack2(acc[p][1]);
        float2 c2 = unpack2(acc[p][2]), c3 = unpack2(acc[p][3]);
        float4 lo = make_float4(c0.x + b0, c1.x + b0, c2.x + b0, c3.x + b0);
        float4 hi = make_float4(c0.y + b1, c1.y + b1, c2.y + b1, c3.y + b1);
        size_t base = ((size_t)b * CCH + r0) * NTOK + (size_t)nt * 64 + tx * 4;
        *reinterpret_cast<float4*>(y + base)        = lo;
        *reinterpret_cast<float4*>(y + base + NTOK) = hi;
    }
}

// ============================================================================
extern "C" void kernel_launch(void* const* d_in, const int* in_sizes, int n_in,
                              void* d_out, int out_size) {
    const float* x      = (const float*)d_in[0];
    const float* g      = (const float*)d_in[1];
    const float* wqkv   = (const float*)d_in[2];
    const float* mem_kv = (const float*)d_in[3];
    const float* wout   = (const float*)d_in[4];
    const float* bout   = (const float*)d_in[5];
    float* y = (float*)d_out;

    const int SMEM_K1 = 25408 * 4;   // 101632 B
    const int SMEM_K5 = 25216 * 4;   // 100864 B
    cudaFuncSetAttribute(k_qkv,   cudaFuncAttributeMaxDynamicSharedMemorySize, SMEM_K1);
    cudaFuncSetAttribute(k_final, cudaFuncAttributeMaxDynamicSharedMemorySize, SMEM_K5);

    k_prepw<<<192, 256>>>(wqkv, g);
    k_qkv<<<dim3(64, 3, 32), 256, SMEM_K1>>>(x);
    k_kstats<<<4096, 256>>>(mem_kv);
    k_context<<<128 * NSPLIT, 256>>>();
    k_w2p<<<dim3(32, 4), 256>>>(wout, mem_kv);
    k_final<<<dim3(64, 32), 256, SMEM_K5>>>(bout, y);
}

// round 5
// speedup vs baseline: 1.2589x; 1.0820x over previous
#include <cuda_runtime.h>
#include <cuda_bf16.h>
#include <math.h>

// Problem constants
#define BATCH 32
#define CCH   128      // channels
#define NTOK  4096     // H*W
#define NH    4        // heads
#define DH    32       // dim head
#define QKV3  384      // 3*hidden
#define NSPLIT 16      // token splits for context partials

// ---------------- scratch (device globals; no allocation allowed) ----------
__device__ float g_qkv[(size_t)BATCH * QKV3 * NTOK];          // ~201 MB
__device__ float g_wg[QKV3 * CCH];                            // g-folded qkv weights
__device__ float g_kmax[BATCH * NH * DH];
__device__ float g_ksum[BATCH * NH * DH];
__device__ float g_ctx_part[NSPLIT * BATCH * NH * DH * DH];   // split ctx partials
__device__ float g_w2t[BATCH * CCH * CCH];                    // W2 transposed: [b][c][o]

// ---------------- f32x2 packed FMA helpers (sm_100+) ------------------------
__device__ __forceinline__ unsigned long long pack2(float x, float y) {
    unsigned long long r;
    asm("mov.b64 %0, {%1, %2};" : "=l"(r) : "f"(x), "f"(y));
    return r;
}
__device__ __forceinline__ void fma2(unsigned long long &d, unsigned long long a,
                                     unsigned long long b) {
    asm("fma.rn.f32x2 %0, %1, %2, %3;" : "=l"(d) : "l"(a), "l"(b), "l"(d));
}
__device__ __forceinline__ float2 unpack2(unsigned long long v) {
    float lo, hi;
    asm("mov.b64 {%0, %1}, %2;" : "=f"(lo), "=f"(hi) : "l"(v));
    return make_float2(lo, hi);
}

// ============================================================================
// K0: fold g[k] * sqrt(C) into qkv weights.  49152 elements.
// ============================================================================
__global__ void k_prepw(const float* __restrict__ wqkv, const float* __restrict__ g) {
    int i = blockIdx.x * 256 + threadIdx.x;   // < 49152
    int k = i & 127;
    g_wg[i] = wqkv[i] * g[k] * 11.313708498984761f;
}

// ============================================================================
// K1: fused RMSNorm + qkv projection GEMM.
// Per block: output tile [128 rows x 64 tokens], K = 128 (full channel dim).
// grid (ntile=64, mtile=3, b=32), block 256.
// ============================================================================
__global__ __launch_bounds__(256, 2)
void k_qkv(const float* __restrict__ x) {
    extern __shared__ float sm1[];
    float* xs   = sm1;                 // 8192
    float* wst  = sm1 + 8192;          // 128*132 = 16896
    float* red  = wst + 16896;         // 256
    float* invs = red + 256;           // 64

    const int nt = blockIdx.x, mt = blockIdx.y, b = blockIdx.z;
    const int tid = threadIdx.x;
    const int t = tid & 63, cq = tid >> 6;

    // load x tile into registers; per-token partial sum of squares
    const float* xb = x + (size_t)b * CCH * NTOK + (size_t)nt * 64 + t;
    float v[32];
    float s = 0.f;
    #pragma unroll
    for (int i = 0; i < 32; i++) {
        v[i] = xb[(size_t)(cq + 4 * i) * NTOK];
        s += v[i] * v[i];
    }
    red[cq * 64 + t] = s;

    // load W tile transposed: wst[k][r] = Wg[mt*128 + r][k]
    const float* wb = g_wg + (size_t)mt * 128 * CCH;
    #pragma unroll
    for (int i = 0; i < 64; i++) {
        int idx = tid + i * 256;
        int k = idx & 127, r = idx >> 7;
        wst[k * 132 + r] = wb[r * CCH + k];
    }
    __syncthreads();

    if (tid < 64) {
        float ss = red[tid] + red[64 + tid] + red[128 + tid] + red[192 + tid];
        invs[tid] = 1.0f / fmaxf(sqrtf(ss), 1e-12f);
    }
    __syncthreads();

    {
        const float it = invs[t];
        #pragma unroll
        for (int i = 0; i < 32; i++)
            xs[(cq + 4 * i) * 64 + t] = v[i] * it;
    }
    __syncthreads();

    // GEMM: thread tile 8 rows x 4 cols, rows packed in f32x2 pairs
    const int ty = tid >> 4, tx = tid & 15;
    unsigned long long acc[4][4];
    #pragma unroll
    for (int p = 0; p < 4; p++)
        #pragma unroll
        for (int c = 0; c < 4; c++) acc[p][c] = 0ull;

    #pragma unroll 4
    for (int k = 0; k < 128; k++) {
        const ulonglong2 a01 = *reinterpret_cast<const ulonglong2*>(&wst[k * 132 + ty * 8]);
        const ulonglong2 a23 = *reinterpret_cast<const ulonglong2*>(&wst[k * 132 + ty * 8 + 4]);
        unsigned long long a2[4] = {a01.x, a01.y, a23.x, a23.y};
        const float4 bv = *reinterpret_cast<const float4*>(&xs[k * 64 + tx * 4]);
        unsigned long long bd[4] = {pack2(bv.x, bv.x), pack2(bv.y, bv.y),
                                    pack2(bv.z, bv.z), pack2(bv.w, bv.w)};
        #pragma unroll
        for (int p = 0; p < 4; p++)
            #pragma unroll
            for (int c = 0; c < 4; c++)
                fma2(acc[p][c], a2[p], bd[c]);
    }

    float* outb = g_qkv + ((size_t)b * QKV3 + (size_t)mt * 128) * NTOK + (size_t)nt * 64;
    #pragma unroll
    for (int p = 0; p < 4; p++) {
        float2 c0 = unpack2(acc[p][0]), c1 = unpack2(acc[p][1]);
        float2 c2 = unpack2(acc[p][2]), c3 = unpack2(acc[p][3]);
        float4 lo = make_float4(c0.x, c1.x, c2.x, c3.x);
        float4 hi = make_float4(c0.y, c1.y, c2.y, c3.y);
        size_t base = (size_t)(ty * 8 + 2 * p) * NTOK + tx * 4;
        *reinterpret_cast<float4*>(outb + base)        = lo;
        *reinterpret_cast<float4*>(outb + base + NTOK) = hi;
    }
}

// ============================================================================
// K2: per (b,h,d) row of k: max and sum(exp) over 4096 tokens + 4 memory slots.
// grid 4096, block 256.  Warp-shuffle reductions.
// ============================================================================
__global__ void k_kstats(const float* __restrict__ mem_kv) {
    __shared__ float wred[8];
    const int row = blockIdx.x;
    const int b = row >> 7, hd = row & 127;
    const int tid = threadIdx.x;
    const int lane = tid & 31, wid = tid >> 5;
    const float* kp = g_qkv + ((size_t)(b * QKV3 + CCH + hd)) * NTOK;

    float vals[16];
    float m = -1e30f;
    #pragma unroll
    for (int i = 0; i < 16; i++) {
        vals[i] = kp[tid + i * 256];
        m = fmaxf(m, vals[i]);
    }
    #pragma unroll
    for (int o = 16; o > 0; o >>= 1)
        m = fmaxf(m, __shfl_xor_sync(0xFFFFFFFFu, m, o));
    if (lane == 0) wred[wid] = m;
    __syncthreads();
    if (tid == 0) {
        float mm = wred[0];
        #pragma unroll
        for (int w = 1; w < 8; w++) mm = fmaxf(mm, wred[w]);
        #pragma unroll
        for (int j = 0; j < 4; j++)
            mm = fmaxf(mm, mem_kv[hd * 4 + j]);
        wred[0] = mm;
    }
    __syncthreads();
    const float M = wred[0];
    __syncthreads();

    float s = 0.f;
    #pragma unroll
    for (int i = 0; i < 16; i++) s += __expf(vals[i] - M);
    #pragma unroll
    for (int o = 16; o > 0; o >>= 1)
        s += __shfl_xor_sync(0xFFFFFFFFu, s, o);
    if (lane == 0) wred[wid] = s;
    __syncthreads();
    if (tid == 0) {
        float tot = 0.f;
        #pragma unroll
        for (int w = 0; w < 8; w++) tot += wred[w];
        #pragma unroll
        for (int j = 0; j < 4; j++) tot += __expf(mem_kv[hd * 4 + j] - M);
        g_kmax[row] = M;
        g_ksum[row] = tot;
    }
}

// ============================================================================
// K3: context partials: ctx[d][e] += sum_n exp(k[d,n]-max_d) * v[e,n]
// grid 128*NSPLIT blocks (NSPLIT token splits of 256), block 256.
// 4 groups x 64 threads; group handles a 32-token slab; 4x4 thread tile with
// CYCLIC row mapping (d rows d0+8i, e rows e0+8j, d0=lt>>3, e0=lt&7) so each
// LDS.128 instruction's lanes span 8 consecutive rows -> distinct banks ->
// conflict-free.  f32x2 packed MACs over token pairs.
// ============================================================================
__global__ __launch_bounds__(256, 3)
void k_context() {
    __shared__ float es[32 * 132];
    __shared__ float vs[32 * 132];
    __shared__ float kms[32];
    const int blk = blockIdx.x;
    const int bh = blk >> 4, split = blk & (NSPLIT - 1);
    const int b = bh >> 2, h = bh & 3;
    const int tid = threadIdx.x;

    if (tid < 32) kms[tid] = g_kmax[bh * 32 + tid];
    const int grp = tid >> 6, lt = tid & 63;
    const int d0 = lt >> 3;          // 0..7 (consecutive rows across lanes)
    const int e0 = lt & 7;           // 0..7
    const int tb = grp * 32;

    unsigned long long acc[4][4];
    #pragma unroll
    for (int i = 0; i < 4; i++)
        #pragma unroll
        for (int j = 0; j < 4; j++) acc[i][j] = 0ull;

    const float* kbase = g_qkv + ((size_t)(b * QKV3 + CCH + h * DH)) * NTOK;
    const float* vbase = g_qkv + ((size_t)(b * QKV3 + 2 * CCH + h * DH)) * NTOK;
    const int t0 = split * 256;
    __syncthreads();

    for (int c0 = 0; c0 < 256; c0 += 128) {
        // vectorized staging: 32 rows x 32 float4-cols per array
        #pragma unroll
        for (int i = 0; i < 4; i++) {
            int f4 = tid + i * 256;
            int d = f4 >> 5, tq = (f4 & 31) * 4;
            const float4 kv4 = *reinterpret_cast<const float4*>(
                &kbase[(size_t)d * NTOK + t0 + c0 + tq]);
            const float4 vv4 = *reinterpret_cast<const float4*>(
                &vbase[(size_t)d * NTOK + t0 + c0 + tq]);
            const float km = kms[d];
            float4 e4 = make_float4(__expf(kv4.x - km), __expf(kv4.y - km),
                                    __expf(kv4.z - km), __expf(kv4.w - km));
            *reinterpret_cast<float4*>(&es[d * 132 + tq]) = e4;
            *reinterpret_cast<float4*>(&vs[d * 132 + tq]) = vv4;
        }
        __syncthreads();

        #pragma unroll
        for (int t4 = 0; t4 < 32; t4 += 4) {
            ulonglong2 a2[4], b2[4];
            #pragma unroll
            for (int i = 0; i < 4; i++)
                a2[i] = *reinterpret_cast<const ulonglong2*>(&es[(d0 + 8 * i) * 132 + tb + t4]);
            #pragma unroll
            for (int j = 0; j < 4; j++)
                b2[j] = *reinterpret_cast<const ulonglong2*>(&vs[(e0 + 8 * j) * 132 + tb + t4]);
            #pragma unroll
            for (int i = 0; i < 4; i++)
                #pragma unroll
                for (int j = 0; j < 4; j++) {
                    fma2(acc[i][j], a2[i].x, b2[j].x);
                    fma2(acc[i][j], a2[i].y, b2[j].y);
                }
        }
        __syncthreads();
    }

    // combine the 4 groups deterministically through smem
    float* part = es;   // 4096 floats needed, es holds 4224
    #pragma unroll
    for (int i = 0; i < 4; i++)
        #pragma unroll
        for (int j = 0; j < 4; j++) {
            float2 p = unpack2(acc[i][j]);
            part[grp * 1024 + (d0 + 8 * i) * 32 + (e0 + 8 * j)] = p.x + p.y;
        }
    __syncthreads();
    for (int idx = tid; idx < 1024; idx += 256) {
        float s = part[idx] + part[idx + 1024] + part[idx + 2048] + part[idx + 3072];
        g_ctx_part[((size_t)split * 128 + bh) * 1024 + idx] = s;
    }
}

// ============================================================================
// K4: fold w_out through normalized context -> W2t[b][c][o].
// grid (32 b, 4 o-tiles of 32), block 256.
// ============================================================================
__global__ void k_w2p(const float* __restrict__ wout, const float* __restrict__ mem_kv) {
    __shared__ float ce[128 * 36];
    __shared__ float ws[32 * 132];
    __shared__ float ews[512];
    __shared__ float invz[128];
    const int b = blockIdx.x, og = blockIdx.y;
    const int tid = threadIdx.x;

    for (int idx = tid; idx < 512; idx += 256) {
        int c = idx >> 2;
        ews[idx] = __expf(mem_kv[idx] - g_kmax[b * 128 + c]);
    }
    if (tid < 128) invz[tid] = 1.0f / g_ksum[b * 128 + tid];
    #pragma unroll
    for (int i = 0; i < 16; i++) {
        int idx = tid + i * 256;
        ws[(idx >> 7) * 132 + (idx & 127)] = wout[og * 32 * 128 + idx];
    }
    __syncthreads();

    for (int idx = tid; idx < 4096; idx += 256) {
        int c = idx >> 5, e = idx & 31, h = c >> 5, d = c & 31;
        size_t base = (size_t)(b * 4 + h) * 1024 + d * 32 + e;
        float vsum = 0.f;
        #pragma unroll
        for (int s = 0; s < NSPLIT; s++)
            vsum += g_ctx_part[(size_t)s * 131072 + base];
        #pragma unroll
        for (int j = 0; j < 4; j++)
            vsum = fmaf(ews[c * 4 + j], mem_kv[512 + ((h * 32 + e) * 4 + j)], vsum);
        ce[c * 36 + e] = vsum * invz[c];
    }
    __syncthreads();

    const int o_l = tid >> 3;
    const int cb = tid & 7;
    const int o = og * 32 + o_l;
    const float* wr = &ws[o_l * 132];
    #pragma unroll
    for (int ci = 0; ci < 16; ci++) {
        int c = cb + ci * 8;
        const float* cr = &ce[c * 36];
        const float* wrr = wr + (c >> 5) * 32;
        float a = 0.f;
        #pragma unroll
        for (int e4 = 0; e4 < 32; e4 += 4) {
            float4 w4 = *reinterpret_cast<const float4*>(wrr + e4);
            float4 c4 = *reinterpret_cast<const float4*>(cr + e4);
            a = fmaf(w4.x, c4.x, a);
            a = fmaf(w4.y, c4.y, a);
            a = fmaf(w4.z, c4.z, a);
            a = fmaf(w4.w, c4.w, a);
        }
        g_w2t[((size_t)b * 128 + c) * 128 + o] = a;
    }
}

// ============================================================================
// K5: fused q-softmax + output GEMM y = W2 @ qs + bias.
// grid (64 token tiles, 32 b), block 256.  Tile [128 x 64], K = 128.
// ============================================================================
__global__ __launch_bounds__(256, 2)
void k_final(const float* __restrict__ bout, float* __restrict__ y) {
    extern __shared__ float sm5[];
    float* qsm = sm5;                 // 8192
    float* w2t = sm5 + 8192;          // 16896
    float* bs  = w2t + 16896;         // 128

    const int nt = blockIdx.x, b = blockIdx.y;
    const int tid = threadIdx.x;

    const float* qg = g_qkv + (size_t)b * QKV3 * NTOK + (size_t)nt * 64;
    #pragma unroll
    for (int i = 0; i < 32; i++) {
        int idx = tid + i * 256;
        int c = idx >> 6, t = idx & 63;
        qsm[c * 64 + t] = qg[(size_t)c * NTOK + t];
    }
    const float* wg = g_w2t + (size_t)b * 16384;
    #pragma unroll
    for (int i = 0; i < 64; i++) {
        int idx = tid + i * 256;
        int c = idx >> 7, o = idx & 127;
        w2t[c * 132 + o] = wg[idx];
    }
    if (tid < 128) bs[tid] = bout[tid];
    __syncthreads();

    {
        const int h = tid >> 6, t = tid & 63;
        float qv[32];
        float m = -1e30f;
        #pragma unroll
        for (int d = 0; d < 32; d++) {
            qv[d] = qsm[(h * 32 + d) * 64 + t];
            m = fmaxf(m, qv[d]);
        }
        float ss = 0.f;
        #pragma unroll
        for (int d = 0; d < 32; d++) {
            qv[d] = __expf(qv[d] - m);
            ss += qv[d];
        }
        const float inv = 0.17677669529663687f / ss;
        #pragma unroll
        for (int d = 0; d < 32; d++)
            qsm[(h * 32 + d) * 64 + t] = qv[d] * inv;
    }
    __syncthreads();

    const int ty = tid >> 4, tx = tid & 15;
    unsigned long long acc[4][4];
    #pragma unroll
    for (int p = 0; p < 4; p++)
        #pragma unroll
        for (int c = 0; c < 4; c++) acc[p][c] = 0ull;

    #pragma unroll 4
    for (int k = 0; k < 128; k++) {
        const ulonglong2 a01 = *reinterpret_cast<const ulonglong2*>(&w2t[k * 132 + ty * 8]);
        const ulonglong2 a23 = *reinterpret_cast<const ulonglong2*>(&w2t[k * 132 + ty * 8 + 4]);
        unsigned long long a2[4] = {a01.x, a01.y, a23.x, a23.y};
        const float4 bv = *reinterpret_cast<const float4*>(&qsm[k * 64 + tx * 4]);
        unsigned long long bd[4] = {pack2(bv.x, bv.x), pack2(bv.y, bv.y),
                                    pack2(bv.z, bv.z), pack2(bv.w, bv.w)};
        #pragma unroll
        for (int p = 0; p < 4; p++)
            #pragma unroll
            for (int c = 0; c < 4; c++)
                fma2(acc[p][c], a2[p], bd[c]);
    }

    #pragma unroll
    for (int p = 0; p < 4; p++) {
        const int r0 = ty * 8 + 2 * p;
        const float b0 = bs[r0], b1 = bs[r0 + 1];
        float2 c0 = unpack2(acc[p][0]), c1 = unpack2(acc[p][1]);
        float2 c2 = unpack2(acc[p][2]), c3 = unpack2(acc[p][3]);
        float4 lo = make_float4(c0.x + b0, c1.x + b0, c2.x + b0, c3.x + b0);
        float4 hi = make_float4(c0.y + b1, c1.y + b1, c2.y + b1, c3.y + b1);
        size_t base = ((size_t)b * CCH + r0) * NTOK + (size_t)nt * 64 + tx * 4;
        *reinterpret_cast<float4*>(y + base)        = lo;
        *reinterpret_cast<float4*>(y + base + NTOK) = hi;
    }
}

// ============================================================================
extern "C" void kernel_launch(void* const* d_in, const int* in_sizes, int n_in,
                              void* d_out, int out_size) {
    const float* x      = (const float*)d_in[0];
    const float* g      = (const float*)d_in[1];
    const float* wqkv   = (const float*)d_in[2];
    const float* mem_kv = (const float*)d_in[3];
    const float* wout   = (const float*)d_in[4];
    const float* bout   = (const float*)d_in[5];
    float* y = (float*)d_out;

    const int SMEM_K1 = 25408 * 4;   // 101632 B
    const int SMEM_K5 = 25216 * 4;   // 100864 B
    cudaFuncSetAttribute(k_qkv,   cudaFuncAttributeMaxDynamicSharedMemorySize, SMEM_K1);
    cudaFuncSetAttribute(k_final, cudaFuncAttributeMaxDynamicSharedMemorySize, SMEM_K5);

    k_prepw<<<192, 256>>>(wqkv, g);
    k_qkv<<<dim3(64, 3, 32), 256, SMEM_K1>>>(x);
    k_kstats<<<4096, 256>>>(mem_kv);
    k_context<<<128 * NSPLIT, 256>>>();
    k_w2p<<<dim3(32, 4), 256>>>(wout, mem_kv);
    k_final<<<dim3(64, 32), 256, SMEM_K5>>>(bout, y);
}

// round 9
// speedup vs baseline: 1.7218x; 1.3677x over previous
#include <cuda_runtime.h>
#include <cuda_bf16.h>
#include <cstdint>
#include <math.h>

// Problem constants
#define BATCH 32
#define CCH   128      // channels
#define NTOK  4096     // H*W
#define NH    4        // heads
#define DH    32       // dim head
#define QKV3  384      // 3*hidden
#define NSPLIT 16      // token splits for context partials

// ---------------- scratch (device globals; no allocation allowed) ----------
__device__ float g_qkv[(size_t)BATCH * QKV3 * NTOK];          // ~201 MB
__device__ float g_wt[QKV3 * CCH];                            // g-folded W, tf32-rounded
__device__ float g_kmax[BATCH * NH * DH];
__device__ float g_ksum[BATCH * NH * DH];
__device__ float g_ctx_part[NSPLIT * BATCH * NH * DH * DH];   // split ctx partials
__device__ float g_w2t[BATCH * CCH * CCH];                    // W2 transposed: [b][c][o]

// ---------------- f32x2 packed FMA helpers (sm_100+) ------------------------
__device__ __forceinline__ unsigned long long pack2(float x, float y) {
    unsigned long long r;
    asm("mov.b64 %0, {%1, %2};" : "=l"(r) : "f"(x), "f"(y));
    return r;
}
__device__ __forceinline__ void fma2(unsigned long long &d, unsigned long long a,
                                     unsigned long long b) {
    asm("fma.rn.f32x2 %0, %1, %2, %3;" : "=l"(d) : "l"(a), "l"(b), "l"(d));
}
__device__ __forceinline__ float2 unpack2(unsigned long long v) {
    float lo, hi;
    asm("mov.b64 {%0, %1}, %2;" : "=f"(lo), "=f"(hi) : "l"(v));
    return make_float2(lo, hi);
}

__device__ __forceinline__ uint32_t f2tf32(float v) {
    uint32_t t;
    asm("cvt.rna.tf32.f32 %0, %1;" : "=r"(t) : "f"(v));
    return t;
}

// mma.sync m16n8k8 tf32 (base ISA, works on compute_103)
__device__ __forceinline__ void mma_tf32(float* d, const uint32_t* a, const uint32_t* bb) {
    asm volatile(
        "mma.sync.aligned.m16n8k8.row.col.f32.tf32.tf32.f32 "
        "{%0,%1,%2,%3}, {%4,%5,%6,%7}, {%8,%9}, {%0,%1,%2,%3};"
        : "+f"(d[0]), "+f"(d[1]), "+f"(d[2]), "+f"(d[3])
        : "r"(a[0]), "r"(a[1]), "r"(a[2]), "r"(a[3]), "r"(bb[0]), "r"(bb[1]));
}

// ============================================================================
// K0: fold g[k]*sqrt(C) into qkv weights, round to tf32.  49152 elements.
// ============================================================================
__global__ void k_prepw(const float* __restrict__ wqkv, const float* __restrict__ g) {
    int i = blockIdx.x * 256 + threadIdx.x;   // < 49152
    int k = i & 127;
    float w = wqkv[i] * g[k] * 11.313708498984761f;
    g_wt[i] = __uint_as_float(f2tf32(w));
}

// ============================================================================
// K1: fused RMSNorm + qkv GEMM on tensor cores (mma.sync tf32, 1 pass).
// CTA tile M=128 x N=64 tokens x K=128.  grid (64 ntiles, 3 mt, 32 b), 256 thr
// (8 warps: 2 along M x 4 along N; warp tile 64x16).
// A (W) in smem XOR-swizzled [m][ (k+4m)&127 ]; B (x, tf32) [k][ (n+8k)&63 ].
// Per-token 1/||x|| applied in epilogue (norm is a per-column scalar).
// ============================================================================
__global__ __launch_bounds__(256, 2)
void k_qkv_mma(const float* __restrict__ x) {
    extern __shared__ float sm[];
    float* a_s  = sm;            // 16384
    float* xs   = sm + 16384;    // 8192
    float* red  = sm + 24576;    // 256
    float* invs = sm + 24832;    // 64   (total 24896 floats = 99584 B)

    const int nt = blockIdx.x, mt = blockIdx.y, b = blockIdx.z;
    const int tid = threadIdx.x;

    // ---- A: W tile [128][128], XOR swizzle ----
    const float* wb = g_wt + mt * 128 * 128;
    #pragma unroll
    for (int i = 0; i < 64; i++) {
        int idx = tid + i * 256;
        int m = idx >> 7, k = idx & 127;
        a_s[m * 128 + ((k + 4 * m) & 127)] = wb[idx];
    }

    // ---- B: x tile [128 ch][64 tok], tf32-round, + ssq partials ----
    {
        const int t = tid & 63, cq = tid >> 6;
        const float* xc = x + (size_t)b * CCH * NTOK + (size_t)nt * 64 + t;
        float ss = 0.f;
        #pragma unroll
        for (int i = 0; i < 32; i++) {
            int c = cq * 32 + i;
            float v = xc[(size_t)c * NTOK];
            ss += v * v;
            xs[c * 64 + ((t + 8 * c) & 63)] = __uint_as_float(f2tf32(v));
        }
        red[cq * 64 + t] = ss;
    }
    __syncthreads();
    if (tid < 64) {
        float ss = red[tid] + red[64 + tid] + red[128 + tid] + red[192 + tid];
        invs[tid] = 1.0f / fmaxf(sqrtf(ss), 1e-12f);
    }
    __syncthreads();

    // ---- MMA mainloop ----
    const int lane = tid & 31, w = tid >> 5;
    const int wm = w >> 2, wn = w & 3;
    const int r4 = lane >> 2, c4 = lane & 3;

    float acc[4][2][4];
    #pragma unroll
    for (int mi = 0; mi < 4; mi++)
        #pragma unroll
        for (int ni = 0; ni < 2; ni++)
            #pragma unroll
            for (int q = 0; q < 4; q++) acc[mi][ni][q] = 0.f;

    const uint32_t* a_u = reinterpret_cast<const uint32_t*>(a_s);
    const uint32_t* x_u = reinterpret_cast<const uint32_t*>(xs);

    #pragma unroll
    for (int ks = 0; ks < 16; ks++) {
        const int k0 = ks * 8;
        uint32_t af[4][4];
        uint32_t bf[2][2];
        #pragma unroll
        for (int mi = 0; mi < 4; mi++) {
            int r0 = wm * 64 + mi * 16 + r4;
            int r1 = r0 + 8;
            int ka = k0 + c4;
            af[mi][0] = a_u[r0 * 128 + ((ka + 4 * r0) & 127)];
            af[mi][1] = a_u[r1 * 128 + ((ka + 4 * r1) & 127)];
            af[mi][2] = a_u[r0 * 128 + ((ka + 4 + 4 * r0) & 127)];
            af[mi][3] = a_u[r1 * 128 + ((ka + 4 + 4 * r1) & 127)];
        }
        #pragma unroll
        for (int ni = 0; ni < 2; ni++) {
            int n0 = wn * 16 + ni * 8 + r4;
            int kb0 = k0 + c4, kb1 = kb0 + 4;
            bf[ni][0] = x_u[kb0 * 64 + ((n0 + 8 * kb0) & 63)];
            bf[ni][1] = x_u[kb1 * 64 + ((n0 + 8 * kb1) & 63)];
        }
        #pragma unroll
        for (int mi = 0; mi < 4; mi++)
            #pragma unroll
            for (int ni = 0; ni < 2; ni++)
                mma_tf32(acc[mi][ni], af[mi], bf[ni]);
    }

    // ---- epilogue: scale by invs[token], float2 stores (32B sectors) ----
    float* outb = g_qkv + ((size_t)b * QKV3 + (size_t)mt * 128) * NTOK + (size_t)nt * 64;
    #pragma unroll
    for (int mi = 0; mi < 4; mi++) {
        #pragma unroll
        for (int ni = 0; ni < 2; ni++) {
            int col = wn * 16 + ni * 8 + 2 * c4;
            float i0 = invs[col], i1 = invs[col + 1];
            int row0 = wm * 64 + mi * 16 + r4;
            float2 v0 = make_float2(acc[mi][ni][0] * i0, acc[mi][ni][1] * i1);
            float2 v1 = make_float2(acc[mi][ni][2] * i0, acc[mi][ni][3] * i1);
            *reinterpret_cast<float2*>(&outb[(size_t)row0 * NTOK + col]) = v0;
            *reinterpret_cast<float2*>(&outb[(size_t)(row0 + 8) * NTOK + col]) = v1;
        }
    }
}

// ============================================================================
// K2: per (b,h,d) row of k: max and sum(exp) over 4096 tokens + 4 memory slots.
// ============================================================================
__global__ void k_kstats(const float* __restrict__ mem_kv) {
    __shared__ float wred[8];
    const int row = blockIdx.x;
    const int b = row >> 7, hd = row & 127;
    const int tid = threadIdx.x;
    const int lane = tid & 31, wid = tid >> 5;
    const float* kp = g_qkv + ((size_t)(b * QKV3 + CCH + hd)) * NTOK;

    float vals[16];
    float m = -1e30f;
    #pragma unroll
    for (int i = 0; i < 16; i++) {
        vals[i] = kp[tid + i * 256];
        m = fmaxf(m, vals[i]);
    }
    #pragma unroll
    for (int o = 16; o > 0; o >>= 1)
        m = fmaxf(m, __shfl_xor_sync(0xFFFFFFFFu, m, o));
    if (lane == 0) wred[wid] = m;
    __syncthreads();
    if (tid == 0) {
        float mm = wred[0];
        #pragma unroll
        for (int w = 1; w < 8; w++) mm = fmaxf(mm, wred[w]);
        #pragma unroll
        for (int j = 0; j < 4; j++)
            mm = fmaxf(mm, mem_kv[hd * 4 + j]);
        wred[0] = mm;
    }
    __syncthreads();
    const float M = wred[0];
    __syncthreads();

    float s = 0.f;
    #pragma unroll
    for (int i = 0; i < 16; i++) s += __expf(vals[i] - M);
    #pragma unroll
    for (int o = 16; o > 0; o >>= 1)
        s += __shfl_xor_sync(0xFFFFFFFFu, s, o);
    if (lane == 0) wred[wid] = s;
    __syncthreads();
    if (tid == 0) {
        float tot = 0.f;
        #pragma unroll
        for (int w = 0; w < 8; w++) tot += wred[w];
        #pragma unroll
        for (int j = 0; j < 4; j++) tot += __expf(mem_kv[hd * 4 + j] - M);
        g_kmax[row] = M;
        g_ksum[row] = tot;
    }
}

// ============================================================================
// K3: context partials (conflict-free cyclic tile, f32x2 MACs).
// ============================================================================
__global__ __launch_bounds__(256, 3)
void k_context() {
    __shared__ float es[32 * 132];
    __shared__ float vs[32 * 132];
    __shared__ float kms[32];
    const int blk = blockIdx.x;
    const int bh = blk >> 4, split = blk & (NSPLIT - 1);
    const int b = bh >> 2, h = bh & 3;
    const int tid = threadIdx.x;

    if (tid < 32) kms[tid] = g_kmax[bh * 32 + tid];
    const int grp = tid >> 6, lt = tid & 63;
    const int d0 = lt >> 3;
    const int e0 = lt & 7;
    const int tb = grp * 32;

    unsigned long long acc[4][4];
    #pragma unroll
    for (int i = 0; i < 4; i++)
        #pragma unroll
        for (int j = 0; j < 4; j++) acc[i][j] = 0ull;

    const float* kbase = g_qkv + ((size_t)(b * QKV3 + CCH + h * DH)) * NTOK;
    const float* vbase = g_qkv + ((size_t)(b * QKV3 + 2 * CCH + h * DH)) * NTOK;
    const int t0 = split * 256;
    __syncthreads();

    for (int c0 = 0; c0 < 256; c0 += 128) {
        #pragma unroll
        for (int i = 0; i < 4; i++) {
            int f4 = tid + i * 256;
            int d = f4 >> 5, tq = (f4 & 31) * 4;
            const float4 kv4 = *reinterpret_cast<const float4*>(
                &kbase[(size_t)d * NTOK + t0 + c0 + tq]);
            const float4 vv4 = *reinterpret_cast<const float4*>(
                &vbase[(size_t)d * NTOK + t0 + c0 + tq]);
            const float km = kms[d];
            float4 e4 = make_float4(__expf(kv4.x - km), __expf(kv4.y - km),
                                    __expf(kv4.z - km), __expf(kv4.w - km));
            *reinterpret_cast<float4*>(&es[d * 132 + tq]) = e4;
            *reinterpret_cast<float4*>(&vs[d * 132 + tq]) = vv4;
        }
        __syncthreads();

        #pragma unroll
        for (int t4 = 0; t4 < 32; t4 += 4) {
            ulonglong2 a2[4], b2[4];
            #pragma unroll
            for (int i = 0; i < 4; i++)
                a2[i] = *reinterpret_cast<const ulonglong2*>(&es[(d0 + 8 * i) * 132 + tb + t4]);
            #pragma unroll
            for (int j = 0; j < 4; j++)
                b2[j] = *reinterpret_cast<const ulonglong2*>(&vs[(e0 + 8 * j) * 132 + tb + t4]);
            #pragma unroll
            for (int i = 0; i < 4; i++)
                #pragma unroll
                for (int j = 0; j < 4; j++) {
                    fma2(acc[i][j], a2[i].x, b2[j].x);
                    fma2(acc[i][j], a2[i].y, b2[j].y);
                }
        }
        __syncthreads();
    }

    float* part = es;
    #pragma unroll
    for (int i = 0; i < 4; i++)
        #pragma unroll
        for (int j = 0; j < 4; j++) {
            float2 p = unpack2(acc[i][j]);
            part[grp * 1024 + (d0 + 8 * i) * 32 + (e0 + 8 * j)] = p.x + p.y;
        }
    __syncthreads();
    for (int idx = tid; idx < 1024; idx += 256) {
        float s = part[idx] + part[idx + 1024] + part[idx + 2048] + part[idx + 3072];
        g_ctx_part[((size_t)split * 128 + bh) * 1024 + idx] = s;
    }
}

// ============================================================================
// K4: fold w_out through normalized context -> W2t[b][c][o].
// ============================================================================
__global__ void k_w2p(const float* __restrict__ wout, const float* __restrict__ mem_kv) {
    __shared__ float ce[128 * 36];
    __shared__ float ws[32 * 132];
    __shared__ float ews[512];
    __shared__ float invz[128];
    const int b = blockIdx.x, og = blockIdx.y;
    const int tid = threadIdx.x;

    for (int idx = tid; idx < 512; idx += 256) {
        int c = idx >> 2;
        ews[idx] = __expf(mem_kv[idx] - g_kmax[b * 128 + c]);
    }
    if (tid < 128) invz[tid] = 1.0f / g_ksum[b * 128 + tid];
    #pragma unroll
    for (int i = 0; i < 16; i++) {
        int idx = tid + i * 256;
        ws[(idx >> 7) * 132 + (idx & 127)] = wout[og * 32 * 128 + idx];
    }
    __syncthreads();

    for (int idx = tid; idx < 4096; idx += 256) {
        int c = idx >> 5, e = idx & 31, h = c >> 5, d = c & 31;
        size_t base = (size_t)(b * 4 + h) * 1024 + d * 32 + e;
        float vsum = 0.f;
        #pragma unroll
        for (int s = 0; s < NSPLIT; s++)
            vsum += g_ctx_part[(size_t)s * 131072 + base];
        #pragma unroll
        for (int j = 0; j < 4; j++)
            vsum = fmaf(ews[c * 4 + j], mem_kv[512 + ((h * 32 + e) * 4 + j)], vsum);
        ce[c * 36 + e] = vsum * invz[c];
    }
    __syncthreads();

    const int o_l = tid >> 3;
    const int cb = tid & 7;
    const int o = og * 32 + o_l;
    const float* wr = &ws[o_l * 132];
    #pragma unroll
    for (int ci = 0; ci < 16; ci++) {
        int c = cb + ci * 8;
        const float* cr = &ce[c * 36];
        const float* wrr = wr + (c >> 5) * 32;
        float a = 0.f;
        #pragma unroll
        for (int e4 = 0; e4 < 32; e4 += 4) {
            float4 w4 = *reinterpret_cast<const float4*>(wrr + e4);
            float4 c4 = *reinterpret_cast<const float4*>(cr + e4);
            a = fmaf(w4.x, c4.x, a);
            a = fmaf(w4.y, c4.y, a);
            a = fmaf(w4.z, c4.z, a);
            a = fmaf(w4.w, c4.w, a);
        }
        g_w2t[((size_t)b * 128 + c) * 128 + o] = a;
    }
}

// ============================================================================
// K5: fused q-softmax + output GEMM y = W2 @ qs + bias.
// ============================================================================
__global__ __launch_bounds__(256, 2)
void k_final(const float* __restrict__ bout, float* __restrict__ y) {
    extern __shared__ float sm5[];
    float* qsm = sm5;                 // 8192
    float* w2t = sm5 + 8192;          // 16896
    float* bs  = w2t + 16896;         // 128

    const int nt = blockIdx.x, b = blockIdx.y;
    const int tid = threadIdx.x;

    const float* qg = g_qkv + (size_t)b * QKV3 * NTOK + (size_t)nt * 64;
    #pragma unroll
    for (int i = 0; i < 32; i++) {
        int idx = tid + i * 256;
        int c = idx >> 6, t = idx & 63;
        qsm[c * 64 + t] = qg[(size_t)c * NTOK + t];
    }
    const float* wg = g_w2t + (size_t)b * 16384;
    #pragma unroll
    for (int i = 0; i < 64; i++) {
        int idx = tid + i * 256;
        int c = idx >> 7, o = idx & 127;
        w2t[c * 132 + o] = wg[idx];
    }
    if (tid < 128) bs[tid] = bout[tid];
    __syncthreads();

    {
        const int h = tid >> 6, t = tid & 63;
        float qv[32];
        float m = -1e30f;
        #pragma unroll
        for (int d = 0; d < 32; d++) {
            qv[d] = qsm[(h * 32 + d) * 64 + t];
            m = fmaxf(m, qv[d]);
        }
        float ss = 0.f;
        #pragma unroll
        for (int d = 0; d < 32; d++) {
            qv[d] = __expf(qv[d] - m);
            ss += qv[d];
        }
        const float inv = 0.17677669529663687f / ss;
        #pragma unroll
        for (int d = 0; d < 32; d++)
            qsm[(h * 32 + d) * 64 + t] = qv[d] * inv;
    }
    __syncthreads();

    const int ty = tid >> 4, tx = tid & 15;
    unsigned long long acc[4][4];
    #pragma unroll
    for (int p = 0; p < 4; p++)
        #pragma unroll
        for (int c = 0; c < 4; c++) acc[p][c] = 0ull;

    #pragma unroll 4
    for (int k = 0; k < 128; k++) {
        const ulonglong2 a01 = *reinterpret_cast<const ulonglong2*>(&w2t[k * 132 + ty * 8]);
        const ulonglong2 a23 = *reinterpret_cast<const ulonglong2*>(&w2t[k * 132 + ty * 8 + 4]);
        unsigned long long a2[4] = {a01.x, a01.y, a23.x, a23.y};
        const float4 bv = *reinterpret_cast<const float4*>(&qsm[k * 64 + tx * 4]);
        unsigned long long bd[4] = {pack2(bv.x, bv.x), pack2(bv.y, bv.y),
                                    pack2(bv.z, bv.z), pack2(bv.w, bv.w)};
        #pragma unroll
        for (int p = 0; p < 4; p++)
            #pragma unroll
            for (int c = 0; c < 4; c++)
                fma2(acc[p][c], a2[p], bd[c]);
    }

    #pragma unroll
    for (int p = 0; p < 4; p++) {
        const int r0 = ty * 8 + 2 * p;
        const float b0 = bs[r0], b1 = bs[r0 + 1];
        float2 c0 = unpack2(acc[p][0]), c1 = unpack2(acc[p][1]);
        float2 c2 = unpack2(acc[p][2]), c3 = unpack2(acc[p][3]);
        float4 lo = make_float4(c0.x + b0, c1.x + b0, c2.x + b0, c3.x + b0);
        float4 hi = make_float4(c0.y + b1, c1.y + b1, c2.y + b1, c3.y + b1);
        size_t base = ((size_t)b * CCH + r0) * NTOK + (size_t)nt * 64 + tx * 4;
        *reinterpret_cast<float4*>(y + base)        = lo;
        *reinterpret_cast<float4*>(y + base + NTOK) = hi;
    }
}

// ============================================================================
extern "C" void kernel_launch(void* const* d_in, const int* in_sizes, int n_in,
                              void* d_out, int out_size) {
    const float* x      = (const float*)d_in[0];
    const float* g      = (const float*)d_in[1];
    const float* wqkv   = (const float*)d_in[2];
    const float* mem_kv = (const float*)d_in[3];
    const float* wout   = (const float*)d_in[4];
    const float* bout   = (const float*)d_in[5];
    float* y = (float*)d_out;

    const int SMEM_K1 = 24896 * 4;   // 99584 B
    const int SMEM_K5 = 25216 * 4;   // 100864 B
    cudaFuncSetAttribute(k_qkv_mma, cudaFuncAttributeMaxDynamicSharedMemorySize, SMEM_K1);
    cudaFuncSetAttribute(k_final,   cudaFuncAttributeMaxDynamicSharedMemorySize, SMEM_K5);

    k_prepw<<<192, 256>>>(wqkv, g);
    k_qkv_mma<<<dim3(64, 3, 32), 256, SMEM_K1>>>(x);
    k_kstats<<<4096, 256>>>(mem_kv);
    k_context<<<128 * NSPLIT, 256>>>();
    k_w2p<<<dim3(32, 4), 256>>>(wout, mem_kv);
    k_final<<<dim3(64, 32), 256, SMEM_K5>>>(bout, y);
}

// round 10
// speedup vs baseline: 2.1177x; 1.2299x over previous
#include <cuda_runtime.h>
#include <cuda_bf16.h>
#include <cstdint>
#include <math.h>

// Problem constants
#define BATCH 32
#define CCH   128      // channels
#define NTOK  4096     // H*W
#define NH    4        // heads
#define DH    32       // dim head
#define QKV3  384      // 3*hidden
#define NSPLIT 16      // token splits for context partials

// ---------------- scratch (device globals; no allocation allowed) ----------
__device__ float g_qkv[(size_t)BATCH * QKV3 * NTOK];          // ~201 MB
__device__ float g_wt[QKV3 * CCH];                            // g-folded W, tf32-rounded
__device__ float g_ctx_part[NSPLIT * BATCH * NH * DH * DH];   // split ctx partials
__device__ float g_zpart[NSPLIT * BATCH * NH * DH];           // split Z partials
__device__ float g_w2[BATCH * CCH * CCH];                     // W2: [b][o][c]

// ---------------- f32x2 packed FMA helpers (sm_100+) ------------------------
__device__ __forceinline__ unsigned long long pack2(float x, float y) {
    unsigned long long r;
    asm("mov.b64 %0, {%1, %2};" : "=l"(r) : "f"(x), "f"(y));
    return r;
}
__device__ __forceinline__ void fma2(unsigned long long &d, unsigned long long a,
                                     unsigned long long b) {
    asm("fma.rn.f32x2 %0, %1, %2, %3;" : "=l"(d) : "l"(a), "l"(b), "l"(d));
}
__device__ __forceinline__ float2 unpack2(unsigned long long v) {
    float lo, hi;
    asm("mov.b64 {%0, %1}, %2;" : "=f"(lo), "=f"(hi) : "l"(v));
    return make_float2(lo, hi);
}

__device__ __forceinline__ uint32_t f2tf32(float v) {
    uint32_t t;
    asm("cvt.rna.tf32.f32 %0, %1;" : "=r"(t) : "f"(v));
    return t;
}

// mma.sync m16n8k8 tf32 (base ISA, works on compute_103)
__device__ __forceinline__ void mma_tf32(float* d, const uint32_t* a, const uint32_t* bb) {
    asm volatile(
        "mma.sync.aligned.m16n8k8.row.col.f32.tf32.tf32.f32 "
        "{%0,%1,%2,%3}, {%4,%5,%6,%7}, {%8,%9}, {%0,%1,%2,%3};"
        : "+f"(d[0]), "+f"(d[1]), "+f"(d[2]), "+f"(d[3])
        : "r"(a[0]), "r"(a[1]), "r"(a[2]), "r"(a[3]), "r"(bb[0]), "r"(bb[1]));
}

// ============================================================================
// K0: fold g[k]*sqrt(C) into qkv weights, round to tf32.  49152 elements.
// ============================================================================
__global__ void k_prepw(const float* __restrict__ wqkv, const float* __restrict__ g) {
    int i = blockIdx.x * 256 + threadIdx.x;   // < 49152
    int k = i & 127;
    float w = wqkv[i] * g[k] * 11.313708498984761f;
    g_wt[i] = __uint_as_float(f2tf32(w));
}

// ============================================================================
// K1: fused RMSNorm + qkv GEMM on tensor cores (mma.sync tf32, 1 pass).
// CTA tile M=128 x N=64 tokens x K=128.  grid (64 ntiles, 3 mt, 32 b), 256 thr.
// ============================================================================
__global__ __launch_bounds__(256, 2)
void k_qkv_mma(const float* __restrict__ x) {
    extern __shared__ float sm[];
    float* a_s  = sm;            // 16384
    float* xs   = sm + 16384;    // 8192
    float* red  = sm + 24576;    // 256
    float* invs = sm + 24832;    // 64   (total 24896 floats)

    const int nt = blockIdx.x, mt = blockIdx.y, b = blockIdx.z;
    const int tid = threadIdx.x;

    // ---- A: W tile [128][128], XOR swizzle ----
    const float* wb = g_wt + mt * 128 * 128;
    #pragma unroll
    for (int i = 0; i < 64; i++) {
        int idx = tid + i * 256;
        int m = idx >> 7, k = idx & 127;
        a_s[m * 128 + ((k + 4 * m) & 127)] = wb[idx];
    }

    // ---- B: x tile [128 ch][64 tok], tf32-round, + ssq partials ----
    {
        const int t = tid & 63, cq = tid >> 6;
        const float* xc = x + (size_t)b * CCH * NTOK + (size_t)nt * 64 + t;
        float ss = 0.f;
        #pragma unroll
        for (int i = 0; i < 32; i++) {
            int c = cq * 32 + i;
            float v = xc[(size_t)c * NTOK];
            ss += v * v;
            xs[c * 64 + ((t + 8 * c) & 63)] = __uint_as_float(f2tf32(v));
        }
        red[cq * 64 + t] = ss;
    }
    __syncthreads();
    if (tid < 64) {
        float ss = red[tid] + red[64 + tid] + red[128 + tid] + red[192 + tid];
        invs[tid] = 1.0f / fmaxf(sqrtf(ss), 1e-12f);
    }
    __syncthreads();

    // ---- MMA mainloop ----
    const int lane = tid & 31, w = tid >> 5;
    const int wm = w >> 2, wn = w & 3;
    const int r4 = lane >> 2, c4 = lane & 3;

    float acc[4][2][4];
    #pragma unroll
    for (int mi = 0; mi < 4; mi++)
        #pragma unroll
        for (int ni = 0; ni < 2; ni++)
            #pragma unroll
            for (int q = 0; q < 4; q++) acc[mi][ni][q] = 0.f;

    const uint32_t* a_u = reinterpret_cast<const uint32_t*>(a_s);
    const uint32_t* x_u = reinterpret_cast<const uint32_t*>(xs);

    #pragma unroll
    for (int ks = 0; ks < 16; ks++) {
        const int k0 = ks * 8;
        uint32_t af[4][4];
        uint32_t bf[2][2];
        #pragma unroll
        for (int mi = 0; mi < 4; mi++) {
            int r0 = wm * 64 + mi * 16 + r4;
            int r1 = r0 + 8;
            int ka = k0 + c4;
            af[mi][0] = a_u[r0 * 128 + ((ka + 4 * r0) & 127)];
            af[mi][1] = a_u[r1 * 128 + ((ka + 4 * r1) & 127)];
            af[mi][2] = a_u[r0 * 128 + ((ka + 4 + 4 * r0) & 127)];
            af[mi][3] = a_u[r1 * 128 + ((ka + 4 + 4 * r1) & 127)];
        }
        #pragma unroll
        for (int ni = 0; ni < 2; ni++) {
            int n0 = wn * 16 + ni * 8 + r4;
            int kb0 = k0 + c4, kb1 = kb0 + 4;
            bf[ni][0] = x_u[kb0 * 64 + ((n0 + 8 * kb0) & 63)];
            bf[ni][1] = x_u[kb1 * 64 + ((n0 + 8 * kb1) & 63)];
        }
        #pragma unroll
        for (int mi = 0; mi < 4; mi++)
            #pragma unroll
            for (int ni = 0; ni < 2; ni++)
                mma_tf32(acc[mi][ni], af[mi], bf[ni]);
    }

    // ---- epilogue: scale by invs[token], float2 stores ----
    float* outb = g_qkv + ((size_t)b * QKV3 + (size_t)mt * 128) * NTOK + (size_t)nt * 64;
    #pragma unroll
    for (int mi = 0; mi < 4; mi++) {
        #pragma unroll
        for (int ni = 0; ni < 2; ni++) {
            int col = wn * 16 + ni * 8 + 2 * c4;
            float i0 = invs[col], i1 = invs[col + 1];
            int row0 = wm * 64 + mi * 16 + r4;
            float2 v0 = make_float2(acc[mi][ni][0] * i0, acc[mi][ni][1] * i1);
            float2 v1 = make_float2(acc[mi][ni][2] * i0, acc[mi][ni][3] * i1);
            *reinterpret_cast<float2*>(&outb[(size_t)row0 * NTOK + col]) = v0;
            *reinterpret_cast<float2*>(&outb[(size_t)(row0 + 8) * NTOK + col]) = v1;
        }
    }
}

// ============================================================================
// K3: context partials UNSTABILIZED: es = exp(k) (values bounded ~e^3.5, safe).
// Also emits per-split Z row sums (Z_d = sum_n exp(k[d,n])) via warp shuffles.
// grid 128*NSPLIT, block 256.  Conflict-free cyclic 4x4 tile, f32x2 MACs.
// ============================================================================
__global__ __launch_bounds__(256, 3)
void k_context() {
    __shared__ float es[32 * 132];
    __shared__ float vs[32 * 132];
    const int blk = blockIdx.x;
    const int bh = blk >> 4, split = blk & (NSPLIT - 1);
    const int b = bh >> 2, h = bh & 3;
    const int tid = threadIdx.x;

    const int grp = tid >> 6, lt = tid & 63;
    const int d0 = lt >> 3;
    const int e0 = lt & 7;
    const int tb = grp * 32;

    unsigned long long acc[4][4];
    #pragma unroll
    for (int i = 0; i < 4; i++)
        #pragma unroll
        for (int j = 0; j < 4; j++) acc[i][j] = 0ull;

    float zp[4] = {0.f, 0.f, 0.f, 0.f};

    const float* kbase = g_qkv + ((size_t)(b * QKV3 + CCH + h * DH)) * NTOK;
    const float* vbase = g_qkv + ((size_t)(b * QKV3 + 2 * CCH + h * DH)) * NTOK;
    const int t0 = split * 256;

    for (int c0 = 0; c0 < 256; c0 += 128) {
        #pragma unroll
        for (int i = 0; i < 4; i++) {
            int f4 = tid + i * 256;
            int d = f4 >> 5, tq = (f4 & 31) * 4;
            const float4 kv4 = *reinterpret_cast<const float4*>(
                &kbase[(size_t)d * NTOK + t0 + c0 + tq]);
            const float4 vv4 = *reinterpret_cast<const float4*>(
                &vbase[(size_t)d * NTOK + t0 + c0 + tq]);
            float4 e4 = make_float4(__expf(kv4.x), __expf(kv4.y),
                                    __expf(kv4.z), __expf(kv4.w));
            zp[i] += e4.x + e4.y + e4.z + e4.w;
            *reinterpret_cast<float4*>(&es[d * 132 + tq]) = e4;
            *reinterpret_cast<float4*>(&vs[d * 132 + tq]) = vv4;
        }
        __syncthreads();

        #pragma unroll
        for (int t4 = 0; t4 < 32; t4 += 4) {
            ulonglong2 a2[4], b2[4];
            #pragma unroll
            for (int i = 0; i < 4; i++)
                a2[i] = *reinterpret_cast<const ulonglong2*>(&es[(d0 + 8 * i) * 132 + tb + t4]);
            #pragma unroll
            for (int j = 0; j < 4; j++)
                b2[j] = *reinterpret_cast<const ulonglong2*>(&vs[(e0 + 8 * j) * 132 + tb + t4]);
            #pragma unroll
            for (int i = 0; i < 4; i++)
                #pragma unroll
                for (int j = 0; j < 4; j++) {
                    fma2(acc[i][j], a2[i].x, b2[j].x);
                    fma2(acc[i][j], a2[i].y, b2[j].y);
                }
        }
        __syncthreads();
    }

    // ---- Z partials: row d = (tid>>5) + 8i is owned entirely by warp tid>>5
    {
        const int lane = tid & 31, wrp = tid >> 5;
        #pragma unroll
        for (int i = 0; i < 4; i++) {
            float v = zp[i];
            #pragma unroll
            for (int o = 16; o > 0; o >>= 1)
                v += __shfl_xor_sync(0xFFFFFFFFu, v, o);
            if (lane == 0)
                g_zpart[split * (BATCH * NH * DH) + bh * 32 + (wrp + 8 * i)] = v;
        }
    }

    // ---- combine the 4 groups deterministically through smem ----
    float* part = es;
    #pragma unroll
    for (int i = 0; i < 4; i++)
        #pragma unroll
        for (int j = 0; j < 4; j++) {
            float2 p = unpack2(acc[i][j]);
            part[grp * 1024 + (d0 + 8 * i) * 32 + (e0 + 8 * j)] = p.x + p.y;
        }
    __syncthreads();
    for (int idx = tid; idx < 1024; idx += 256) {
        float s = part[idx] + part[idx + 1024] + part[idx + 2048] + part[idx + 3072];
        g_ctx_part[((size_t)split * 128 + bh) * 1024 + idx] = s;
    }
}

// ============================================================================
// K4: fold w_out through normalized context -> W2[b][o][c] (o-major for MMA).
// grid (32 b, 4 o-tiles of 32), block 256.
// ============================================================================
__global__ void k_w2p(const float* __restrict__ wout, const float* __restrict__ mem_kv) {
    __shared__ float ce[128 * 36];
    __shared__ float ws[32 * 132];
    __shared__ float ews[512];
    __shared__ float invz[128];
    const int b = blockIdx.x, og = blockIdx.y;
    const int tid = threadIdx.x;

    for (int idx = tid; idx < 512; idx += 256)
        ews[idx] = __expf(mem_kv[idx]);          // exp(mem_k), unstabilized
    #pragma unroll
    for (int i = 0; i < 16; i++) {
        int idx = tid + i * 256;
        ws[(idx >> 7) * 132 + (idx & 127)] = wout[og * 32 * 128 + idx];
    }
    __syncthreads();

    if (tid < 128) {
        float z = 0.f;
        #pragma unroll
        for (int s = 0; s < NSPLIT; s++)
            z += g_zpart[s * (BATCH * NH * DH) + b * 128 + tid];
        z += ews[tid * 4] + ews[tid * 4 + 1] + ews[tid * 4 + 2] + ews[tid * 4 + 3];
        invz[tid] = 1.0f / z;
    }
    __syncthreads();

    for (int idx = tid; idx < 4096; idx += 256) {
        int c = idx >> 5, e = idx & 31, h = c >> 5, d = c & 31;
        size_t base = (size_t)(b * 4 + h) * 1024 + d * 32 + e;
        float vsum = 0.f;
        #pragma unroll
        for (int s = 0; s < NSPLIT; s++)
            vsum += g_ctx_part[(size_t)s * 131072 + base];
        #pragma unroll
        for (int j = 0; j < 4; j++)
            vsum = fmaf(ews[c * 4 + j], mem_kv[512 + ((h * 32 + e) * 4 + j)], vsum);
        ce[c * 36 + e] = vsum * invz[c];
    }
    __syncthreads();

    const int o_l = tid >> 3;
    const int cb = tid & 7;
    const int o = og * 32 + o_l;
    const float* wr = &ws[o_l * 132];
    #pragma unroll
    for (int ci = 0; ci < 16; ci++) {
        int c = cb + ci * 8;
        const float* cr = &ce[c * 36];
        const float* wrr = wr + (c >> 5) * 32;
        float a = 0.f;
        #pragma unroll
        for (int e4 = 0; e4 < 32; e4 += 4) {
            float4 w4 = *reinterpret_cast<const float4*>(wrr + e4);
            float4 c4 = *reinterpret_cast<const float4*>(cr + e4);
            a = fmaf(w4.x, c4.x, a);
            a = fmaf(w4.y, c4.y, a);
            a = fmaf(w4.z, c4.z, a);
            a = fmaf(w4.w, c4.w, a);
        }
        g_w2[((size_t)b * 128 + o) * 128 + c] = a;   // [b][o][c]
    }
}

// ============================================================================
// K5: fused q-softmax + output GEMM on tensor cores (mma.sync tf32).
// CTA tile M=128(o) x N=64(t) x K=128(c).  grid (64 nt, 32 b), 256 thr.
// ============================================================================
__global__ __launch_bounds__(256, 2)
void k_final_mma(const float* __restrict__ bout, float* __restrict__ y) {
    extern __shared__ float sm5[];
    float* a_s = sm5;             // 16384  (W2 swizzled [o][(c+4o)&127])
    float* xs  = sm5 + 16384;     // 8192   (q swizzled [c][(t+8c)&63])
    float* bs  = sm5 + 24576;     // 128

    const int nt = blockIdx.x, b = blockIdx.y;
    const int tid = threadIdx.x;

    // ---- A: W2 tile [128 o][128 c], XOR swizzle (coalesced from [b][o][c]) ----
    const float* wg = g_w2 + (size_t)b * 16384;
    #pragma unroll
    for (int i = 0; i < 64; i++) {
        int idx = tid + i * 256;
        int o = idx >> 7, c = idx & 127;
        a_s[o * 128 + ((c + 4 * o) & 127)] = wg[idx];
    }

    // ---- B: q tile [128 c][64 t] into swizzled slots (fp32 for now) ----
    {
        const int t = tid & 63, cq = tid >> 6;
        const float* qc = g_qkv + (size_t)b * QKV3 * NTOK + (size_t)nt * 64 + t;
        #pragma unroll
        for (int i = 0; i < 32; i++) {
            int c = cq * 32 + i;
            xs[c * 64 + ((t + 8 * c) & 63)] = qc[(size_t)c * NTOK];
        }
    }
    if (tid < 128) bs[tid] = bout[tid];
    __syncthreads();

    // ---- softmax over d per (head, token), write back tf32 * scale ----
    {
        const int h = tid >> 6, t = tid & 63;
        float qv[32];
        float m = -1e30f;
        #pragma unroll
        for (int d = 0; d < 32; d++) {
            int c = h * 32 + d;
            qv[d] = xs[c * 64 + ((t + 8 * c) & 63)];
            m = fmaxf(m, qv[d]);
        }
        float ss = 0.f;
        #pragma unroll
        for (int d = 0; d < 32; d++) {
            qv[d] = __expf(qv[d] - m);
            ss += qv[d];
        }
        const float inv = 0.17677669529663687f / ss;
        #pragma unroll
        for (int d = 0; d < 32; d++) {
            int c = h * 32 + d;
            xs[c * 64 + ((t + 8 * c) & 63)] = __uint_as_float(f2tf32(qv[d] * inv));
        }
    }
    __syncthreads();

    // ---- MMA mainloop (identical structure to k_qkv_mma) ----
    const int lane = tid & 31, w = tid >> 5;
    const int wm = w >> 2, wn = w & 3;
    const int r4 = lane >> 2, c4 = lane & 3;

    float acc[4][2][4];
    #pragma unroll
    for (int mi = 0; mi < 4; mi++)
        #pragma unroll
        for (int ni = 0; ni < 2; ni++)
            #pragma unroll
            for (int q = 0; q < 4; q++) acc[mi][ni][q] = 0.f;

    const uint32_t* a_u = reinterpret_cast<const uint32_t*>(a_s);
    const uint32_t* x_u = reinterpret_cast<const uint32_t*>(xs);

    #pragma unroll
    for (int ks = 0; ks < 16; ks++) {
        const int k0 = ks * 8;
        uint32_t af[4][4];
        uint32_t bf[2][2];
        #pragma unroll
        for (int mi = 0; mi < 4; mi++) {
            int r0 = wm * 64 + mi * 16 + r4;
            int r1 = r0 + 8;
            int ka = k0 + c4;
            af[mi][0] = a_u[r0 * 128 + ((ka + 4 * r0) & 127)];
            af[mi][1] = a_u[r1 * 128 + ((ka + 4 * r1) & 127)];
            af[mi][2] = a_u[r0 * 128 + ((ka + 4 + 4 * r0) & 127)];
            af[mi][3] = a_u[r1 * 128 + ((ka + 4 + 4 * r1) & 127)];
        }
        #pragma unroll
        for (int ni = 0; ni < 2; ni++) {
            int n0 = wn * 16 + ni * 8 + r4;
            int kb0 = k0 + c4, kb1 = kb0 + 4;
            bf[ni][0] = x_u[kb0 * 64 + ((n0 + 8 * kb0) & 63)];
            bf[ni][1] = x_u[kb1 * 64 + ((n0 + 8 * kb1) & 63)];
        }
        #pragma unroll
        for (int mi = 0; mi < 4; mi++)
            #pragma unroll
            for (int ni = 0; ni < 2; ni++)
                mma_tf32(acc[mi][ni], af[mi], bf[ni]);
    }

    // ---- epilogue: + bias, float2 stores ----
    float* outb = y + (size_t)b * CCH * NTOK + (size_t)nt * 64;
    #pragma unroll
    for (int mi = 0; mi < 4; mi++) {
        #pragma unroll
        for (int ni = 0; ni < 2; ni++) {
            int col = wn * 16 + ni * 8 + 2 * c4;
            int row0 = wm * 64 + mi * 16 + r4;
            float b0 = bs[row0], b1 = bs[row0 + 8];
            float2 v0 = make_float2(acc[mi][ni][0] + b0, acc[mi][ni][1] + b0);
            float2 v1 = make_float2(acc[mi][ni][2] + b1, acc[mi][ni][3] + b1);
            *reinterpret_cast<float2*>(&outb[(size_t)row0 * NTOK + col]) = v0;
            *reinterpret_cast<float2*>(&outb[(size_t)(row0 + 8) * NTOK + col]) = v1;
        }
    }
}

// ============================================================================
extern "C" void kernel_launch(void* const* d_in, const int* in_sizes, int n_in,
                              void* d_out, int out_size) {
    const float* x      = (const float*)d_in[0];
    const float* g      = (const float*)d_in[1];
    const float* wqkv   = (const float*)d_in[2];
    const float* mem_kv = (const float*)d_in[3];
    const float* wout   = (const float*)d_in[4];
    const float* bout   = (const float*)d_in[5];
    float* y = (float*)d_out;

    const int SMEM_K1 = 24896 * 4;   // 99584 B
    const int SMEM_K5 = 24704 * 4;   // 98816 B
    cudaFuncSetAttribute(k_qkv_mma,   cudaFuncAttributeMaxDynamicSharedMemorySize, SMEM_K1);
    cudaFuncSetAttribute(k_final_mma, cudaFuncAttributeMaxDynamicSharedMemorySize, SMEM_K5);

    k_prepw<<<192, 256>>>(wqkv, g);
    k_qkv_mma<<<dim3(64, 3, 32), 256, SMEM_K1>>>(x);
    k_context<<<128 * NSPLIT, 256>>>();
    k_w2p<<<dim3(32, 4), 256>>>(wout, mem_kv);
    k_final_mma<<<dim3(64, 32), 256, SMEM_K5>>>(bout, y);
}

// round 11
// speedup vs baseline: 2.2651x; 1.0696x over previous
#include <cuda_runtime.h>
#include <cuda_bf16.h>
#include <cuda_fp16.h>
#include <cstdint>
#include <math.h>

// Problem constants
#define BATCH 32
#define CCH   128      // channels
#define NTOK  4096     // H*W
#define NH    4        // heads
#define DH    32       // dim head
#define QKV3  384      // 3*hidden
#define NSPLIT 16      // token splits for context partials

// ---------------- scratch (device globals; no allocation allowed) ----------
__device__ __half g_qkvh[(size_t)BATCH * QKV3 * NTOK];        // ~100 MB, fp16
__device__ float g_wt[QKV3 * CCH];                            // g-folded W, tf32-rounded
__device__ float g_ctx_part[NSPLIT * BATCH * NH * DH * DH];   // split ctx partials
__device__ float g_zpart[NSPLIT * BATCH * NH * DH];           // split Z partials
__device__ float g_w2[BATCH * CCH * CCH];                     // W2: [b][o][c]

// ---------------- f32x2 packed FMA helpers (sm_100+) ------------------------
__device__ __forceinline__ unsigned long long pack2(float x, float y) {
    unsigned long long r;
    asm("mov.b64 %0, {%1, %2};" : "=l"(r) : "f"(x), "f"(y));
    return r;
}
__device__ __forceinline__ void fma2(unsigned long long &d, unsigned long long a,
                                     unsigned long long b) {
    asm("fma.rn.f32x2 %0, %1, %2, %3;" : "=l"(d) : "l"(a), "l"(b), "l"(d));
}
__device__ __forceinline__ float2 unpack2(unsigned long long v) {
    float lo, hi;
    asm("mov.b64 {%0, %1}, %2;" : "=f"(lo), "=f"(hi) : "l"(v));
    return make_float2(lo, hi);
}

__device__ __forceinline__ uint32_t f2tf32(float v) {
    uint32_t t;
    asm("cvt.rna.tf32.f32 %0, %1;" : "=r"(t) : "f"(v));
    return t;
}

// mma.sync m16n8k8 tf32 (base ISA, works on compute_103)
__device__ __forceinline__ void mma_tf32(float* d, const uint32_t* a, const uint32_t* bb) {
    asm volatile(
        "mma.sync.aligned.m16n8k8.row.col.f32.tf32.tf32.f32 "
        "{%0,%1,%2,%3}, {%4,%5,%6,%7}, {%8,%9}, {%0,%1,%2,%3};"
        : "+f"(d[0]), "+f"(d[1]), "+f"(d[2]), "+f"(d[3])
        : "r"(a[0]), "r"(a[1]), "r"(a[2]), "r"(a[3]), "r"(bb[0]), "r"(bb[1]));
}

// ============================================================================
// K0: fold g[k]*sqrt(C) into qkv weights, round to tf32.  49152 elements.
// ============================================================================
__global__ void k_prepw(const float* __restrict__ wqkv, const float* __restrict__ g) {
    int i = blockIdx.x * 256 + threadIdx.x;   // < 49152
    int k = i & 127;
    float w = wqkv[i] * g[k] * 11.313708498984761f;
    g_wt[i] = __uint_as_float(f2tf32(w));
}

// ============================================================================
// K1: fused RMSNorm + qkv GEMM on tensor cores (mma.sync tf32, 1 pass).
// CTA tile M=128 x N=64 tokens x K=128.  grid (64 ntiles, 3 mt, 32 b), 256 thr.
// Output stored fp16 (halves write traffic).
// ============================================================================
__global__ __launch_bounds__(256, 2)
void k_qkv_mma(const float* __restrict__ x) {
    extern __shared__ float sm[];
    float* a_s  = sm;            // 16384
    float* xs   = sm + 16384;    // 8192
    float* red  = sm + 24576;    // 256
    float* invs = sm + 24832;    // 64   (total 24896 floats)

    const int nt = blockIdx.x, mt = blockIdx.y, b = blockIdx.z;
    const int tid = threadIdx.x;

    // ---- A: W tile [128][128], XOR swizzle ----
    const float* wb = g_wt + mt * 128 * 128;
    #pragma unroll
    for (int i = 0; i < 64; i++) {
        int idx = tid + i * 256;
        int m = idx >> 7, k = idx & 127;
        a_s[m * 128 + ((k + 4 * m) & 127)] = wb[idx];
    }

    // ---- B: x tile [128 ch][64 tok], tf32-round, + ssq partials ----
    {
        const int t = tid & 63, cq = tid >> 6;
        const float* xc = x + (size_t)b * CCH * NTOK + (size_t)nt * 64 + t;
        float ss = 0.f;
        #pragma unroll
        for (int i = 0; i < 32; i++) {
            int c = cq * 32 + i;
            float v = xc[(size_t)c * NTOK];
            ss += v * v;
            xs[c * 64 + ((t + 8 * c) & 63)] = __uint_as_float(f2tf32(v));
        }
        red[cq * 64 + t] = ss;
    }
    __syncthreads();
    if (tid < 64) {
        float ss = red[tid] + red[64 + tid] + red[128 + tid] + red[192 + tid];
        invs[tid] = 1.0f / fmaxf(sqrtf(ss), 1e-12f);
    }
    __syncthreads();

    // ---- MMA mainloop ----
    const int lane = tid & 31, w = tid >> 5;
    const int wm = w >> 2, wn = w & 3;
    const int r4 = lane >> 2, c4 = lane & 3;

    float acc[4][2][4];
    #pragma unroll
    for (int mi = 0; mi < 4; mi++)
        #pragma unroll
        for (int ni = 0; ni < 2; ni++)
            #pragma unroll
            for (int q = 0; q < 4; q++) acc[mi][ni][q] = 0.f;

    const uint32_t* a_u = reinterpret_cast<const uint32_t*>(a_s);
    const uint32_t* x_u = reinterpret_cast<const uint32_t*>(xs);

    #pragma unroll
    for (int ks = 0; ks < 16; ks++) {
        const int k0 = ks * 8;
        uint32_t af[4][4];
        uint32_t bf[2][2];
        #pragma unroll
        for (int mi = 0; mi < 4; mi++) {
            int r0 = wm * 64 + mi * 16 + r4;
            int r1 = r0 + 8;
            int ka = k0 + c4;
            af[mi][0] = a_u[r0 * 128 + ((ka + 4 * r0) & 127)];
            af[mi][1] = a_u[r1 * 128 + ((ka + 4 * r1) & 127)];
            af[mi][2] = a_u[r0 * 128 + ((ka + 4 + 4 * r0) & 127)];
            af[mi][3] = a_u[r1 * 128 + ((ka + 4 + 4 * r1) & 127)];
        }
        #pragma unroll
        for (int ni = 0; ni < 2; ni++) {
            int n0 = wn * 16 + ni * 8 + r4;
            int kb0 = k0 + c4, kb1 = kb0 + 4;
            bf[ni][0] = x_u[kb0 * 64 + ((n0 + 8 * kb0) & 63)];
            bf[ni][1] = x_u[kb1 * 64 + ((n0 + 8 * kb1) & 63)];
        }
        #pragma unroll
        for (int mi = 0; mi < 4; mi++)
            #pragma unroll
            for (int ni = 0; ni < 2; ni++)
                mma_tf32(acc[mi][ni], af[mi], bf[ni]);
    }

    // ---- epilogue: scale by invs[token], half2 stores ----
    __half* outb = g_qkvh + ((size_t)b * QKV3 + (size_t)mt * 128) * NTOK + (size_t)nt * 64;
    #pragma unroll
    for (int mi = 0; mi < 4; mi++) {
        #pragma unroll
        for (int ni = 0; ni < 2; ni++) {
            int col = wn * 16 + ni * 8 + 2 * c4;
            float i0 = invs[col], i1 = invs[col + 1];
            int row0 = wm * 64 + mi * 16 + r4;
            __half2 v0 = __floats2half2_rn(acc[mi][ni][0] * i0, acc[mi][ni][1] * i1);
            __half2 v1 = __floats2half2_rn(acc[mi][ni][2] * i0, acc[mi][ni][3] * i1);
            *reinterpret_cast<__half2*>(&outb[(size_t)row0 * NTOK + col]) = v0;
            *reinterpret_cast<__half2*>(&outb[(size_t)(row0 + 8) * NTOK + col]) = v1;
        }
    }
}

// ============================================================================
// K3: context partials, unstabilized exp (k bounded ~3.5, safe in fp32).
// Emits per-split Z row sums via warp shuffles.  k/v read as fp16.
// grid 128*NSPLIT, block 256.  Conflict-free cyclic 4x4 tile, f32x2 MACs.
// ============================================================================
__global__ __launch_bounds__(256, 3)
void k_context() {
    __shared__ float es[32 * 132];
    __shared__ float vs[32 * 132];
    const int blk = blockIdx.x;
    const int bh = blk >> 4, split = blk & (NSPLIT - 1);
    const int b = bh >> 2, h = bh & 3;
    const int tid = threadIdx.x;

    const int grp = tid >> 6, lt = tid & 63;
    const int d0 = lt >> 3;
    const int e0 = lt & 7;
    const int tb = grp * 32;

    unsigned long long acc[4][4];
    #pragma unroll
    for (int i = 0; i < 4; i++)
        #pragma unroll
        for (int j = 0; j < 4; j++) acc[i][j] = 0ull;

    float zp[4] = {0.f, 0.f, 0.f, 0.f};

    const __half* kbase = g_qkvh + ((size_t)(b * QKV3 + CCH + h * DH)) * NTOK;
    const __half* vbase = g_qkvh + ((size_t)(b * QKV3 + 2 * CCH + h * DH)) * NTOK;
    const int t0 = split * 256;

    for (int c0 = 0; c0 < 256; c0 += 128) {
        #pragma unroll
        for (int i = 0; i < 4; i++) {
            int f4 = tid + i * 256;
            int d = f4 >> 5, tq = (f4 & 31) * 4;
            const __half2* kp = reinterpret_cast<const __half2*>(
                &kbase[(size_t)d * NTOK + t0 + c0 + tq]);
            const __half2* vp = reinterpret_cast<const __half2*>(
                &vbase[(size_t)d * NTOK + t0 + c0 + tq]);
            float2 k01 = __half22float2(kp[0]);
            float2 k23 = __half22float2(kp[1]);
            float2 v01 = __half22float2(vp[0]);
            float2 v23 = __half22float2(vp[1]);
            float4 e4 = make_float4(__expf(k01.x), __expf(k01.y),
                                    __expf(k23.x), __expf(k23.y));
            zp[i] += e4.x + e4.y + e4.z + e4.w;
            *reinterpret_cast<float4*>(&es[d * 132 + tq]) = e4;
            *reinterpret_cast<float4*>(&vs[d * 132 + tq]) =
                make_float4(v01.x, v01.y, v23.x, v23.y);
        }
        __syncthreads();

        #pragma unroll
        for (int t4 = 0; t4 < 32; t4 += 4) {
            ulonglong2 a2[4], b2[4];
            #pragma unroll
            for (int i = 0; i < 4; i++)
                a2[i] = *reinterpret_cast<const ulonglong2*>(&es[(d0 + 8 * i) * 132 + tb + t4]);
            #pragma unroll
            for (int j = 0; j < 4; j++)
                b2[j] = *reinterpret_cast<const ulonglong2*>(&vs[(e0 + 8 * j) * 132 + tb + t4]);
            #pragma unroll
            for (int i = 0; i < 4; i++)
                #pragma unroll
                for (int j = 0; j < 4; j++) {
                    fma2(acc[i][j], a2[i].x, b2[j].x);
                    fma2(acc[i][j], a2[i].y, b2[j].y);
                }
        }
        __syncthreads();
    }

    // ---- Z partials: row d = (tid>>5) + 8i is owned entirely by warp tid>>5
    {
        const int lane = tid & 31, wrp = tid >> 5;
        #pragma unroll
        for (int i = 0; i < 4; i++) {
            float v = zp[i];
            #pragma unroll
            for (int o = 16; o > 0; o >>= 1)
                v += __shfl_xor_sync(0xFFFFFFFFu, v, o);
            if (lane == 0)
                g_zpart[split * (BATCH * NH * DH) + bh * 32 + (wrp + 8 * i)] = v;
        }
    }

    // ---- combine the 4 groups deterministically through smem ----
    float* part = es;
    #pragma unroll
    for (int i = 0; i < 4; i++)
        #pragma unroll
        for (int j = 0; j < 4; j++) {
            float2 p = unpack2(acc[i][j]);
            part[grp * 1024 + (d0 + 8 * i) * 32 + (e0 + 8 * j)] = p.x + p.y;
        }
    __syncthreads();
    for (int idx = tid; idx < 1024; idx += 256) {
        float s = part[idx] + part[idx + 1024] + part[idx + 2048] + part[idx + 3072];
        g_ctx_part[((size_t)split * 128 + bh) * 1024 + idx] = s;
    }
}

// ============================================================================
// K4: fold w_out through normalized context -> W2[b][o][c].
// grid (32 b, 4 o-tiles, 4 c-tiles): each block = one head slice (h = cg),
// 32 o x 32 c outputs.  512 blocks for occupancy.
// ============================================================================
__global__ void k_w2p(const float* __restrict__ wout, const float* __restrict__ mem_kv) {
    __shared__ float ce[32 * 36];     // normalized ctx rows for this c-tile
    __shared__ float ws[32 * 36];     // w_out slice [o][e] for head cg
    __shared__ float ews[128];        // exp(mem_k) for this c-tile
    __shared__ float invz[32];
    const int b = blockIdx.x, og = blockIdx.y, cg = blockIdx.z;   // head h == cg
    const int tid = threadIdx.x;

    if (tid < 128)
        ews[tid] = __expf(mem_kv[cg * 128 + tid]);   // mem_kv[0][cg][lc][j], lc=tid>>2
    // ws[ol][e] = wout[(og*32+ol)*128 + cg*32+e]
    for (int idx = tid; idx < 1024; idx += 256) {
        int ol = idx >> 5, e = idx & 31;
        ws[ol * 36 + e] = wout[(og * 32 + ol) * 128 + cg * 32 + e];
    }
    __syncthreads();

    if (tid < 32) {
        float z = 0.f;
        #pragma unroll
        for (int s = 0; s < NSPLIT; s++)
            z += g_zpart[s * (BATCH * NH * DH) + b * 128 + cg * 32 + tid];
        z += ews[tid * 4] + ews[tid * 4 + 1] + ews[tid * 4 + 2] + ews[tid * 4 + 3];
        invz[tid] = 1.0f / z;
    }
    __syncthreads();

    for (int idx = tid; idx < 1024; idx += 256) {
        int lc = idx >> 5, e = idx & 31;
        size_t base = (size_t)(b * 4 + cg) * 1024 + idx;
        float vsum = 0.f;
        #pragma unroll
        for (int s = 0; s < NSPLIT; s++)
            vsum += g_ctx_part[(size_t)s * 131072 + base];
        #pragma unroll
        for (int j = 0; j < 4; j++)
            vsum = fmaf(ews[lc * 4 + j], mem_kv[512 + ((cg * 32 + e) * 4 + j)], vsum);
        ce[lc * 36 + e] = vsum * invz[lc];
    }
    __syncthreads();

    const int o_l = tid >> 3;          // 0..31
    const int cb = tid & 7;
    const float* wr = &ws[o_l * 36];
    #pragma unroll
    for (int ci = 0; ci < 4; ci++) {
        int c_l = cb + ci * 8;
        const float* cr = &ce[c_l * 36];
        float a = 0.f;
        #pragma unroll
        for (int e4 = 0; e4 < 32; e4 += 4) {
            float4 w4 = *reinterpret_cast<const float4*>(wr + e4);
            float4 c4v = *reinterpret_cast<const float4*>(cr + e4);
            a = fmaf(w4.x, c4v.x, a);
            a = fmaf(w4.y, c4v.y, a);
            a = fmaf(w4.z, c4v.z, a);
            a = fmaf(w4.w, c4v.w, a);
        }
        g_w2[((size_t)b * 128 + og * 32 + o_l) * 128 + cg * 32 + c_l] = a;
    }
}

// ============================================================================
// K5: fused q-softmax + output GEMM on tensor cores (mma.sync tf32).
// q read as fp16.  CTA tile M=128(o) x N=64(t) x K=128(c).  grid (64 nt, 32 b).
// ============================================================================
__global__ __launch_bounds__(256, 2)
void k_final_mma(const float* __restrict__ bout, float* __restrict__ y) {
    extern __shared__ float sm5[];
    float* a_s = sm5;             // 16384  (W2 swizzled [o][(c+4o)&127])
    float* xs  = sm5 + 16384;     // 8192   (q swizzled [c][(t+8c)&63])
    float* bs  = sm5 + 24576;     // 128

    const int nt = blockIdx.x, b = blockIdx.y;
    const int tid = threadIdx.x;

    // ---- A: W2 tile [128 o][128 c], XOR swizzle ----
    const float* wg = g_w2 + (size_t)b * 16384;
    #pragma unroll
    for (int i = 0; i < 64; i++) {
        int idx = tid + i * 256;
        int o = idx >> 7, c = idx & 127;
        a_s[o * 128 + ((c + 4 * o) & 127)] = wg[idx];
    }

    // ---- B: q tile [128 c][64 t] (fp16 -> fp32) ----
    {
        const int t = tid & 63, cq = tid >> 6;
        const __half* qc = g_qkvh + (size_t)b * QKV3 * NTOK + (size_t)nt * 64 + t;
        #pragma unroll
        for (int i = 0; i < 32; i++) {
            int c = cq * 32 + i;
            xs[c * 64 + ((t + 8 * c) & 63)] = __half2float(qc[(size_t)c * NTOK]);
        }
    }
    if (tid < 128) bs[tid] = bout[tid];
    __syncthreads();

    // ---- softmax over d per (head, token), write back tf32 * scale ----
    {
        const int h = tid >> 6, t = tid & 63;
        float qv[32];
        float m = -1e30f;
        #pragma unroll
        for (int d = 0; d < 32; d++) {
            int c = h * 32 + d;
            qv[d] = xs[c * 64 + ((t + 8 * c) & 63)];
            m = fmaxf(m, qv[d]);
        }
        float ss = 0.f;
        #pragma unroll
        for (int d = 0; d < 32; d++) {
            qv[d] = __expf(qv[d] - m);
            ss += qv[d];
        }
        const float inv = 0.17677669529663687f / ss;
        #pragma unroll
        for (int d = 0; d < 32; d++) {
            int c = h * 32 + d;
            xs[c * 64 + ((t + 8 * c) & 63)] = __uint_as_float(f2tf32(qv[d] * inv));
        }
    }
    __syncthreads();

    // ---- MMA mainloop ----
    const int lane = tid & 31, w = tid >> 5;
    const int wm = w >> 2, wn = w & 3;
    const int r4 = lane >> 2, c4 = lane & 3;

    float acc[4][2][4];
    #pragma unroll
    for (int mi = 0; mi < 4; mi++)
        #pragma unroll
        for (int ni = 0; ni < 2; ni++)
            #pragma unroll
            for (int q = 0; q < 4; q++) acc[mi][ni][q] = 0.f;

    const uint32_t* a_u = reinterpret_cast<const uint32_t*>(a_s);
    const uint32_t* x_u = reinterpret_cast<const uint32_t*>(xs);

    #pragma unroll
    for (int ks = 0; ks < 16; ks++) {
        const int k0 = ks * 8;
        uint32_t af[4][4];
        uint32_t bf[2][2];
        #pragma unroll
        for (int mi = 0; mi < 4; mi++) {
            int r0 = wm * 64 + mi * 16 + r4;
            int r1 = r0 + 8;
            int ka = k0 + c4;
            af[mi][0] = a_u[r0 * 128 + ((ka + 4 * r0) & 127)];
            af[mi][1] = a_u[r1 * 128 + ((ka + 4 * r1) & 127)];
            af[mi][2] = a_u[r0 * 128 + ((ka + 4 + 4 * r0) & 127)];
            af[mi][3] = a_u[r1 * 128 + ((ka + 4 + 4 * r1) & 127)];
        }
        #pragma unroll
        for (int ni = 0; ni < 2; ni++) {
            int n0 = wn * 16 + ni * 8 + r4;
            int kb0 = k0 + c4, kb1 = kb0 + 4;
            bf[ni][0] = x_u[kb0 * 64 + ((n0 + 8 * kb0) & 63)];
            bf[ni][1] = x_u[kb1 * 64 + ((n0 + 8 * kb1) & 63)];
        }
        #pragma unroll
        for (int mi = 0; mi < 4; mi++)
            #pragma unroll
            for (int ni = 0; ni < 2; ni++)
                mma_tf32(acc[mi][ni], af[mi], bf[ni]);
    }

    // ---- epilogue: + bias, float2 stores ----
    float* outb = y + (size_t)b * CCH * NTOK + (size_t)nt * 64;
    #pragma unroll
    for (int mi = 0; mi < 4; mi++) {
        #pragma unroll
        for (int ni = 0; ni < 2; ni++) {
            int col = wn * 16 + ni * 8 + 2 * c4;
            int row0 = wm * 64 + mi * 16 + r4;
            float b0 = bs[row0], b1 = bs[row0 + 8];
            float2 v0 = make_float2(acc[mi][ni][0] + b0, acc[mi][ni][1] + b0);
            float2 v1 = make_float2(acc[mi][ni][2] + b1, acc[mi][ni][3] + b1);
            *reinterpret_cast<float2*>(&outb[(size_t)row0 * NTOK + col]) = v0;
            *reinterpret_cast<float2*>(&outb[(size_t)(row0 + 8) * NTOK + col]) = v1;
        }
    }
}

// ============================================================================
extern "C" void kernel_launch(void* const* d_in, const int* in_sizes, int n_in,
                              void* d_out, int out_size) {
    const float* x      = (const float*)d_in[0];
    const float* g      = (const float*)d_in[1];
    const float* wqkv   = (const float*)d_in[2];
    const float* mem_kv = (const float*)d_in[3];
    const float* wout   = (const float*)d_in[4];
    const float* bout   = (const float*)d_in[5];
    float* y = (float*)d_out;

    const int SMEM_K1 = 24896 * 4;   // 99584 B
    const int SMEM_K5 = 24704 * 4;   // 98816 B
    cudaFuncSetAttribute(k_qkv_mma,   cudaFuncAttributeMaxDynamicSharedMemorySize, SMEM_K1);
    cudaFuncSetAttribute(k_final_mma, cudaFuncAttributeMaxDynamicSharedMemorySize, SMEM_K5);

    k_prepw<<<192, 256>>>(wqkv, g);
    k_qkv_mma<<<dim3(64, 3, 32), 256, SMEM_K1>>>(x);
    k_context<<<128 * NSPLIT, 256>>>();
    k_w2p<<<dim3(32, 4, 4), 256>>>(wout, mem_kv);
    k_final_mma<<<dim3(64, 32), 256, SMEM_K5>>>(bout, y);
}

// round 13
// speedup vs baseline: 2.4414x; 1.0778x over previous
#include <cuda_runtime.h>
#include <cuda_bf16.h>
#include <cuda_fp16.h>
#include <cstdint>
#include <math.h>

// Problem constants
#define BATCH 32
#define CCH   128
#define NTOK  4096
#define NH    4
#define DH    32
#define QKV3  384
#define NSPLIT 16

// ---------------- scratch (device globals; no allocation allowed) ----------
__device__ __half g_qkvh[(size_t)BATCH * QKV3 * NTOK];        // q, exp(k), v (fp16)
__device__ float g_wt[QKV3 * CCH];                            // g-folded W, tf32
__device__ float g_ctx_part[NSPLIT * BATCH * NH * DH * DH];
__device__ float g_zpart[NSPLIT * BATCH * NH * DH];
__device__ float g_w2[BATCH * CCH * CCH];                     // W2: [b][o][c]

__device__ __forceinline__ uint32_t f2tf32(float v) {
    uint32_t t;
    asm("cvt.rna.tf32.f32 %0, %1;" : "=r"(t) : "f"(v));
    return t;
}
__device__ __forceinline__ uint32_t smem_u32(const void* p) {
    uint32_t a;
    asm("{ .reg .u64 t; cvta.to.shared.u64 t, %1; cvt.u32.u64 %0, t; }"
        : "=r"(a) : "l"(p));
    return a;
}
__device__ __forceinline__ void mma_tf32(float* d, const uint32_t* a, const uint32_t* bb) {
    asm volatile(
        "mma.sync.aligned.m16n8k8.row.col.f32.tf32.tf32.f32 "
        "{%0,%1,%2,%3}, {%4,%5,%6,%7}, {%8,%9}, {%0,%1,%2,%3};"
        : "+f"(d[0]), "+f"(d[1]), "+f"(d[2]), "+f"(d[3])
        : "r"(a[0]), "r"(a[1]), "r"(a[2]), "r"(a[3]), "r"(bb[0]), "r"(bb[1]));
}
__device__ __forceinline__ void mma_f16(float* d, uint32_t a0, uint32_t a1,
                                        uint32_t a2, uint32_t a3,
                                        uint32_t b0, uint32_t b1) {
    asm volatile(
        "mma.sync.aligned.m16n8k16.row.col.f32.f16.f16.f32 "
        "{%0,%1,%2,%3}, {%4,%5,%6,%7}, {%8,%9}, {%0,%1,%2,%3};"
        : "+f"(d[0]), "+f"(d[1]), "+f"(d[2]), "+f"(d[3])
        : "r"(a0), "r"(a1), "r"(a2), "r"(a3), "r"(b0), "r"(b1));
}
__device__ __forceinline__ void ldsm_x4(uint32_t& r0, uint32_t& r1, uint32_t& r2,
                                        uint32_t& r3, uint32_t addr) {
    asm volatile("ldmatrix.sync.aligned.m8n8.x4.shared.b16 {%0,%1,%2,%3}, [%4];"
                 : "=r"(r0), "=r"(r1), "=r"(r2), "=r"(r3) : "r"(addr));
}
__device__ __forceinline__ void ldsm_x2(uint32_t& r0, uint32_t& r1, uint32_t addr) {
    asm volatile("ldmatrix.sync.aligned.m8n8.x2.shared.b16 {%0,%1}, [%2];"
                 : "=r"(r0), "=r"(r1) : "r"(addr));
}

// ============================================================================
// K0: fold g[k]*sqrt(C) into qkv weights, round to tf32.
// ============================================================================
__global__ void k_prepw(const float* __restrict__ wqkv, const float* __restrict__ g) {
    int i = blockIdx.x * 256 + threadIdx.x;
    int k = i & 127;
    float w = wqkv[i] * g[k] * 11.313708498984761f;
    g_wt[i] = __uint_as_float(f2tf32(w));
}

// ============================================================================
// K1: fused RMSNorm + qkv GEMM (mma.sync tf32).  For mt==1 (k rows) the
// epilogue stores exp(k-hat) directly (fp16), removing exp from k_context.
// ============================================================================
__global__ __launch_bounds__(256, 2)
void k_qkv_mma(const float* __restrict__ x) {
    extern __shared__ float sm[];
    float* a_s  = sm;            // 16384
    float* xs   = sm + 16384;    // 8192
    float* red  = sm + 24576;    // 256
    float* invs = sm + 24832;    // 64

    const int nt = blockIdx.x, mt = blockIdx.y, b = blockIdx.z;
    const int tid = threadIdx.x;

    const float* wb = g_wt + mt * 128 * 128;
    #pragma unroll
    for (int i = 0; i < 64; i++) {
        int idx = tid + i * 256;
        int m = idx >> 7, k = idx & 127;
        a_s[m * 128 + ((k + 4 * m) & 127)] = wb[idx];
    }
    {
        const int t = tid & 63, cq = tid >> 6;
        const float* xc = x + (size_t)b * CCH * NTOK + (size_t)nt * 64 + t;
        float ss = 0.f;
        #pragma unroll
        for (int i = 0; i < 32; i++) {
            int c = cq * 32 + i;
            float v = xc[(size_t)c * NTOK];
            ss += v * v;
            xs[c * 64 + ((t + 8 * c) & 63)] = __uint_as_float(f2tf32(v));
        }
        red[cq * 64 + t] = ss;
    }
    __syncthreads();
    if (tid < 64) {
        float ss = red[tid] + red[64 + tid] + red[128 + tid] + red[192 + tid];
        invs[tid] = 1.0f / fmaxf(sqrtf(ss), 1e-12f);
    }
    __syncthreads();

    const int lane = tid & 31, w = tid >> 5;
    const int wm = w >> 2, wn = w & 3;
    const int r4 = lane >> 2, c4 = lane & 3;

    float acc[4][2][4];
    #pragma unroll
    for (int mi = 0; mi < 4; mi++)
        #pragma unroll
        for (int ni = 0; ni < 2; ni++)
            #pragma unroll
            for (int q = 0; q < 4; q++) acc[mi][ni][q] = 0.f;

    const uint32_t* a_u = reinterpret_cast<const uint32_t*>(a_s);
    const uint32_t* x_u = reinterpret_cast<const uint32_t*>(xs);

    #pragma unroll
    for (int ks = 0; ks < 16; ks++) {
        const int k0 = ks * 8;
        uint32_t af[4][4];
        uint32_t bf[2][2];
        #pragma unroll
        for (int mi = 0; mi < 4; mi++) {
            int r0 = wm * 64 + mi * 16 + r4;
            int r1 = r0 + 8;
            int ka = k0 + c4;
            af[mi][0] = a_u[r0 * 128 + ((ka + 4 * r0) & 127)];
            af[mi][1] = a_u[r1 * 128 + ((ka + 4 * r1) & 127)];
            af[mi][2] = a_u[r0 * 128 + ((ka + 4 + 4 * r0) & 127)];
            af[mi][3] = a_u[r1 * 128 + ((ka + 4 + 4 * r1) & 127)];
        }
        #pragma unroll
        for (int ni = 0; ni < 2; ni++) {
            int n0 = wn * 16 + ni * 8 + r4;
            int kb0 = k0 + c4, kb1 = kb0 + 4;
            bf[ni][0] = x_u[kb0 * 64 + ((n0 + 8 * kb0) & 63)];
            bf[ni][1] = x_u[kb1 * 64 + ((n0 + 8 * kb1) & 63)];
        }
        #pragma unroll
        for (int mi = 0; mi < 4; mi++)
            #pragma unroll
            for (int ni = 0; ni < 2; ni++)
                mma_tf32(acc[mi][ni], af[mi], bf[ni]);
    }

    // epilogue: scale by invs[token]; for k rows (mt==1) store exp() instead
    __half* outb = g_qkvh + ((size_t)b * QKV3 + (size_t)mt * 128) * NTOK + (size_t)nt * 64;
    const bool is_k = (mt == 1);
    #pragma unroll
    for (int mi = 0; mi < 4; mi++) {
        #pragma unroll
        for (int ni = 0; ni < 2; ni++) {
            int col = wn * 16 + ni * 8 + 2 * c4;
            float i0 = invs[col], i1 = invs[col + 1];
            int row0 = wm * 64 + mi * 16 + r4;
            float v00 = acc[mi][ni][0] * i0, v01 = acc[mi][ni][1] * i1;
            float v10 = acc[mi][ni][2] * i0, v11 = acc[mi][ni][3] * i1;
            if (is_k) {
                v00 = __expf(v00); v01 = __expf(v01);
                v10 = __expf(v10); v11 = __expf(v11);
            }
            *reinterpret_cast<__half2*>(&outb[(size_t)row0 * NTOK + col]) =
                __floats2half2_rn(v00, v01);
            *reinterpret_cast<__half2*>(&outb[(size_t)(row0 + 8) * NTOK + col]) =
                __floats2half2_rn(v10, v11);
        }
    }
}

// ============================================================================
// K3: context partials on fp16 HMMA.  es (=exp(k), pre-applied) and v staged
// as raw fp16, pitch 264 halfs (528 B -> conflict-free 8-row ldmatrix).
// 8 warps: warp w owns (mi=w>>2, ni=w&3) -> D tile 16(d) x 8(e), K=256 tokens.
// Z row sums from smem pass + shuffles.  grid 128*NSPLIT, block 256.
// ============================================================================
__global__ __launch_bounds__(256)
void k_context() {
    __shared__ __half es[32 * 264];
    __shared__ __half vs[32 * 264];
    const int blk = blockIdx.x;
    const int bh = blk >> 4, split = blk & (NSPLIT - 1);
    const int b = bh >> 2, h = bh & 3;
    const int tid = threadIdx.x;
    const int t0 = split * 256;

    const __half* kbase = g_qkvh + ((size_t)(b * QKV3 + CCH + h * DH)) * NTOK;
    const __half* vbase = g_qkvh + ((size_t)(b * QKV3 + 2 * CCH + h * DH)) * NTOK;

    // ---- staging: coalesced half2 copies (rows of 128 half2) ----
    #pragma unroll
    for (int j = 0; j < 16; j++) {
        int hidx = tid + j * 256;          // half2 index in [32][128]
        int d = hidx >> 7, col = hidx & 127;
        uint32_t kv = *reinterpret_cast<const uint32_t*>(
            &kbase[(size_t)d * NTOK + t0 + 2 * col]);
        uint32_t vv = *reinterpret_cast<const uint32_t*>(
            &vbase[(size_t)d * NTOK + t0 + 2 * col]);
        *reinterpret_cast<uint32_t*>(&es[d * 264 + 2 * col]) = kv;
        *reinterpret_cast<uint32_t*>(&vs[d * 264 + 2 * col]) = vv;
    }
    __syncthreads();

    // ---- Z row sums: thread -> row d = tid>>3, 16 half2 from smem ----
    {
        const int d = tid >> 3, seg = (tid & 7) * 16;
        float z = 0.f;
        #pragma unroll
        for (int j = 0; j < 16; j++) {
            __half2 hv = *reinterpret_cast<const __half2*>(&es[d * 264 + 2 * (seg + j)]);
            float2 f = __half22float2(hv);
            z += f.x + f.y;
        }
        z += __shfl_xor_sync(0xFFFFFFFFu, z, 1);
        z += __shfl_xor_sync(0xFFFFFFFFu, z, 2);
        z += __shfl_xor_sync(0xFFFFFFFFu, z, 4);
        if ((tid & 7) == 0)
            g_zpart[split * (BATCH * NH * DH) + bh * 32 + d] = z;
    }

    // ---- HMMA mainloop ----
    const int w = tid >> 5, lane = tid & 31;
    const int mi = w >> 2, ni = w & 3;
    float dacc[4] = {0.f, 0.f, 0.f, 0.f};

    const uint32_t es_b = smem_u32(es);
    const uint32_t vs_b = smem_u32(vs);
    const uint32_t a_addr = es_b + ((mi * 16 + (lane & 15)) * 264 + ((lane >> 4) << 3)) * 2;
    const uint32_t b_addr = vs_b + ((ni * 8 + (lane & 7)) * 264 + (((lane >> 3) & 1) << 3)) * 2;

    #pragma unroll
    for (int kc = 0; kc < 16; kc++) {
        uint32_t a0, a1, a2, a3, b0, b1;
        ldsm_x4(a0, a1, a2, a3, a_addr + kc * 32);   // 16 halfs = 32 B per kc
        ldsm_x2(b0, b1, b_addr + kc * 32);
        mma_f16(dacc, a0, a1, a2, a3, b0, b1);
    }

    // ---- store partials (each (d,e) warp-owned; no combine needed) ----
    float* outp = g_ctx_part + ((size_t)split * 128 + bh) * 1024;
    const int r = lane >> 2, c2 = (lane & 3) * 2;
    const int dr = mi * 16 + r, ec = ni * 8 + c2;
    *reinterpret_cast<float2*>(&outp[dr * 32 + ec]) = make_float2(dacc[0], dacc[1]);
    *reinterpret_cast<float2*>(&outp[(dr + 8) * 32 + ec]) = make_float2(dacc[2], dacc[3]);
}

// ============================================================================
// K4: fold w_out through normalized context -> W2[b][o][c].
// grid (32 b, 4 o-tiles, 4 heads), block 256.  float4 split reduction.
// ============================================================================
__global__ void k_w2p(const float* __restrict__ wout, const float* __restrict__ mem_kv) {
    __shared__ float ce[32 * 36];
    __shared__ float ws[32 * 36];
    __shared__ float ews[128];
    __shared__ float invz[32];
    const int b = blockIdx.x, og = blockIdx.y, cg = blockIdx.z;
    const int tid = threadIdx.x;

    if (tid < 128)
        ews[tid] = __expf(mem_kv[cg * 128 + tid]);
    for (int idx = tid; idx < 1024; idx += 256) {
        int ol = idx >> 5, e = idx & 31;
        ws[ol * 36 + e] = wout[(og * 32 + ol) * 128 + cg * 32 + e];
    }
    __syncthreads();

    if (tid < 32) {
        float z = 0.f;
        #pragma unroll
        for (int s = 0; s < NSPLIT; s++)
            z += g_zpart[s * (BATCH * NH * DH) + b * 128 + cg * 32 + tid];
        z += ews[tid * 4] + ews[tid * 4 + 1] + ews[tid * 4 + 2] + ews[tid * 4 + 3];
        invz[tid] = 1.0f / z;
    }
    __syncthreads();

    // ctx reduction: one float4 per thread (lc = tid>>3, e block = (tid&7)*4)
    {
        const int lc = tid >> 3, e4 = (tid & 7) * 4;
        const size_t base = (size_t)(b * 4 + cg) * 1024 + lc * 32 + e4;
        float4 v = make_float4(0.f, 0.f, 0.f, 0.f);
        #pragma unroll
        for (int s = 0; s < NSPLIT; s++) {
            float4 t = *reinterpret_cast<const float4*>(&g_ctx_part[(size_t)s * 131072 + base]);
            v.x += t.x; v.y += t.y; v.z += t.z; v.w += t.w;
        }
        #pragma unroll
        for (int j = 0; j < 4; j++) {
            float ew = ews[lc * 4 + j];
            v.x = fmaf(ew, mem_kv[512 + ((cg * 32 + e4 + 0) * 4 + j)], v.x);
            v.y = fmaf(ew, mem_kv[512 + ((cg * 32 + e4 + 1) * 4 + j)], v.y);
            v.z = fmaf(ew, mem_kv[512 + ((cg * 32 + e4 + 2) * 4 + j)], v.z);
            v.w = fmaf(ew, mem_kv[512 + ((cg * 32 + e4 + 3) * 4 + j)], v.w);
        }
        const float iz = invz[lc];
        v.x *= iz; v.y *= iz; v.z *= iz; v.w *= iz;
        *reinterpret_cast<float4*>(&ce[lc * 36 + e4]) = v;
    }
    __syncthreads();

    const int o_l = tid >> 3;
    const int cb = tid & 7;
    const float* wr = &ws[o_l * 36];
    #pragma unroll
    for (int ci = 0; ci < 4; ci++) {
        int c_l = cb + ci * 8;
        const float* cr = &ce[c_l * 36];
        float a = 0.f;
        #pragma unroll
        for (int e4 = 0; e4 < 32; e4 += 4) {
            float4 w4 = *reinterpret_cast<const float4*>(wr + e4);
            float4 c4v = *reinterpret_cast<const float4*>(cr + e4);
            a = fmaf(w4.x, c4v.x, a);
            a = fmaf(w4.y, c4v.y, a);
            a = fmaf(w4.z, c4v.z, a);
            a = fmaf(w4.w, c4v.w, a);
        }
        g_w2[((size_t)b * 128 + og * 32 + o_l) * 128 + cg * 32 + c_l] = a;
    }
}

// ============================================================================
// K5: fused q-softmax + output GEMM (mma.sync tf32).  q read fp16.
// ============================================================================
__global__ __launch_bounds__(256, 2)
void k_final_mma(const float* __restrict__ bout, float* __restrict__ y) {
    extern __shared__ float sm5[];
    float* a_s = sm5;             // 16384
    float* xs  = sm5 + 16384;     // 8192
    float* bs  = sm5 + 24576;     // 128

    const int nt = blockIdx.x, b = blockIdx.y;
    const int tid = threadIdx.x;

    const float* wg = g_w2 + (size_t)b * 16384;
    #pragma unroll
    for (int i = 0; i < 64; i++) {
        int idx = tid + i * 256;
        int o = idx >> 7, c = idx & 127;
        a_s[o * 128 + ((c + 4 * o) & 127)] = wg[idx];
    }
    {
        const int t = tid & 63, cq = tid >> 6;
        const __half* qc = g_qkvh + (size_t)b * QKV3 * NTOK + (size_t)nt * 64 + t;
        #pragma unroll
        for (int i = 0; i < 32; i++) {
            int c = cq * 32 + i;
            xs[c * 64 + ((t + 8 * c) & 63)] = __half2float(qc[(size_t)c * NTOK]);
        }
    }
    if (tid < 128) bs[tid] = bout[tid];
    __syncthreads();

    {
        const int h = tid >> 6, t = tid & 63;
        float qv[32];
        float m = -1e30f;
        #pragma unroll
        for (int d = 0; d < 32; d++) {
            int c = h * 32 + d;
            qv[d] = xs[c * 64 + ((t + 8 * c) & 63)];
            m = fmaxf(m, qv[d]);
        }
        float ss = 0.f;
        #pragma unroll
        for (int d = 0; d < 32; d++) {
            qv[d] = __expf(qv[d] - m);
            ss += qv[d];
        }
        const float inv = 0.17677669529663687f / ss;
        #pragma unroll
        for (int d = 0; d < 32; d++) {
            int c = h * 32 + d;
            xs[c * 64 + ((t + 8 * c) & 63)] = __uint_as_float(f2tf32(qv[d] * inv));
        }
    }
    __syncthreads();

    const int lane = tid & 31, w = tid >> 5;
    const int wm = w >> 2, wn = w & 3;
    const int r4 = lane >> 2, c4 = lane & 3;

    float acc[4][2][4];
    #pragma unroll
    for (int mi = 0; mi < 4; mi++)
        #pragma unroll
        for (int ni = 0; ni < 2; ni++)
            #pragma unroll
            for (int q = 0; q < 4; q++) acc[mi][ni][q] = 0.f;

    const uint32_t* a_u = reinterpret_cast<const uint32_t*>(a_s);
    const uint32_t* x_u = reinterpret_cast<const uint32_t*>(xs);

    #pragma unroll
    for (int ks = 0; ks < 16; ks++) {
        const int k0 = ks * 8;
        uint32_t af[4][4];
        uint32_t bf[2][2];
        #pragma unroll
        for (int mi = 0; mi < 4; mi++) {
            int r0 = wm * 64 + mi * 16 + r4;
            int r1 = r0 + 8;
            int ka = k0 + c4;
            af[mi][0] = a_u[r0 * 128 + ((ka + 4 * r0) & 127)];
            af[mi][1] = a_u[r1 * 128 + ((ka + 4 * r1) & 127)];
            af[mi][2] = a_u[r0 * 128 + ((ka + 4 + 4 * r0) & 127)];
            af[mi][3] = a_u[r1 * 128 + ((ka + 4 + 4 * r1) & 127)];
        }
        #pragma unroll
        for (int ni = 0; ni < 2; ni++) {
            int n0 = wn * 16 + ni * 8 + r4;
            int kb0 = k0 + c4, kb1 = kb0 + 4;
            bf[ni][0] = x_u[kb0 * 64 + ((n0 + 8 * kb0) & 63)];
            bf[ni][1] = x_u[kb1 * 64 + ((n0 + 8 * kb1) & 63)];
        }
        #pragma unroll
        for (int mi = 0; mi < 4; mi++)
            #pragma unroll
            for (int ni = 0; ni < 2; ni++)
                mma_tf32(acc[mi][ni], af[mi], bf[ni]);
    }

    float* outb = y + (size_t)b * CCH * NTOK + (size_t)nt * 64;
    #pragma unroll
    for (int mi = 0; mi < 4; mi++) {
        #pragma unroll
        for (int ni = 0; ni < 2; ni++) {
            int col = wn * 16 + ni * 8 + 2 * c4;
            int row0 = wm * 64 + mi * 16 + r4;
            float b0 = bs[row0], b1 = bs[row0 + 8];
            float2 v0 = make_float2(acc[mi][ni][0] + b0, acc[mi][ni][1] + b0);
            float2 v1 = make_float2(acc[mi][ni][2] + b1, acc[mi][ni][3] + b1);
            *reinterpret_cast<float2*>(&outb[(size_t)row0 * NTOK + col]) = v0;
            *reinterpret_cast<float2*>(&outb[(size_t)(row0 + 8) * NTOK + col]) = v1;
        }
    }
}

// ============================================================================
extern "C" void kernel_launch(void* const* d_in, const int* in_sizes, int n_in,
                              void* d_out, int out_size) {
    const float* x      = (const float*)d_in[0];
    const float* g      = (const float*)d_in[1];
    const float* wqkv   = (const float*)d_in[2];
    const float* mem_kv = (const float*)d_in[3];
    const float* wout   = (const float*)d_in[4];
    const float* bout   = (const float*)d_in[5];
    float* y = (float*)d_out;

    const int SMEM_K1 = 24896 * 4;
    const int SMEM_K5 = 24704 * 4;
    cudaFuncSetAttribute(k_qkv_mma,   cudaFuncAttributeMaxDynamicSharedMemorySize, SMEM_K1);
    cudaFuncSetAttribute(k_final_mma, cudaFuncAttributeMaxDynamicSharedMemorySize, SMEM_K5);

    k_prepw<<<192, 256>>>(wqkv, g);
    k_qkv_mma<<<dim3(64, 3, 32), 256, SMEM_K1>>>(x);
    k_context<<<128 * NSPLIT, 256>>>();
    k_w2p<<<dim3(32, 4, 4), 256>>>(wout, mem_kv);
    k_final_mma<<<dim3(64, 32), 256, SMEM_K5>>>(bout, y);
}

// round 14
// speedup vs baseline: 2.5072x; 1.0270x over previous
#include <cuda_runtime.h>
#include <cuda_bf16.h>
#include <cuda_fp16.h>
#include <cstdint>
#include <math.h>

// Problem constants
#define BATCH 32
#define CCH   128
#define NTOK  4096
#define NH    4
#define DH    32
#define QKV3  384
#define NSPLIT 8

// ---------------- scratch (device globals; no allocation allowed) ----------
__device__ __half g_qkvh[(size_t)BATCH * QKV3 * NTOK];        // q, exp(k), v (fp16)
__device__ float g_wt[QKV3 * CCH];                            // g-folded W, tf32
__device__ float g_ctx_part[NSPLIT * BATCH * NH * DH * DH];
__device__ float g_zpart[NSPLIT * BATCH * NH * DH];
__device__ float g_w2[BATCH * CCH * CCH];                     // W2: [b][o][c]

__device__ __forceinline__ uint32_t f2tf32(float v) {
    uint32_t t;
    asm("cvt.rna.tf32.f32 %0, %1;" : "=r"(t) : "f"(v));
    return t;
}
__device__ __forceinline__ uint32_t smem_u32(const void* p) {
    uint32_t a;
    asm("{ .reg .u64 t; cvta.to.shared.u64 t, %1; cvt.u32.u64 %0, t; }"
        : "=r"(a) : "l"(p));
    return a;
}
__device__ __forceinline__ void mma_tf32(float* d, const uint32_t* a, const uint32_t* bb) {
    asm volatile(
        "mma.sync.aligned.m16n8k8.row.col.f32.tf32.tf32.f32 "
        "{%0,%1,%2,%3}, {%4,%5,%6,%7}, {%8,%9}, {%0,%1,%2,%3};"
        : "+f"(d[0]), "+f"(d[1]), "+f"(d[2]), "+f"(d[3])
        : "r"(a[0]), "r"(a[1]), "r"(a[2]), "r"(a[3]), "r"(bb[0]), "r"(bb[1]));
}
__device__ __forceinline__ void mma_f16(float* d, uint32_t a0, uint32_t a1,
                                        uint32_t a2, uint32_t a3,
                                        uint32_t b0, uint32_t b1) {
    asm volatile(
        "mma.sync.aligned.m16n8k16.row.col.f32.f16.f16.f32 "
        "{%0,%1,%2,%3}, {%4,%5,%6,%7}, {%8,%9}, {%0,%1,%2,%3};"
        : "+f"(d[0]), "+f"(d[1]), "+f"(d[2]), "+f"(d[3])
        : "r"(a0), "r"(a1), "r"(a2), "r"(a3), "r"(b0), "r"(b1));
}
__device__ __forceinline__ void ldsm_x4(uint32_t& r0, uint32_t& r1, uint32_t& r2,
                                        uint32_t& r3, uint32_t addr) {
    asm volatile("ldmatrix.sync.aligned.m8n8.x4.shared.b16 {%0,%1,%2,%3}, [%4];"
                 : "=r"(r0), "=r"(r1), "=r"(r2), "=r"(r3) : "r"(addr));
}
__device__ __forceinline__ void ldsm_x2(uint32_t& r0, uint32_t& r1, uint32_t addr) {
    asm volatile("ldmatrix.sync.aligned.m8n8.x2.shared.b16 {%0,%1}, [%2];"
                 : "=r"(r0), "=r"(r1) : "r"(addr));
}

// ============================================================================
// K0: fold g[k]*sqrt(C) into qkv weights, round to tf32.
// ============================================================================
__global__ void k_prepw(const float* __restrict__ wqkv, const float* __restrict__ g) {
    int i = blockIdx.x * 256 + threadIdx.x;
    int k = i & 127;
    float w = wqkv[i] * g[k] * 11.313708498984761f;
    g_wt[i] = __uint_as_float(f2tf32(w));
}

// ============================================================================
// K1: fused RMSNorm + qkv GEMM (mma.sync tf32).  ALL 3 mt tiles in one CTA:
// x staged + normalized ONCE, W tile reloaded per mt (L2-resident).
// grid (64 nt, 32 b), block 256.  For mt==1 epilogue stores exp(k-hat) fp16.
// ============================================================================
__global__ __launch_bounds__(256, 2)
void k_qkv_mma(const float* __restrict__ x) {
    extern __shared__ float sm[];
    float* a_s  = sm;            // 16384
    float* xs   = sm + 16384;    // 8192
    float* red  = sm + 24576;    // 256
    float* invs = sm + 24832;    // 64

    const int nt = blockIdx.x, b = blockIdx.y;
    const int tid = threadIdx.x;

    // ---- B: x tile [128 ch][64 tok], tf32-round, + ssq partials (ONCE) ----
    {
        const int t = tid & 63, cq = tid >> 6;
        const float* xc = x + (size_t)b * CCH * NTOK + (size_t)nt * 64 + t;
        float ss = 0.f;
        #pragma unroll
        for (int i = 0; i < 32; i++) {
            int c = cq * 32 + i;
            float v = xc[(size_t)c * NTOK];
            ss += v * v;
            xs[c * 64 + ((t + 8 * c) & 63)] = __uint_as_float(f2tf32(v));
        }
        red[cq * 64 + t] = ss;
    }
    __syncthreads();
    if (tid < 64) {
        float ss = red[tid] + red[64 + tid] + red[128 + tid] + red[192 + tid];
        invs[tid] = 1.0f / fmaxf(sqrtf(ss), 1e-12f);
    }
    __syncthreads();

    const int lane = tid & 31, w = tid >> 5;
    const int wm = w >> 2, wn = w & 3;
    const int r4 = lane >> 2, c4 = lane & 3;

    const uint32_t* a_u = reinterpret_cast<const uint32_t*>(a_s);
    const uint32_t* x_u = reinterpret_cast<const uint32_t*>(xs);

    for (int mt = 0; mt < 3; mt++) {
        // ---- A: W tile [128][128], XOR swizzle ----
        const float* wb = g_wt + mt * 128 * 128;
        #pragma unroll
        for (int i = 0; i < 64; i++) {
            int idx = tid + i * 256;
            int m = idx >> 7, k = idx & 127;
            a_s[m * 128 + ((k + 4 * m) & 127)] = wb[idx];
        }
        __syncthreads();

        float acc[4][2][4];
        #pragma unroll
        for (int mi = 0; mi < 4; mi++)
            #pragma unroll
            for (int ni = 0; ni < 2; ni++)
                #pragma unroll
                for (int q = 0; q < 4; q++) acc[mi][ni][q] = 0.f;

        #pragma unroll
        for (int ks = 0; ks < 16; ks++) {
            const int k0 = ks * 8;
            uint32_t af[4][4];
            uint32_t bf[2][2];
            #pragma unroll
            for (int mi = 0; mi < 4; mi++) {
                int r0 = wm * 64 + mi * 16 + r4;
                int r1 = r0 + 8;
                int ka = k0 + c4;
                af[mi][0] = a_u[r0 * 128 + ((ka + 4 * r0) & 127)];
                af[mi][1] = a_u[r1 * 128 + ((ka + 4 * r1) & 127)];
                af[mi][2] = a_u[r0 * 128 + ((ka + 4 + 4 * r0) & 127)];
                af[mi][3] = a_u[r1 * 128 + ((ka + 4 + 4 * r1) & 127)];
            }
            #pragma unroll
            for (int ni = 0; ni < 2; ni++) {
                int n0 = wn * 16 + ni * 8 + r4;
                int kb0 = k0 + c4, kb1 = kb0 + 4;
                bf[ni][0] = x_u[kb0 * 64 + ((n0 + 8 * kb0) & 63)];
                bf[ni][1] = x_u[kb1 * 64 + ((n0 + 8 * kb1) & 63)];
            }
            #pragma unroll
            for (int mi = 0; mi < 4; mi++)
                #pragma unroll
                for (int ni = 0; ni < 2; ni++)
                    mma_tf32(acc[mi][ni], af[mi], bf[ni]);
        }

        // epilogue: scale by invs[token]; for k rows (mt==1) store exp()
        __half* outb = g_qkvh + ((size_t)b * QKV3 + (size_t)mt * 128) * NTOK
                       + (size_t)nt * 64;
        const bool is_k = (mt == 1);
        #pragma unroll
        for (int mi = 0; mi < 4; mi++) {
            #pragma unroll
            for (int ni = 0; ni < 2; ni++) {
                int col = wn * 16 + ni * 8 + 2 * c4;
                float i0 = invs[col], i1 = invs[col + 1];
                int row0 = wm * 64 + mi * 16 + r4;
                float v00 = acc[mi][ni][0] * i0, v01 = acc[mi][ni][1] * i1;
                float v10 = acc[mi][ni][2] * i0, v11 = acc[mi][ni][3] * i1;
                if (is_k) {
                    v00 = __expf(v00); v01 = __expf(v01);
                    v10 = __expf(v10); v11 = __expf(v11);
                }
                *reinterpret_cast<__half2*>(&outb[(size_t)row0 * NTOK + col]) =
                    __floats2half2_rn(v00, v01);
                *reinterpret_cast<__half2*>(&outb[(size_t)(row0 + 8) * NTOK + col]) =
                    __floats2half2_rn(v10, v11);
            }
        }
        __syncthreads();   // a_s safe to overwrite next iteration
    }
}

// ============================================================================
// K3: context partials on fp16 HMMA, 512 tokens per block in 2 chunks of 256.
// es (=exp(k), pre-applied) and v staged raw fp16, pitch 264 (conflict-free
// ldmatrix).  8 warps: warp w owns 16(d) x 8(e) D tile.  Z via shuffles.
// grid 128*NSPLIT (=1024), block 256.
// ============================================================================
__global__ __launch_bounds__(256)
void k_context() {
    __shared__ __half es[32 * 264];
    __shared__ __half vs[32 * 264];
    const int blk = blockIdx.x;
    const int bh = blk >> 3, split = blk & (NSPLIT - 1);
    const int b = bh >> 2, h = bh & 3;
    const int tid = threadIdx.x;

    const __half* kbase = g_qkvh + ((size_t)(b * QKV3 + CCH + h * DH)) * NTOK;
    const __half* vbase = g_qkvh + ((size_t)(b * QKV3 + 2 * CCH + h * DH)) * NTOK;

    const int w = tid >> 5, lane = tid & 31;
    const int mi = w >> 2, ni = w & 3;
    float dacc[4] = {0.f, 0.f, 0.f, 0.f};
    float zacc = 0.f;

    const uint32_t es_b = smem_u32(es);
    const uint32_t vs_b = smem_u32(vs);
    const uint32_t a_addr = es_b + ((mi * 16 + (lane & 15)) * 264 + ((lane >> 4) << 3)) * 2;
    const uint32_t b_addr = vs_b + ((ni * 8 + (lane & 7)) * 264 + (((lane >> 3) & 1) << 3)) * 2;
    const int zd = tid >> 3, zseg = (tid & 7) * 16;

    for (int chunk = 0; chunk < 2; chunk++) {
        const int t0 = split * 512 + chunk * 256;

        // ---- staging: coalesced half2 copies ----
        #pragma unroll
        for (int j = 0; j < 16; j++) {
            int hidx = tid + j * 256;
            int d = hidx >> 7, col = hidx & 127;
            uint32_t kv = *reinterpret_cast<const uint32_t*>(
                &kbase[(size_t)d * NTOK + t0 + 2 * col]);
            uint32_t vv = *reinterpret_cast<const uint32_t*>(
                &vbase[(size_t)d * NTOK + t0 + 2 * col]);
            *reinterpret_cast<uint32_t*>(&es[d * 264 + 2 * col]) = kv;
            *reinterpret_cast<uint32_t*>(&vs[d * 264 + 2 * col]) = vv;
        }
        __syncthreads();

        // ---- Z partial (per-thread; shuffle at the very end) ----
        #pragma unroll
        for (int j = 0; j < 16; j++) {
            __half2 hv = *reinterpret_cast<const __half2*>(&es[zd * 264 + 2 * (zseg + j)]);
            float2 f = __half22float2(hv);
            zacc += f.x + f.y;
        }

        // ---- HMMA ----
        #pragma unroll
        for (int kc = 0; kc < 16; kc++) {
            uint32_t a0, a1, a2, a3, b0, b1;
            ldsm_x4(a0, a1, a2, a3, a_addr + kc * 32);
            ldsm_x2(b0, b1, b_addr + kc * 32);
            mma_f16(dacc, a0, a1, a2, a3, b0, b1);
        }
        __syncthreads();
    }

    // ---- Z reduce across the 8 threads sharing row zd, store ----
    {
        float z = zacc;
        z += __shfl_xor_sync(0xFFFFFFFFu, z, 1);
        z += __shfl_xor_sync(0xFFFFFFFFu, z, 2);
        z += __shfl_xor_sync(0xFFFFFFFFu, z, 4);
        if ((tid & 7) == 0)
            g_zpart[split * (BATCH * NH * DH) + bh * 32 + zd] = z;
    }

    // ---- store partials (each (d,e) warp-owned) ----
    float* outp = g_ctx_part + ((size_t)split * 128 + bh) * 1024;
    const int r = lane >> 2, c2 = (lane & 3) * 2;
    const int dr = mi * 16 + r, ec = ni * 8 + c2;
    *reinterpret_cast<float2*>(&outp[dr * 32 + ec]) = make_float2(dacc[0], dacc[1]);
    *reinterpret_cast<float2*>(&outp[(dr + 8) * 32 + ec]) = make_float2(dacc[2], dacc[3]);
}

// ============================================================================
// K4: fold w_out through normalized context -> W2[b][o][c].
// grid (32 b, 4 o-tiles, 4 heads), block 256.  float4 split reduction.
// ============================================================================
__global__ void k_w2p(const float* __restrict__ wout, const float* __restrict__ mem_kv) {
    __shared__ float ce[32 * 36];
    __shared__ float ws[32 * 36];
    __shared__ float ews[128];
    __shared__ float invz[32];
    const int b = blockIdx.x, og = blockIdx.y, cg = blockIdx.z;
    const int tid = threadIdx.x;

    if (tid < 128)
        ews[tid] = __expf(mem_kv[cg * 128 + tid]);
    for (int idx = tid; idx < 1024; idx += 256) {
        int ol = idx >> 5, e = idx & 31;
        ws[ol * 36 + e] = wout[(og * 32 + ol) * 128 + cg * 32 + e];
    }
    __syncthreads();

    if (tid < 32) {
        float z = 0.f;
        #pragma unroll
        for (int s = 0; s < NSPLIT; s++)
            z += g_zpart[s * (BATCH * NH * DH) + b * 128 + cg * 32 + tid];
        z += ews[tid * 4] + ews[tid * 4 + 1] + ews[tid * 4 + 2] + ews[tid * 4 + 3];
        invz[tid] = 1.0f / z;
    }
    __syncthreads();

    // ctx reduction: one float4 per thread
    {
        const int lc = tid >> 3, e4 = (tid & 7) * 4;
        const size_t base = (size_t)(b * 4 + cg) * 1024 + lc * 32 + e4;
        float4 v = make_float4(0.f, 0.f, 0.f, 0.f);
        #pragma unroll
        for (int s = 0; s < NSPLIT; s++) {
            float4 t = *reinterpret_cast<const float4*>(&g_ctx_part[(size_t)s * 131072 + base]);
            v.x += t.x; v.y += t.y; v.z += t.z; v.w += t.w;
        }
        #pragma unroll
        for (int j = 0; j < 4; j++) {
            float ew = ews[lc * 4 + j];
            v.x = fmaf(ew, mem_kv[512 + ((cg * 32 + e4 + 0) * 4 + j)], v.x);
            v.y = fmaf(ew, mem_kv[512 + ((cg * 32 + e4 + 1) * 4 + j)], v.y);
            v.z = fmaf(ew, mem_kv[512 + ((cg * 32 + e4 + 2) * 4 + j)], v.z);
            v.w = fmaf(ew, mem_kv[512 + ((cg * 32 + e4 + 3) * 4 + j)], v.w);
        }
        const float iz = invz[lc];
        v.x *= iz; v.y *= iz; v.z *= iz; v.w *= iz;
        *reinterpret_cast<float4*>(&ce[lc * 36 + e4]) = v;
    }
    __syncthreads();

    const int o_l = tid >> 3;
    const int cb = tid & 7;
    const float* wr = &ws[o_l * 36];
    #pragma unroll
    for (int ci = 0; ci < 4; ci++) {
        int c_l = cb + ci * 8;
        const float* cr = &ce[c_l * 36];
        float a = 0.f;
        #pragma unroll
        for (int e4 = 0; e4 < 32; e4 += 4) {
            float4 w4 = *reinterpret_cast<const float4*>(wr + e4);
            float4 c4v = *reinterpret_cast<const float4*>(cr + e4);
            a = fmaf(w4.x, c4v.x, a);
            a = fmaf(w4.y, c4v.y, a);
            a = fmaf(w4.z, c4v.z, a);
            a = fmaf(w4.w, c4v.w, a);
        }
        g_w2[((size_t)b * 128 + og * 32 + o_l) * 128 + cg * 32 + c_l] = a;
    }
}

// ============================================================================
// K5: fused q-softmax + output GEMM (mma.sync tf32).  q read fp16.
// ============================================================================
__global__ __launch_bounds__(256, 2)
void k_final_mma(const float* __restrict__ bout, float* __restrict__ y) {
    extern __shared__ float sm5[];
    float* a_s = sm5;             // 16384
    float* xs  = sm5 + 16384;     // 8192
    float* bs  = sm5 + 24576;     // 128

    const int nt = blockIdx.x, b = blockIdx.y;
    const int tid = threadIdx.x;

    const float* wg = g_w2 + (size_t)b * 16384;
    #pragma unroll
    for (int i = 0; i < 64; i++) {
        int idx = tid + i * 256;
        int o = idx >> 7, c = idx & 127;
        a_s[o * 128 + ((c + 4 * o) & 127)] = wg[idx];
    }
    {
        const int t = tid & 63, cq = tid >> 6;
        const __half* qc = g_qkvh + (size_t)b * QKV3 * NTOK + (size_t)nt * 64 + t;
        #pragma unroll
        for (int i = 0; i < 32; i++) {
            int c = cq * 32 + i;
            xs[c * 64 + ((t + 8 * c) & 63)] = __half2float(qc[(size_t)c * NTOK]);
        }
    }
    if (tid < 128) bs[tid] = bout[tid];
    __syncthreads();

    {
        const int h = tid >> 6, t = tid & 63;
        float qv[32];
        float m = -1e30f;
        #pragma unroll
        for (int d = 0; d < 32; d++) {
            int c = h * 32 + d;
            qv[d] = xs[c * 64 + ((t + 8 * c) & 63)];
            m = fmaxf(m, qv[d]);
        }
        float ss = 0.f;
        #pragma unroll
        for (int d = 0; d < 32; d++) {
            qv[d] = __expf(qv[d] - m);
            ss += qv[d];
        }
        const float inv = 0.17677669529663687f / ss;
        #pragma unroll
        for (int d = 0; d < 32; d++) {
            int c = h * 32 + d;
            xs[c * 64 + ((t + 8 * c) & 63)] = __uint_as_float(f2tf32(qv[d] * inv));
        }
    }
    __syncthreads();

    const int lane = tid & 31, w = tid >> 5;
    const int wm = w >> 2, wn = w & 3;
    const int r4 = lane >> 2, c4 = lane & 3;

    float acc[4][2][4];
    #pragma unroll
    for (int mi = 0; mi < 4; mi++)
        #pragma unroll
        for (int ni = 0; ni < 2; ni++)
            #pragma unroll
            for (int q = 0; q < 4; q++) acc[mi][ni][q] = 0.f;

    const uint32_t* a_u = reinterpret_cast<const uint32_t*>(a_s);
    const uint32_t* x_u = reinterpret_cast<const uint32_t*>(xs);

    #pragma unroll
    for (int ks = 0; ks < 16; ks++) {
        const int k0 = ks * 8;
        uint32_t af[4][4];
        uint32_t bf[2][2];
        #pragma unroll
        for (int mi = 0; mi < 4; mi++) {
            int r0 = wm * 64 + mi * 16 + r4;
            int r1 = r0 + 8;
            int ka = k0 + c4;
            af[mi][0] = a_u[r0 * 128 + ((ka + 4 * r0) & 127)];
            af[mi][1] = a_u[r1 * 128 + ((ka + 4 * r1) & 127)];
            af[mi][2] = a_u[r0 * 128 + ((ka + 4 + 4 * r0) & 127)];
            af[mi][3] = a_u[r1 * 128 + ((ka + 4 + 4 * r1) & 127)];
        }
        #pragma unroll
        for (int ni = 0; ni < 2; ni++) {
            int n0 = wn * 16 + ni * 8 + r4;
            int kb0 = k0 + c4, kb1 = kb0 + 4;
            bf[ni][0] = x_u[kb0 * 64 + ((n0 + 8 * kb0) & 63)];
            bf[ni][1] = x_u[kb1 * 64 + ((n0 + 8 * kb1) & 63)];
        }
        #pragma unroll
        for (int mi = 0; mi < 4; mi++)
            #pragma unroll
            for (int ni = 0; ni < 2; ni++)
                mma_tf32(acc[mi][ni], af[mi], bf[ni]);
    }

    float* outb = y + (size_t)b * CCH * NTOK + (size_t)nt * 64;
    #pragma unroll
    for (int mi = 0; mi < 4; mi++) {
        #pragma unroll
        for (int ni = 0; ni < 2; ni++) {
            int col = wn * 16 + ni * 8 + 2 * c4;
            int row0 = wm * 64 + mi * 16 + r4;
            float b0 = bs[row0], b1 = bs[row0 + 8];
            float2 v0 = make_float2(acc[mi][ni][0] + b0, acc[mi][ni][1] + b0);
            float2 v1 = make_float2(acc[mi][ni][2] + b1, acc[mi][ni][3] + b1);
            *reinterpret_cast<float2*>(&outb[(size_t)row0 * NTOK + col]) = v0;
            *reinterpret_cast<float2*>(&outb[(size_t)(row0 + 8) * NTOK + col]) = v1;
        }
    }
}

// ============================================================================
extern "C" void kernel_launch(void* const* d_in, const int* in_sizes, int n_in,
                              void* d_out, int out_size) {
    const float* x      = (const float*)d_in[0];
    const float* g      = (const float*)d_in[1];
    const float* wqkv   = (const float*)d_in[2];
    const float* mem_kv = (const float*)d_in[3];
    const float* wout   = (const float*)d_in[4];
    const float* bout   = (const float*)d_in[5];
    float* y = (float*)d_out;

    const int SMEM_K1 = 24896 * 4;
    const int SMEM_K5 = 24704 * 4;
    cudaFuncSetAttribute(k_qkv_mma,   cudaFuncAttributeMaxDynamicSharedMemorySize, SMEM_K1);
    cudaFuncSetAttribute(k_final_mma, cudaFuncAttributeMaxDynamicSharedMemorySize, SMEM_K5);

    k_prepw<<<192, 256>>>(wqkv, g);
    k_qkv_mma<<<dim3(64, 32), 256, SMEM_K1>>>(x);
    k_context<<<128 * NSPLIT, 256>>>();
    k_w2p<<<dim3(32, 4, 4), 256>>>(wout, mem_kv);
    k_final_mma<<<dim3(64, 32), 256, SMEM_K5>>>(bout, y);
}

// round 15
// speedup vs baseline: 3.7503x; 1.4958x over previous
#include <cuda_runtime.h>
#include <cuda_bf16.h>
#include <cuda_fp16.h>
#include <cstdint>
#include <math.h>

// Problem constants
#define BATCH 32
#define CCH   128
#define NTOK  4096
#define NH    4
#define DH    32
#define QKV3  384
#define NSPLIT 8

// ---------------- scratch (device globals; no allocation allowed) ----------
__device__ __half g_qkvh[(size_t)BATCH * QKV3 * NTOK];        // q, exp(k), v (fp16)
__device__ __half g_wth[QKV3 * CCH];                          // g-folded W, fp16
__device__ float g_ctx_part[NSPLIT * BATCH * NH * DH * DH];
__device__ float g_zpart[NSPLIT * BATCH * NH * DH];
__device__ __half g_w2h[BATCH * CCH * CCH];                   // W2 fp16: [b][o][c]

__device__ __forceinline__ uint32_t smem_u32(const void* p) {
    uint32_t a;
    asm("{ .reg .u64 t; cvta.to.shared.u64 t, %1; cvt.u32.u64 %0, t; }"
        : "=r"(a) : "l"(p));
    return a;
}
__device__ __forceinline__ void mma_f16(float* d, uint32_t a0, uint32_t a1,
                                        uint32_t a2, uint32_t a3,
                                        uint32_t b0, uint32_t b1) {
    asm volatile(
        "mma.sync.aligned.m16n8k16.row.col.f32.f16.f16.f32 "
        "{%0,%1,%2,%3}, {%4,%5,%6,%7}, {%8,%9}, {%0,%1,%2,%3};"
        : "+f"(d[0]), "+f"(d[1]), "+f"(d[2]), "+f"(d[3])
        : "r"(a0), "r"(a1), "r"(a2), "r"(a3), "r"(b0), "r"(b1));
}
__device__ __forceinline__ void ldsm_x4(uint32_t& r0, uint32_t& r1, uint32_t& r2,
                                        uint32_t& r3, uint32_t addr) {
    asm volatile("ldmatrix.sync.aligned.m8n8.x4.shared.b16 {%0,%1,%2,%3}, [%4];"
                 : "=r"(r0), "=r"(r1), "=r"(r2), "=r"(r3) : "r"(addr));
}
__device__ __forceinline__ void ldsm_x2(uint32_t& r0, uint32_t& r1, uint32_t addr) {
    asm volatile("ldmatrix.sync.aligned.m8n8.x2.shared.b16 {%0,%1}, [%2];"
                 : "=r"(r0), "=r"(r1) : "r"(addr));
}

#define PITCH 136   // halfs; 272 B row stride == 16 mod 128 -> conflict-free ldmatrix

// ============================================================================
// K0: fold g[k]*sqrt(C) into qkv weights, store fp16.
// ============================================================================
__global__ void k_prepw(const float* __restrict__ wqkv, const float* __restrict__ g) {
    int i = blockIdx.x * 256 + threadIdx.x;
    int k = i & 127;
    float w = wqkv[i] * g[k] * 11.313708498984761f;
    g_wth[i] = __float2half(w);
}

// ============================================================================
// K1: fused RMSNorm + qkv GEMM on fp16 HMMA + ldmatrix.
// CTA tile M=128 x N=64 x K=128; 3 mt tiles looped (x staged once).
// grid (64 nt, 32 b), block 256 (8 warps = 2 wm x 4 wn, warp tile 64x16).
// mt==1 (k rows): epilogue stores exp(k-hat).
// ============================================================================
__global__ __launch_bounds__(256, 2)
void k_qkv_mma(const float* __restrict__ x) {
    extern __shared__ __half smh[];
    __half* a_s = smh;                         // 128*PITCH
    __half* xs  = smh + 128 * PITCH;           // 64*PITCH
    float* red  = reinterpret_cast<float*>(smh + 192 * PITCH);  // 256
    float* invs = red + 256;                   // 64

    const int nt = blockIdx.x, b = blockIdx.y;
    const int tid = threadIdx.x;

    // ---- B: x tile -> xs[t][c] fp16, + ssq partials (once) ----
    {
        const int t = tid & 63, cq = tid >> 6;
        const float* xc = x + (size_t)b * CCH * NTOK + (size_t)nt * 64 + t;
        float ss = 0.f;
        #pragma unroll
        for (int i = 0; i < 16; i++) {
            int c = cq * 32 + 2 * i;
            float v0 = xc[(size_t)c * NTOK];
            float v1 = xc[(size_t)(c + 1) * NTOK];
            ss += v0 * v0 + v1 * v1;
            *reinterpret_cast<__half2*>(&xs[t * PITCH + c]) = __floats2half2_rn(v0, v1);
        }
        red[cq * 64 + t] = ss;
    }
    __syncthreads();
    if (tid < 64) {
        float ss = red[tid] + red[64 + tid] + red[128 + tid] + red[192 + tid];
        invs[tid] = 1.0f / fmaxf(sqrtf(ss), 1e-12f);
    }
    __syncthreads();

    const int lane = tid & 31, w = tid >> 5;
    const int wm = w >> 2, wn = w & 3;
    const int r4 = lane >> 2, c4 = lane & 3;

    const uint32_t as_b = smem_u32(a_s);
    const uint32_t xs_b = smem_u32(xs);
    const uint32_t a_addr = as_b + ((wm * 64 + (lane & 15)) * PITCH + ((lane >> 4) << 3)) * 2;
    const uint32_t b_addr = xs_b + ((wn * 16 + (lane & 7)) * PITCH + (((lane >> 3) & 1) << 3)) * 2;

    for (int mt = 0; mt < 3; mt++) {
        // ---- A: W tile [128 m][128 k] fp16 (coalesced, conflict-free) ----
        const uint32_t* wbh = reinterpret_cast<const uint32_t*>(g_wth) + mt * 8192;
        #pragma unroll
        for (int i = 0; i < 32; i++) {
            int idx = tid + i * 256;           // 8192 u32
            int m = idx >> 6, c2 = idx & 63;
            *reinterpret_cast<uint32_t*>(&a_s[m * PITCH + 2 * c2]) = wbh[idx];
        }
        __syncthreads();

        float acc[4][2][4];
        #pragma unroll
        for (int mi = 0; mi < 4; mi++)
            #pragma unroll
            for (int ni = 0; ni < 2; ni++)
                #pragma unroll
                for (int q = 0; q < 4; q++) acc[mi][ni][q] = 0.f;

        #pragma unroll
        for (int kc = 0; kc < 8; kc++) {
            uint32_t af[4][4], bf[2][2];
            #pragma unroll
            for (int mi = 0; mi < 4; mi++)
                ldsm_x4(af[mi][0], af[mi][1], af[mi][2], af[mi][3],
                        a_addr + mi * (16 * PITCH * 2) + kc * 32);
            #pragma unroll
            for (int ni = 0; ni < 2; ni++)
                ldsm_x2(bf[ni][0], bf[ni][1],
                        b_addr + ni * (8 * PITCH * 2) + kc * 32);
            #pragma unroll
            for (int mi = 0; mi < 4; mi++)
                #pragma unroll
                for (int ni = 0; ni < 2; ni++)
                    mma_f16(acc[mi][ni], af[mi][0], af[mi][1], af[mi][2], af[mi][3],
                            bf[ni][0], bf[ni][1]);
        }

        // ---- epilogue: scale by invs[token]; mt==1 stores exp() ----
        __half* outb = g_qkvh + ((size_t)b * QKV3 + (size_t)mt * 128) * NTOK
                       + (size_t)nt * 64;
        const bool is_k = (mt == 1);
        #pragma unroll
        for (int mi = 0; mi < 4; mi++) {
            #pragma unroll
            for (int ni = 0; ni < 2; ni++) {
                int col = wn * 16 + ni * 8 + 2 * c4;
                float i0 = invs[col], i1 = invs[col + 1];
                int row0 = wm * 64 + mi * 16 + r4;
                float v00 = acc[mi][ni][0] * i0, v01 = acc[mi][ni][1] * i1;
                float v10 = acc[mi][ni][2] * i0, v11 = acc[mi][ni][3] * i1;
                if (is_k) {
                    v00 = __expf(v00); v01 = __expf(v01);
                    v10 = __expf(v10); v11 = __expf(v11);
                }
                *reinterpret_cast<__half2*>(&outb[(size_t)row0 * NTOK + col]) =
                    __floats2half2_rn(v00, v01);
                *reinterpret_cast<__half2*>(&outb[(size_t)(row0 + 8) * NTOK + col]) =
                    __floats2half2_rn(v10, v11);
            }
        }
        __syncthreads();
    }
}

// ============================================================================
// K3: context partials on fp16 HMMA, 512 tokens per block in 2 chunks of 256.
// grid 128*NSPLIT (=1024), block 256.  (unchanged from R14)
// ============================================================================
__global__ __launch_bounds__(256)
void k_context() {
    __shared__ __half es[32 * 264];
    __shared__ __half vs[32 * 264];
    const int blk = blockIdx.x;
    const int bh = blk >> 3, split = blk & (NSPLIT - 1);
    const int b = bh >> 2, h = bh & 3;
    const int tid = threadIdx.x;

    const __half* kbase = g_qkvh + ((size_t)(b * QKV3 + CCH + h * DH)) * NTOK;
    const __half* vbase = g_qkvh + ((size_t)(b * QKV3 + 2 * CCH + h * DH)) * NTOK;

    const int w = tid >> 5, lane = tid & 31;
    const int mi = w >> 2, ni = w & 3;
    float dacc[4] = {0.f, 0.f, 0.f, 0.f};
    float zacc = 0.f;

    const uint32_t es_b = smem_u32(es);
    const uint32_t vs_b = smem_u32(vs);
    const uint32_t a_addr = es_b + ((mi * 16 + (lane & 15)) * 264 + ((lane >> 4) << 3)) * 2;
    const uint32_t b_addr = vs_b + ((ni * 8 + (lane & 7)) * 264 + (((lane >> 3) & 1) << 3)) * 2;
    const int zd = tid >> 3, zseg = (tid & 7) * 16;

    for (int chunk = 0; chunk < 2; chunk++) {
        const int t0 = split * 512 + chunk * 256;

        #pragma unroll
        for (int j = 0; j < 16; j++) {
            int hidx = tid + j * 256;
            int d = hidx >> 7, col = hidx & 127;
            uint32_t kv = *reinterpret_cast<const uint32_t*>(
                &kbase[(size_t)d * NTOK + t0 + 2 * col]);
            uint32_t vv = *reinterpret_cast<const uint32_t*>(
                &vbase[(size_t)d * NTOK + t0 + 2 * col]);
            *reinterpret_cast<uint32_t*>(&es[d * 264 + 2 * col]) = kv;
            *reinterpret_cast<uint32_t*>(&vs[d * 264 + 2 * col]) = vv;
        }
        __syncthreads();

        #pragma unroll
        for (int j = 0; j < 16; j++) {
            __half2 hv = *reinterpret_cast<const __half2*>(&es[zd * 264 + 2 * (zseg + j)]);
            float2 f = __half22float2(hv);
            zacc += f.x + f.y;
        }

        #pragma unroll
        for (int kc = 0; kc < 16; kc++) {
            uint32_t a0, a1, a2, a3, b0, b1;
            ldsm_x4(a0, a1, a2, a3, a_addr + kc * 32);
            ldsm_x2(b0, b1, b_addr + kc * 32);
            mma_f16(dacc, a0, a1, a2, a3, b0, b1);
        }
        __syncthreads();
    }

    {
        float z = zacc;
        z += __shfl_xor_sync(0xFFFFFFFFu, z, 1);
        z += __shfl_xor_sync(0xFFFFFFFFu, z, 2);
        z += __shfl_xor_sync(0xFFFFFFFFu, z, 4);
        if ((tid & 7) == 0)
            g_zpart[split * (BATCH * NH * DH) + bh * 32 + zd] = z;
    }

    float* outp = g_ctx_part + ((size_t)split * 128 + bh) * 1024;
    const int r = lane >> 2, c2 = (lane & 3) * 2;
    const int dr = mi * 16 + r, ec = ni * 8 + c2;
    *reinterpret_cast<float2*>(&outp[dr * 32 + ec]) = make_float2(dacc[0], dacc[1]);
    *reinterpret_cast<float2*>(&outp[(dr + 8) * 32 + ec]) = make_float2(dacc[2], dacc[3]);
}

// ============================================================================
// K4: fold w_out through normalized context -> W2 fp16 [b][o][c].
// grid (32 b, 4 o-tiles, 4 heads), block 256.
// ============================================================================
__global__ void k_w2p(const float* __restrict__ wout, const float* __restrict__ mem_kv) {
    __shared__ float ce[32 * 36];
    __shared__ float ws[32 * 36];
    __shared__ float ews[128];
    __shared__ float invz[32];
    const int b = blockIdx.x, og = blockIdx.y, cg = blockIdx.z;
    const int tid = threadIdx.x;

    if (tid < 128)
        ews[tid] = __expf(mem_kv[cg * 128 + tid]);
    for (int idx = tid; idx < 1024; idx += 256) {
        int ol = idx >> 5, e = idx & 31;
        ws[ol * 36 + e] = wout[(og * 32 + ol) * 128 + cg * 32 + e];
    }
    __syncthreads();

    if (tid < 32) {
        float z = 0.f;
        #pragma unroll
        for (int s = 0; s < NSPLIT; s++)
            z += g_zpart[s * (BATCH * NH * DH) + b * 128 + cg * 32 + tid];
        z += ews[tid * 4] + ews[tid * 4 + 1] + ews[tid * 4 + 2] + ews[tid * 4 + 3];
        invz[tid] = 1.0f / z;
    }
    __syncthreads();

    {
        const int lc = tid >> 3, e4 = (tid & 7) * 4;
        const size_t base = (size_t)(b * 4 + cg) * 1024 + lc * 32 + e4;
        float4 v = make_float4(0.f, 0.f, 0.f, 0.f);
        #pragma unroll
        for (int s = 0; s < NSPLIT; s++) {
            float4 t = *reinterpret_cast<const float4*>(&g_ctx_part[(size_t)s * 131072 + base]);
            v.x += t.x; v.y += t.y; v.z += t.z; v.w += t.w;
        }
        #pragma unroll
        for (int j = 0; j < 4; j++) {
            float ew = ews[lc * 4 + j];
            v.x = fmaf(ew, mem_kv[512 + ((cg * 32 + e4 + 0) * 4 + j)], v.x);
            v.y = fmaf(ew, mem_kv[512 + ((cg * 32 + e4 + 1) * 4 + j)], v.y);
            v.z = fmaf(ew, mem_kv[512 + ((cg * 32 + e4 + 2) * 4 + j)], v.z);
            v.w = fmaf(ew, mem_kv[512 + ((cg * 32 + e4 + 3) * 4 + j)], v.w);
        }
        const float iz = invz[lc];
        v.x *= iz; v.y *= iz; v.z *= iz; v.w *= iz;
        *reinterpret_cast<float4*>(&ce[lc * 36 + e4]) = v;
    }
    __syncthreads();

    const int o_l = tid >> 3;
    const int cb = tid & 7;
    const float* wr = &ws[o_l * 36];
    #pragma unroll
    for (int ci = 0; ci < 4; ci++) {
        int c_l = cb + ci * 8;
        const float* cr = &ce[c_l * 36];
        float a = 0.f;
        #pragma unroll
        for (int e4 = 0; e4 < 32; e4 += 4) {
            float4 w4 = *reinterpret_cast<const float4*>(wr + e4);
            float4 c4v = *reinterpret_cast<const float4*>(cr + e4);
            a = fmaf(w4.x, c4v.x, a);
            a = fmaf(w4.y, c4v.y, a);
            a = fmaf(w4.z, c4v.z, a);
            a = fmaf(w4.w, c4v.w, a);
        }
        g_w2h[((size_t)b * 128 + og * 32 + o_l) * 128 + cg * 32 + c_l] = __float2half(a);
    }
}

// ============================================================================
// K5: fused q-softmax + output GEMM on fp16 HMMA + ldmatrix.
// CTA tile M=128(o) x N=64(t) x K=128(c).  grid (64 nt, 32 b), block 256.
// Softmax computed in f32 registers during B staging.
// ============================================================================
__global__ __launch_bounds__(256, 2)
void k_final_mma(const float* __restrict__ bout, float* __restrict__ y) {
    extern __shared__ __half smh5[];
    __half* a_s = smh5;                        // 128*PITCH
    __half* xs  = smh5 + 128 * PITCH;          // 64*PITCH
    float* bs   = reinterpret_cast<float*>(smh5 + 192 * PITCH);  // 128

    const int nt = blockIdx.x, b = blockIdx.y;
    const int tid = threadIdx.x;

    // ---- A: W2 fp16 tile (coalesced, conflict-free stores) ----
    const uint32_t* wgh = reinterpret_cast<const uint32_t*>(g_w2h) + (size_t)b * 8192;
    #pragma unroll
    for (int i = 0; i < 32; i++) {
        int idx = tid + i * 256;
        int o = idx >> 6, c2 = idx & 63;
        *reinterpret_cast<uint32_t*>(&a_s[o * PITCH + 2 * c2]) = wgh[idx];
    }

    // ---- B: q tile, softmax in registers, write fp16 ----
    {
        const int t = tid & 63, h = tid >> 6;
        const __half* qc = g_qkvh + (size_t)b * QKV3 * NTOK + (size_t)nt * 64 + t;
        float qv[32];
        float m = -1e30f;
        #pragma unroll
        for (int d = 0; d < 32; d++) {
            qv[d] = __half2float(qc[(size_t)(h * 32 + d) * NTOK]);
            m = fmaxf(m, qv[d]);
        }
        float ss = 0.f;
        #pragma unroll
        for (int d = 0; d < 32; d++) {
            qv[d] = __expf(qv[d] - m);
            ss += qv[d];
        }
        const float inv = 0.17677669529663687f / ss;
        #pragma unroll
        for (int d = 0; d < 32; d += 2) {
            *reinterpret_cast<__half2*>(&xs[t * PITCH + h * 32 + d]) =
                __floats2half2_rn(qv[d] * inv, qv[d + 1] * inv);
        }
    }
    if (tid < 128) bs[tid] = bout[tid];
    __syncthreads();

    const int lane = tid & 31, w = tid >> 5;
    const int wm = w >> 2, wn = w & 3;
    const int r4 = lane >> 2, c4 = lane & 3;

    const uint32_t as_b = smem_u32(a_s);
    const uint32_t xs_b = smem_u32(xs);
    const uint32_t a_addr = as_b + ((wm * 64 + (lane & 15)) * PITCH + ((lane >> 4) << 3)) * 2;
    const uint32_t b_addr = xs_b + ((wn * 16 + (lane & 7)) * PITCH + (((lane >> 3) & 1) << 3)) * 2;

    float acc[4][2][4];
    #pragma unroll
    for (int mi = 0; mi < 4; mi++)
        #pragma unroll
        for (int ni = 0; ni < 2; ni++)
            #pragma unroll
            for (int q = 0; q < 4; q++) acc[mi][ni][q] = 0.f;

    #pragma unroll
    for (int kc = 0; kc < 8; kc++) {
        uint32_t af[4][4], bf[2][2];
        #pragma unroll
        for (int mi = 0; mi < 4; mi++)
            ldsm_x4(af[mi][0], af[mi][1], af[mi][2], af[mi][3],
                    a_addr + mi * (16 * PITCH * 2) + kc * 32);
        #pragma unroll
        for (int ni = 0; ni < 2; ni++)
            ldsm_x2(bf[ni][0], bf[ni][1],
                    b_addr + ni * (8 * PITCH * 2) + kc * 32);
        #pragma unroll
        for (int mi = 0; mi < 4; mi++)
            #pragma unroll
            for (int ni = 0; ni < 2; ni++)
                mma_f16(acc[mi][ni], af[mi][0], af[mi][1], af[mi][2], af[mi][3],
                        bf[ni][0], bf[ni][1]);
    }

    // ---- epilogue: + bias, float2 stores ----
    float* outb = y + (size_t)b * CCH * NTOK + (size_t)nt * 64;
    #pragma unroll
    for (int mi = 0; mi < 4; mi++) {
        #pragma unroll
        for (int ni = 0; ni < 2; ni++) {
            int col = wn * 16 + ni * 8 + 2 * c4;
            int row0 = wm * 64 + mi * 16 + r4;
            float b0 = bs[row0], b1 = bs[row0 + 8];
            float2 v0 = make_float2(acc[mi][ni][0] + b0, acc[mi][ni][1] + b0);
            float2 v1 = make_float2(acc[mi][ni][2] + b1, acc[mi][ni][3] + b1);
            *reinterpret_cast<float2*>(&outb[(size_t)row0 * NTOK + col]) = v0;
            *reinterpret_cast<float2*>(&outb[(size_t)(row0 + 8) * NTOK + col]) = v1;
        }
    }
}

// ============================================================================
extern "C" void kernel_launch(void* const* d_in, const int* in_sizes, int n_in,
                              void* d_out, int out_size) {
    const float* x      = (const float*)d_in[0];
    const float* g      = (const float*)d_in[1];
    const float* wqkv   = (const float*)d_in[2];
    const float* mem_kv = (const float*)d_in[3];
    const float* wout   = (const float*)d_in[4];
    const float* bout   = (const float*)d_in[5];
    float* y = (float*)d_out;

    const int SMEM_K1 = 192 * PITCH * 2 + 320 * 4;   // 53504 B
    const int SMEM_K5 = 192 * PITCH * 2 + 128 * 4;   // 52736 B
    cudaFuncSetAttribute(k_qkv_mma,   cudaFuncAttributeMaxDynamicSharedMemorySize, SMEM_K1);
    cudaFuncSetAttribute(k_final_mma, cudaFuncAttributeMaxDynamicSharedMemorySize, SMEM_K5);

    k_prepw<<<192, 256>>>(wqkv, g);
    k_qkv_mma<<<dim3(64, 32), 256, SMEM_K1>>>(x);
    k_context<<<128 * NSPLIT, 256>>>();
    k_w2p<<<dim3(32, 4, 4), 256>>>(wout, mem_kv);
    k_final_mma<<<dim3(64, 32), 256, SMEM_K5>>>(bout, y);
}